// round 1
// baseline (speedup 1.0000x reference)
#include <cuda_runtime.h>

// ---------------------------------------------------------------------------
// GINRegressor: 3x [agg -> MLP(Lin,ReLU,Lin)] (+ReLU between layers),
// then global mean pool per graph + final Linear(H,1).
//
// Inputs (metadata order):
//  0 x [N*128] f32, 1 edge_index [2*E] i32, 2 batch [N] i32,
//  3..7   W1_0,b1_0,W2_0,b2_0,eps_0
//  8..12  W1_1,b1_1,W2_1,b2_1,eps_1
//  13..17 W1_2,b1_2,W2_2,b2_2,eps_2
//  18 fc_w [128], 19 fc_b [1]
// Output: [G] f32
// ---------------------------------------------------------------------------

#define NMAX 50000
#define GMAX 500
#define HDIM 128
#define BM 64
#define LDA 132   // padded A-tile row stride (floats) to avoid smem bank conflicts

__device__ float g_bufM[NMAX * HDIM];  // (1+eps)*h + agg
__device__ float g_bufH[NMAX * HDIM];  // layer output
__device__ float g_gsum[GMAX];
__device__ float g_gcnt[GMAX];

// M[i] = (1+eps) * X[i], vectorized float4
__global__ void scale_kernel(const float* __restrict__ X, float* __restrict__ M,
                             const float* __restrict__ epsp, int n4) {
    int i = blockIdx.x * blockDim.x + threadIdx.x;
    if (i >= n4) return;
    float s = 1.0f + *epsp;
    float4 v = ((const float4*)X)[i];
    v.x *= s; v.y *= s; v.z *= s; v.w *= s;
    ((float4*)M)[i] = v;
}

// One warp per edge: M[dst] += X[src] via vector reductions (no return).
__global__ void scatter_kernel(const float* __restrict__ X, float* __restrict__ M,
                               const int* __restrict__ ei, int E) {
    int gtid = blockIdx.x * blockDim.x + threadIdx.x;
    int e = gtid >> 5;
    int lane = gtid & 31;
    if (e >= E) return;
    int src = ei[e];
    int dst = ei[E + e];
    float4 v = ((const float4*)(X + (size_t)src * HDIM))[lane];
    float* mp = M + (size_t)dst * HDIM + lane * 4;
    asm volatile("red.global.add.v4.f32 [%0], {%1,%2,%3,%4};"
                 :: "l"(mp), "f"(v.x), "f"(v.y), "f"(v.z), "f"(v.w)
                 : "memory");
}

// Fused MLP: H = act( ReLU(M @ W1 + b1) @ W2 + b2 )
// If pool != 0: instead of storing H, compute per-node dot with fc_w and
// atomically accumulate per-graph sums/counts.
__global__ __launch_bounds__(256, 1) void mlp_kernel(
    const float* __restrict__ M, float* __restrict__ H,
    const float* __restrict__ W1, const float* __restrict__ b1,
    const float* __restrict__ W2, const float* __restrict__ b2,
    int n, int relu_out, int pool,
    const int* __restrict__ batch, const float* __restrict__ fcw,
    float* __restrict__ gsum, float* __restrict__ gcnt) {
    extern __shared__ float sm[];
    float* sW1 = sm;                   // 128*128
    float* sW2 = sW1 + 16384;          // 128*128
    float* sA  = sW2 + 16384;          // BM * LDA (also reused for T)
    float* sB1 = sA + BM * LDA;        // 128
    float* sB2 = sB1 + 128;            // 128
    float* sFW = sB2 + 128;            // 128

    int tid = threadIdx.x;

    // load weights
    {
        const float4* s4 = (const float4*)W1;
        float4* d4 = (float4*)sW1;
        for (int i = tid; i < 4096; i += 256) d4[i] = s4[i];
        s4 = (const float4*)W2;
        d4 = (float4*)sW2;
        for (int i = tid; i < 4096; i += 256) d4[i] = s4[i];
    }
    if (tid < 128) { sB1[tid] = b1[tid]; sB2[tid] = b2[tid]; sFW[tid] = fcw[tid]; }

    // load A tile (BM x 128), zero-pad rows >= n
    int row0 = blockIdx.x * BM;
    for (int i = tid; i < BM * 32; i += 256) {
        int r = i >> 5, c4 = i & 31;
        int gr = row0 + r;
        float4 v = (gr < n) ? ((const float4*)M)[(size_t)gr * 32 + c4]
                            : make_float4(0.f, 0.f, 0.f, 0.f);
        *(float4*)&sA[r * LDA + c4 * 4] = v;
    }
    __syncthreads();

    int tx = tid & 15, ty = tid >> 4;
    int rr = ty * 4;            // 4 rows per thread
    int ca = tx * 4;            // cols [ca, ca+3]
    int cb = 64 + tx * 4;       // cols [cb, cb+3]

    float acc[4][8];
    #pragma unroll
    for (int i = 0; i < 4; i++)
        #pragma unroll
        for (int j = 0; j < 8; j++) acc[i][j] = 0.f;

    // GEMM1: acc = A @ W1
    #pragma unroll 4
    for (int k = 0; k < 128; k++) {
        float4 bA = *(const float4*)&sW1[k * 128 + ca];
        float4 bB = *(const float4*)&sW1[k * 128 + cb];
        #pragma unroll
        for (int i = 0; i < 4; i++) {
            float a = sA[(rr + i) * LDA + k];
            acc[i][0] += a * bA.x; acc[i][1] += a * bA.y;
            acc[i][2] += a * bA.z; acc[i][3] += a * bA.w;
            acc[i][4] += a * bB.x; acc[i][5] += a * bB.y;
            acc[i][6] += a * bB.z; acc[i][7] += a * bB.w;
        }
    }
    __syncthreads();  // everyone done reading sA

    // T = ReLU(acc + b1) -> sA
    #pragma unroll
    for (int i = 0; i < 4; i++) {
        #pragma unroll
        for (int j = 0; j < 4; j++) {
            sA[(rr + i) * LDA + ca + j] = fmaxf(acc[i][j] + sB1[ca + j], 0.f);
            sA[(rr + i) * LDA + cb + j] = fmaxf(acc[i][4 + j] + sB1[cb + j], 0.f);
        }
    }
    __syncthreads();

    #pragma unroll
    for (int i = 0; i < 4; i++)
        #pragma unroll
        for (int j = 0; j < 8; j++) acc[i][j] = 0.f;

    // GEMM2: acc = T @ W2
    #pragma unroll 4
    for (int k = 0; k < 128; k++) {
        float4 bA = *(const float4*)&sW2[k * 128 + ca];
        float4 bB = *(const float4*)&sW2[k * 128 + cb];
        #pragma unroll
        for (int i = 0; i < 4; i++) {
            float a = sA[(rr + i) * LDA + k];
            acc[i][0] += a * bA.x; acc[i][1] += a * bA.y;
            acc[i][2] += a * bA.z; acc[i][3] += a * bA.w;
            acc[i][4] += a * bB.x; acc[i][5] += a * bB.y;
            acc[i][6] += a * bB.z; acc[i][7] += a * bB.w;
        }
    }

    // bias (+ optional ReLU)
    #pragma unroll
    for (int i = 0; i < 4; i++) {
        #pragma unroll
        for (int j = 0; j < 4; j++) {
            float va = acc[i][j] + sB2[ca + j];
            float vb = acc[i][4 + j] + sB2[cb + j];
            if (relu_out) { va = fmaxf(va, 0.f); vb = fmaxf(vb, 0.f); }
            acc[i][j] = va;
            acc[i][4 + j] = vb;
        }
    }

    if (!pool) {
        #pragma unroll
        for (int i = 0; i < 4; i++) {
            int gr = row0 + rr + i;
            if (gr < n) {
                *(float4*)&H[(size_t)gr * HDIM + ca] =
                    make_float4(acc[i][0], acc[i][1], acc[i][2], acc[i][3]);
                *(float4*)&H[(size_t)gr * HDIM + cb] =
                    make_float4(acc[i][4], acc[i][5], acc[i][6], acc[i][7]);
            }
        }
    } else {
        // fused mean-pool epilogue: per-row dot with fc_w, reduce across tx
        float pd[4];
        #pragma unroll
        for (int i = 0; i < 4; i++) {
            float s = 0.f;
            #pragma unroll
            for (int j = 0; j < 4; j++) {
                s += acc[i][j] * sFW[ca + j];
                s += acc[i][4 + j] * sFW[cb + j];
            }
            pd[i] = s;
        }
        #pragma unroll
        for (int off = 8; off > 0; off >>= 1) {
            #pragma unroll
            for (int i = 0; i < 4; i++)
                pd[i] += __shfl_down_sync(0xffffffffu, pd[i], off);
        }
        if (tx == 0) {
            #pragma unroll
            for (int i = 0; i < 4; i++) {
                int gr = row0 + rr + i;
                if (gr < n) {
                    int g = batch[gr];
                    atomicAdd(&gsum[g], pd[i]);
                    atomicAdd(&gcnt[g], 1.0f);
                }
            }
        }
    }
}

__global__ void final_kernel(const float* __restrict__ gsum,
                             const float* __restrict__ gcnt,
                             const float* __restrict__ fcb,
                             float* __restrict__ out, int G) {
    int i = blockIdx.x * blockDim.x + threadIdx.x;
    if (i < G) out[i] = gsum[i] / fmaxf(gcnt[i], 1.0f) + fcb[0];
}

extern "C" void kernel_launch(void* const* d_in, const int* in_sizes, int n_in,
                              void* d_out, int out_size) {
    const float* x     = (const float*)d_in[0];
    const int*   ei    = (const int*)d_in[1];
    const int*   batch = (const int*)d_in[2];
    const float* W1s[3] = {(const float*)d_in[3],  (const float*)d_in[8],  (const float*)d_in[13]};
    const float* b1s[3] = {(const float*)d_in[4],  (const float*)d_in[9],  (const float*)d_in[14]};
    const float* W2s[3] = {(const float*)d_in[5],  (const float*)d_in[10], (const float*)d_in[15]};
    const float* b2s[3] = {(const float*)d_in[6],  (const float*)d_in[11], (const float*)d_in[16]};
    const float* epss[3]= {(const float*)d_in[7],  (const float*)d_in[12], (const float*)d_in[17]};
    const float* fcw   = (const float*)d_in[18];
    const float* fcb   = (const float*)d_in[19];

    int N = in_sizes[2];
    int E = in_sizes[1] / 2;
    int G = out_size;

    float *bufM, *bufH, *gsum, *gcnt;
    cudaGetSymbolAddress((void**)&bufM, g_bufM);
    cudaGetSymbolAddress((void**)&bufH, g_bufH);
    cudaGetSymbolAddress((void**)&gsum, g_gsum);
    cudaGetSymbolAddress((void**)&gcnt, g_gcnt);

    size_t smem = (size_t)(16384 * 2 + BM * LDA + 128 * 3) * sizeof(float);
    cudaFuncSetAttribute(mlp_kernel, cudaFuncAttributeMaxDynamicSharedMemorySize,
                         (int)smem);

    cudaMemsetAsync(gsum, 0, (size_t)G * sizeof(float));
    cudaMemsetAsync(gcnt, 0, (size_t)G * sizeof(float));

    const float* hp = x;
    for (int l = 0; l < 3; l++) {
        int n4 = N * 32;  // float4 count
        scale_kernel<<<(n4 + 255) / 256, 256>>>(hp, bufM, epss[l], n4);
        scatter_kernel<<<((size_t)E * 32 + 255) / 256, 256>>>(hp, bufM, ei, E);
        mlp_kernel<<<(N + BM - 1) / BM, 256, smem>>>(
            bufM, bufH, W1s[l], b1s[l], W2s[l], b2s[l],
            N, (l < 2) ? 1 : 0, (l == 2) ? 1 : 0,
            batch, fcw, gsum, gcnt);
        hp = bufH;
    }
    final_kernel<<<(G + 255) / 256, 256>>>(gsum, gcnt, fcb, (float*)d_out, G);
}

// round 3
// speedup vs baseline: 1.6202x; 1.6202x over previous
#include <cuda_runtime.h>
#include <cuda_bf16.h>
#include <cstdint>

// ---------------------------------------------------------------------------
// GINRegressor on GB300 (PTX target lacks sm_103a features -> use mma.sync).
// 3x [memset agg; scatter-add; fused MLP(split-bf16 tensor GEMM x2)] + pool/FC.
//
// Inputs (metadata order):
//  0 x [N*128] f32, 1 edge_index [2*E] i32, 2 batch [N] i32,
//  3..7   W1_0,b1_0,W2_0,b2_0,eps_0
//  8..12  W1_1,b1_1,W2_1,b2_1,eps_1
//  13..17 W1_2,b1_2,W2_2,b2_2,eps_2
//  18 fc_w [128], 19 fc_b [1]
// Output: [G] f32
// ---------------------------------------------------------------------------

#define NMAX 50000
#define GMAX 500
#define LDT 136  // padded smem tile stride (bf16 elems) -> conflict-free

__device__ float g_agg[NMAX * 128];
__device__ float g_bufH[NMAX * 128];
__device__ float g_gsum[GMAX];
__device__ float g_gcnt[GMAX];
__device__ __align__(16) __nv_bfloat16 g_wthi[6 * 16384];  // W^T hi planes
__device__ __align__(16) __nv_bfloat16 g_wtlo[6 * 16384];  // W^T lo planes

// ---------------- helpers ----------------
__device__ __forceinline__ uint32_t smem_u32(const void* p) {
    uint32_t a;
    asm("{ .reg .u64 t; cvta.to.shared.u64 t, %1; cvt.u32.u64 %0, t; }"
        : "=r"(a) : "l"(p));
    return a;
}

__device__ __forceinline__ void ldmA(uint32_t* a, uint32_t addr) {
    asm volatile("ldmatrix.sync.aligned.m8n8.x4.shared.b16 {%0,%1,%2,%3}, [%4];"
                 : "=r"(a[0]), "=r"(a[1]), "=r"(a[2]), "=r"(a[3]) : "r"(addr));
}

__device__ __forceinline__ void mma16816(float* c, const uint32_t* a,
                                         uint32_t b0, uint32_t b1) {
    asm volatile(
        "mma.sync.aligned.m16n8k16.row.col.f32.bf16.bf16.f32 "
        "{%0,%1,%2,%3}, {%4,%5,%6,%7}, {%8,%9}, {%0,%1,%2,%3};"
        : "+f"(c[0]), "+f"(c[1]), "+f"(c[2]), "+f"(c[3])
        : "r"(a[0]), "r"(a[1]), "r"(a[2]), "r"(a[3]), "r"(b0), "r"(b1));
}

__device__ __forceinline__ uint32_t pack_hi(float a, float b, float& ra, float& rb) {
    __nv_bfloat16 ha = __float2bfloat16(a), hb = __float2bfloat16(b);
    ra = a - __bfloat162float(ha);
    rb = b - __bfloat162float(hb);
    return ((uint32_t)__bfloat16_as_ushort(hb) << 16) | __bfloat16_as_ushort(ha);
}
__device__ __forceinline__ uint32_t pack_lo(float a, float b) {
    return ((uint32_t)__bfloat16_as_ushort(__float2bfloat16(b)) << 16) |
           __bfloat16_as_ushort(__float2bfloat16(a));
}

// ---------------- small kernels ----------------

// transpose + bf16-split all 6 weight matrices: out[m][n*128+k] = W_m[k*128+n]
__global__ void wprep_kernel(const float* __restrict__ Wa, const float* __restrict__ Wb,
                             const float* __restrict__ Wc, const float* __restrict__ Wd,
                             const float* __restrict__ We, const float* __restrict__ Wf,
                             __nv_bfloat16* __restrict__ hi,
                             __nv_bfloat16* __restrict__ lo) {
    int t = blockIdx.x * blockDim.x + threadIdx.x;  // 0 .. 6*16384-1
    int m = t >> 14;
    int i = t & 16383;
    int n = i >> 7, k = i & 127;
    const float* W = (m == 0) ? Wa : (m == 1) ? Wb : (m == 2) ? Wc
                   : (m == 3) ? Wd : (m == 4) ? We : Wf;
    float v = W[k * 128 + n];
    __nv_bfloat16 h = __float2bfloat16(v);
    hi[t] = h;
    lo[t] = __float2bfloat16(v - __bfloat162float(h));
}

// One warp per edge: agg[dst] += X[src] via vector reductions (no return).
__global__ void scatter_kernel(const float* __restrict__ X, float* __restrict__ M,
                               const int* __restrict__ ei, int E) {
    int gtid = blockIdx.x * blockDim.x + threadIdx.x;
    int e = gtid >> 5;
    int lane = gtid & 31;
    if (e >= E) return;
    int src = ei[e];
    int dst = ei[E + e];
    float4 v = ((const float4*)(X + (size_t)src * 128))[lane];
    float* mp = M + (size_t)dst * 128 + lane * 4;
    asm volatile("red.global.add.v4.f32 [%0], {%1,%2,%3,%4};"
                 :: "l"(mp), "f"(v.x), "f"(v.y), "f"(v.z), "f"(v.w) : "memory");
}

__global__ void final_kernel(const float* __restrict__ gsum,
                             const float* __restrict__ gcnt,
                             const float* __restrict__ fcb,
                             float* __restrict__ out, int G) {
    int i = blockIdx.x * blockDim.x + threadIdx.x;
    if (i < G) out[i] = gsum[i] / fmaxf(gcnt[i], 1.0f) + fcb[0];
}

// ---------------- fused MLP ----------------
// smem byte offsets
#define SM_B1H 0
#define SM_B1L 34816
#define SM_B2H 69632
#define SM_B2L 104448
#define SM_AH  139264
#define SM_AL  174080
#define SM_SB1 208896
#define SM_SB2 209408
#define SM_SFW 209920
#define SM_SROW 210432
#define SM_TOTAL 210944

// split-bf16 GEMM: acc += Ah*Bh + Ah*Bl + Al*Bh  (per-warp 32x64 tile)
__device__ __forceinline__ void gemm_tile(
    const __nv_bfloat16* sAh, const __nv_bfloat16* sAl,
    const __nv_bfloat16* sBh, const __nv_bfloat16* sBl,
    float acc[2][8][4], int wr, int wc, int lane) {
    for (int prod = 0; prod < 3; prod++) {
        const __nv_bfloat16* Ap = (prod == 2) ? sAl : sAh;
        const __nv_bfloat16* Bp = (prod == 1) ? sBl : sBh;
        int arow = wr * 32 + (lane & 15);
        int acol = (lane >> 4) * 8;
        int bn = wc * 64 + (lane >> 2);
        int bk = (lane & 3) * 2;
        #pragma unroll 2
        for (int k0 = 0; k0 < 8; k0++) {
            uint32_t a0[4], a1[4];
            ldmA(a0, smem_u32(Ap + arow * LDT + k0 * 16 + acol));
            ldmA(a1, smem_u32(Ap + (arow + 16) * LDT + k0 * 16 + acol));
            #pragma unroll
            for (int nf = 0; nf < 8; nf++) {
                const __nv_bfloat16* bp = Bp + (bn + nf * 8) * LDT + k0 * 16 + bk;
                uint32_t b0 = *(const uint32_t*)bp;
                uint32_t b1 = *(const uint32_t*)(bp + 8);
                mma16816(acc[0][nf], a0, b0, b1);
                mma16816(acc[1][nf], a1, b0, b1);
            }
        }
    }
}

__global__ __launch_bounds__(256, 1) void mlp_kernel(
    const float* __restrict__ X, const float* __restrict__ AGG,
    float* __restrict__ H,
    const __nv_bfloat16* __restrict__ W1h, const __nv_bfloat16* __restrict__ W1l,
    const __nv_bfloat16* __restrict__ W2h, const __nv_bfloat16* __restrict__ W2l,
    const float* __restrict__ b1, const float* __restrict__ b2,
    const float* __restrict__ epsp,
    int n, int relu_out, int pool,
    const int* __restrict__ batch, const float* __restrict__ fcw,
    float* __restrict__ gsum, float* __restrict__ gcnt) {
    extern __shared__ char sm[];
    __nv_bfloat16* sB1h = (__nv_bfloat16*)(sm + SM_B1H);
    __nv_bfloat16* sB1l = (__nv_bfloat16*)(sm + SM_B1L);
    __nv_bfloat16* sB2h = (__nv_bfloat16*)(sm + SM_B2H);
    __nv_bfloat16* sB2l = (__nv_bfloat16*)(sm + SM_B2L);
    __nv_bfloat16* sAh  = (__nv_bfloat16*)(sm + SM_AH);
    __nv_bfloat16* sAl  = (__nv_bfloat16*)(sm + SM_AL);
    float* sb1  = (float*)(sm + SM_SB1);
    float* sb2  = (float*)(sm + SM_SB2);
    float* sfw  = (float*)(sm + SM_SFW);
    float* srow = (float*)(sm + SM_SROW);

    int tid = threadIdx.x;
    int lane = tid & 31;
    int wid = tid >> 5;
    int wr = wid & 3, wc = wid >> 2;

    if (tid < 128) {
        sb1[tid] = b1[tid];
        sb2[tid] = b2[tid];
        sfw[tid] = fcw[tid];
        srow[tid] = 0.f;
    }

    // load 4 weight planes into padded smem tiles
    {
        const uint4* p1h = (const uint4*)W1h;
        const uint4* p1l = (const uint4*)W1l;
        const uint4* p2h = (const uint4*)W2h;
        const uint4* p2l = (const uint4*)W2l;
        for (int i = tid; i < 2048; i += 256) {
            int r = i >> 4, c = (i & 15) * 8;
            int d = r * LDT + c;
            *(uint4*)&sB1h[d] = p1h[i];
            *(uint4*)&sB1l[d] = p1l[i];
            *(uint4*)&sB2h[d] = p2h[i];
            *(uint4*)&sB2l[d] = p2l[i];
        }
    }

    // build A = (1+eps)*X + AGG, split to bf16 hi/lo planes
    int row0 = blockIdx.x * 128;
    float s = 1.0f + __ldg(epsp);
    for (int i = tid; i < 4096; i += 256) {
        int r = i >> 5, c4 = i & 31;
        int gr = row0 + r;
        float4 v = make_float4(0.f, 0.f, 0.f, 0.f);
        if (gr < n) {
            float4 xv = ((const float4*)X)[(size_t)gr * 32 + c4];
            float4 av = ((const float4*)AGG)[(size_t)gr * 32 + c4];
            v.x = fmaf(s, xv.x, av.x);
            v.y = fmaf(s, xv.y, av.y);
            v.z = fmaf(s, xv.z, av.z);
            v.w = fmaf(s, xv.w, av.w);
        }
        float r0, r1, r2, r3;
        uint2 hi2, lo2;
        hi2.x = pack_hi(v.x, v.y, r0, r1);
        hi2.y = pack_hi(v.z, v.w, r2, r3);
        lo2.x = pack_lo(r0, r1);
        lo2.y = pack_lo(r2, r3);
        int d = r * LDT + c4 * 4;
        *(uint2*)&sAh[d] = hi2;
        *(uint2*)&sAl[d] = lo2;
    }
    __syncthreads();

    float acc[2][8][4];
    #pragma unroll
    for (int i = 0; i < 2; i++)
        #pragma unroll
        for (int j = 0; j < 8; j++)
            #pragma unroll
            for (int q = 0; q < 4; q++) acc[i][j][q] = 0.f;

    // GEMM1
    gemm_tile(sAh, sAl, sB1h, sB1l, acc, wr, wc, lane);
    __syncthreads();  // all reads of sA done

    // epilogue1: T = ReLU(acc + b1) -> split back into sA planes
    #pragma unroll
    for (int rf = 0; rf < 2; rf++) {
        int r = wr * 32 + rf * 16 + (lane >> 2);
        #pragma unroll
        for (int nf = 0; nf < 8; nf++) {
            int c = wc * 64 + nf * 8 + (lane & 3) * 2;
            float* a = acc[rf][nf];
            float v0 = fmaxf(a[0] + sb1[c], 0.f);
            float v1 = fmaxf(a[1] + sb1[c + 1], 0.f);
            float v2 = fmaxf(a[2] + sb1[c], 0.f);
            float v3 = fmaxf(a[3] + sb1[c + 1], 0.f);
            float q0, q1;
            uint32_t h = pack_hi(v0, v1, q0, q1);
            *(uint32_t*)&sAh[r * LDT + c] = h;
            *(uint32_t*)&sAl[r * LDT + c] = pack_lo(q0, q1);
            h = pack_hi(v2, v3, q0, q1);
            *(uint32_t*)&sAh[(r + 8) * LDT + c] = h;
            *(uint32_t*)&sAl[(r + 8) * LDT + c] = pack_lo(q0, q1);
        }
    }
    __syncthreads();

    #pragma unroll
    for (int i = 0; i < 2; i++)
        #pragma unroll
        for (int j = 0; j < 8; j++)
            #pragma unroll
            for (int q = 0; q < 4; q++) acc[i][j][q] = 0.f;

    // GEMM2
    gemm_tile(sAh, sAl, sB2h, sB2l, acc, wr, wc, lane);

    // epilogue2
    if (!pool) {
        #pragma unroll
        for (int rf = 0; rf < 2; rf++) {
            int r = wr * 32 + rf * 16 + (lane >> 2);
            int gr0 = row0 + r, gr1 = gr0 + 8;
            #pragma unroll
            for (int nf = 0; nf < 8; nf++) {
                int c = wc * 64 + nf * 8 + (lane & 3) * 2;
                float* a = acc[rf][nf];
                float v0 = a[0] + sb2[c], v1 = a[1] + sb2[c + 1];
                float v2 = a[2] + sb2[c], v3 = a[3] + sb2[c + 1];
                if (relu_out) {
                    v0 = fmaxf(v0, 0.f); v1 = fmaxf(v1, 0.f);
                    v2 = fmaxf(v2, 0.f); v3 = fmaxf(v3, 0.f);
                }
                if (gr0 < n) *(float2*)&H[(size_t)gr0 * 128 + c] = make_float2(v0, v1);
                if (gr1 < n) *(float2*)&H[(size_t)gr1 * 128 + c] = make_float2(v2, v3);
            }
        }
    } else {
        #pragma unroll
        for (int rf = 0; rf < 2; rf++) {
            int r = wr * 32 + rf * 16 + (lane >> 2);
            float d0 = 0.f, d1 = 0.f;
            #pragma unroll
            for (int nf = 0; nf < 8; nf++) {
                int c = wc * 64 + nf * 8 + (lane & 3) * 2;
                float* a = acc[rf][nf];
                d0 = fmaf(a[0] + sb2[c], sfw[c], d0);
                d0 = fmaf(a[1] + sb2[c + 1], sfw[c + 1], d0);
                d1 = fmaf(a[2] + sb2[c], sfw[c], d1);
                d1 = fmaf(a[3] + sb2[c + 1], sfw[c + 1], d1);
            }
            atomicAdd(&srow[r], d0);
            atomicAdd(&srow[r + 8], d1);
        }
        __syncthreads();
        if (tid < 128) {
            int gr = row0 + tid;
            if (gr < n) {
                int g = batch[gr];
                atomicAdd(&gsum[g], srow[tid]);
                atomicAdd(&gcnt[g], 1.0f);
            }
        }
    }
}

// ---------------- host launcher ----------------
extern "C" void kernel_launch(void* const* d_in, const int* in_sizes, int n_in,
                              void* d_out, int out_size) {
    const float* x     = (const float*)d_in[0];
    const int*   ei    = (const int*)d_in[1];
    const int*   batch = (const int*)d_in[2];
    const float* W1s[3] = {(const float*)d_in[3],  (const float*)d_in[8],  (const float*)d_in[13]};
    const float* b1s[3] = {(const float*)d_in[4],  (const float*)d_in[9],  (const float*)d_in[14]};
    const float* W2s[3] = {(const float*)d_in[5],  (const float*)d_in[10], (const float*)d_in[15]};
    const float* b2s[3] = {(const float*)d_in[6],  (const float*)d_in[11], (const float*)d_in[16]};
    const float* epss[3]= {(const float*)d_in[7],  (const float*)d_in[12], (const float*)d_in[17]};
    const float* fcw   = (const float*)d_in[18];
    const float* fcb   = (const float*)d_in[19];

    int N = in_sizes[2];
    int E = in_sizes[1] / 2;
    int G = out_size;

    float *agg, *bufH, *gsum, *gcnt;
    __nv_bfloat16 *wthi, *wtlo;
    cudaGetSymbolAddress((void**)&agg,  g_agg);
    cudaGetSymbolAddress((void**)&bufH, g_bufH);
    cudaGetSymbolAddress((void**)&gsum, g_gsum);
    cudaGetSymbolAddress((void**)&gcnt, g_gcnt);
    cudaGetSymbolAddress((void**)&wthi, g_wthi);
    cudaGetSymbolAddress((void**)&wtlo, g_wtlo);

    cudaFuncSetAttribute(mlp_kernel, cudaFuncAttributeMaxDynamicSharedMemorySize, SM_TOTAL);

    // prep: transpose + bf16-split all 6 weight matrices (order: W1_0,W2_0,W1_1,W2_1,W1_2,W2_2)
    wprep_kernel<<<384, 256>>>(W1s[0], W2s[0], W1s[1], W2s[1], W1s[2], W2s[2], wthi, wtlo);

    cudaMemsetAsync(gsum, 0, (size_t)G * sizeof(float));
    cudaMemsetAsync(gcnt, 0, (size_t)G * sizeof(float));

    const float* hp = x;
    int nblk = (N + 127) / 128;
    for (int l = 0; l < 3; l++) {
        cudaMemsetAsync(agg, 0, (size_t)N * 128 * sizeof(float));
        scatter_kernel<<<(int)(((size_t)E * 32 + 255) / 256), 256>>>(hp, agg, ei, E);
        mlp_kernel<<<nblk, 256, SM_TOTAL>>>(
            hp, agg, bufH,
            wthi + (2 * l) * 16384, wtlo + (2 * l) * 16384,
            wthi + (2 * l + 1) * 16384, wtlo + (2 * l + 1) * 16384,
            b1s[l], b2s[l], epss[l],
            N, (l < 2) ? 1 : 0, (l == 2) ? 1 : 0,
            batch, fcw, gsum, gcnt);
        hp = bufH;
    }
    final_kernel<<<(G + 255) / 256, 256>>>(gsum, gcnt, fcb, (float*)d_out, G);
}

// round 5
// speedup vs baseline: 1.7395x; 1.0737x over previous
#include <cuda_runtime.h>
#include <cuda_bf16.h>
#include <cstdint>

// ---------------------------------------------------------------------------
// GINRegressor on GB300: CSR gather-aggregation fused into split-bf16 tensor
// MLP (mma.sync m16n8k16). CSR built once per launch. Ping-pong layer buffers
// (gather reads arbitrary rows -> input and output must not alias).
//
// Inputs (metadata order):
//  0 x [N*128] f32, 1 edge_index [2*E] i32, 2 batch [N] i32,
//  3..7   W1_0,b1_0,W2_0,b2_0,eps_0
//  8..12  W1_1,b1_1,W2_1,b2_1,eps_1
//  13..17 W1_2,b1_2,W2_2,b2_2,eps_2
//  18 fc_w [128], 19 fc_b [1]
// Output: [G] f32
// ---------------------------------------------------------------------------

#define NMAX 50000
#define EMAX 800000
#define GMAX 500
#define LDT 136  // padded smem tile stride (bf16 elems) -> conflict-free

__device__ float g_bufA[NMAX * 128];
__device__ float g_bufB[NMAX * 128];
__device__ float g_gsum[GMAX];
__device__ float g_gcnt[GMAX];
__device__ int   g_rowptr[NMAX + 1];
__device__ int   g_cursor[NMAX];
__device__ int   g_csrc[EMAX];
__device__ __align__(16) __nv_bfloat16 g_wthi[6 * 16384];  // W^T hi planes
__device__ __align__(16) __nv_bfloat16 g_wtlo[6 * 16384];  // W^T lo planes

// ---------------- helpers ----------------
__device__ __forceinline__ uint32_t smem_u32(const void* p) {
    uint32_t a;
    asm("{ .reg .u64 t; cvta.to.shared.u64 t, %1; cvt.u32.u64 %0, t; }"
        : "=r"(a) : "l"(p));
    return a;
}

__device__ __forceinline__ void ldmA(uint32_t* a, uint32_t addr) {
    asm volatile("ldmatrix.sync.aligned.m8n8.x4.shared.b16 {%0,%1,%2,%3}, [%4];"
                 : "=r"(a[0]), "=r"(a[1]), "=r"(a[2]), "=r"(a[3]) : "r"(addr));
}

__device__ __forceinline__ void mma16816(float* c, const uint32_t* a,
                                         uint32_t b0, uint32_t b1) {
    asm volatile(
        "mma.sync.aligned.m16n8k16.row.col.f32.bf16.bf16.f32 "
        "{%0,%1,%2,%3}, {%4,%5,%6,%7}, {%8,%9}, {%0,%1,%2,%3};"
        : "+f"(c[0]), "+f"(c[1]), "+f"(c[2]), "+f"(c[3])
        : "r"(a[0]), "r"(a[1]), "r"(a[2]), "r"(a[3]), "r"(b0), "r"(b1));
}

__device__ __forceinline__ uint32_t pack_hi(float a, float b, float& ra, float& rb) {
    __nv_bfloat16 ha = __float2bfloat16(a), hb = __float2bfloat16(b);
    ra = a - __bfloat162float(ha);
    rb = b - __bfloat162float(hb);
    return ((uint32_t)__bfloat16_as_ushort(hb) << 16) | __bfloat16_as_ushort(ha);
}
__device__ __forceinline__ uint32_t pack_lo(float a, float b) {
    return ((uint32_t)__bfloat16_as_ushort(__float2bfloat16(b)) << 16) |
           __bfloat16_as_ushort(__float2bfloat16(a));
}

// ---------------- CSR build (once per launch) ----------------
__global__ void count_kernel(const int* __restrict__ ei, int* __restrict__ cnt, int E) {
    int t = blockIdx.x * blockDim.x + threadIdx.x;
    if (t < E) atomicAdd(&cnt[ei[E + t]], 1);
}

// single-block exclusive scan over counts (in cursor) -> rowptr, cursor=excl
__global__ __launch_bounds__(1024) void scan_kernel(int* __restrict__ cursor,
                                                    int* __restrict__ rowptr, int N) {
    __shared__ int warpsums[32];
    __shared__ int s_carry;
    int tid = threadIdx.x, lane = tid & 31, wid = tid >> 5;
    if (tid == 0) s_carry = 0;
    __syncthreads();
    for (int base = 0; base < N; base += 1024) {
        int i = base + tid;
        int v = (i < N) ? cursor[i] : 0;
        int x = v;
        #pragma unroll
        for (int d = 1; d < 32; d <<= 1) {
            int y = __shfl_up_sync(0xffffffffu, x, d);
            if (lane >= d) x += y;
        }
        if (lane == 31) warpsums[wid] = x;
        __syncthreads();
        if (wid == 0) {
            int w = warpsums[lane];
            #pragma unroll
            for (int d = 1; d < 32; d <<= 1) {
                int y = __shfl_up_sync(0xffffffffu, w, d);
                if (lane >= d) w += y;
            }
            warpsums[lane] = w;
        }
        __syncthreads();
        int excl = x - v + ((wid > 0) ? warpsums[wid - 1] : 0) + s_carry;
        if (i < N) { rowptr[i] = excl; cursor[i] = excl; }
        __syncthreads();
        if (tid == 0) s_carry += warpsums[31];
        __syncthreads();
    }
    if (threadIdx.x == 0) rowptr[N] = s_carry;
}

__global__ void fill_kernel(const int* __restrict__ ei, int* __restrict__ cursor,
                            int* __restrict__ csrc, int E) {
    int t = blockIdx.x * blockDim.x + threadIdx.x;
    if (t < E) {
        int d = ei[E + t];
        int p = atomicAdd(&cursor[d], 1);
        csrc[p] = ei[t];
    }
}

// ---------------- small kernels ----------------
__global__ void wprep_kernel(const float* __restrict__ Wa, const float* __restrict__ Wb,
                             const float* __restrict__ Wc, const float* __restrict__ Wd,
                             const float* __restrict__ We, const float* __restrict__ Wf,
                             __nv_bfloat16* __restrict__ hi,
                             __nv_bfloat16* __restrict__ lo) {
    int t = blockIdx.x * blockDim.x + threadIdx.x;  // 0 .. 6*16384-1
    int m = t >> 14;
    int i = t & 16383;
    int n = i >> 7, k = i & 127;
    const float* W = (m == 0) ? Wa : (m == 1) ? Wb : (m == 2) ? Wc
                   : (m == 3) ? Wd : (m == 4) ? We : Wf;
    float v = W[k * 128 + n];
    __nv_bfloat16 h = __float2bfloat16(v);
    hi[t] = h;
    lo[t] = __float2bfloat16(v - __bfloat162float(h));
}

__global__ void final_kernel(const float* __restrict__ gsum,
                             const float* __restrict__ gcnt,
                             const float* __restrict__ fcb,
                             float* __restrict__ out, int G) {
    int i = blockIdx.x * blockDim.x + threadIdx.x;
    if (i < G) out[i] = gsum[i] / fmaxf(gcnt[i], 1.0f) + fcb[0];
}

// ---------------- fused aggregate + MLP ----------------
// smem byte offsets
#define SM_B1H 0
#define SM_B1L 34816
#define SM_B2H 69632
#define SM_B2L 104448
#define SM_AH  139264
#define SM_AL  174080
#define SM_SB1 208896
#define SM_SB2 209408
#define SM_SFW 209920
#define SM_SROW 210432
#define SM_TOTAL 210944

// split-bf16 GEMM: acc += Ah*Bh + Ah*Bl + Al*Bh  (per-warp 32x64 tile)
__device__ __forceinline__ void gemm_tile(
    const __nv_bfloat16* sAh, const __nv_bfloat16* sAl,
    const __nv_bfloat16* sBh, const __nv_bfloat16* sBl,
    float acc[2][8][4], int wr, int wc, int lane) {
    for (int prod = 0; prod < 3; prod++) {
        const __nv_bfloat16* Ap = (prod == 2) ? sAl : sAh;
        const __nv_bfloat16* Bp = (prod == 1) ? sBl : sBh;
        int arow = wr * 32 + (lane & 15);
        int acol = (lane >> 4) * 8;
        int bn = wc * 64 + (lane >> 2);
        int bk = (lane & 3) * 2;
        #pragma unroll 2
        for (int k0 = 0; k0 < 8; k0++) {
            uint32_t a0[4], a1[4];
            ldmA(a0, smem_u32(Ap + arow * LDT + k0 * 16 + acol));
            ldmA(a1, smem_u32(Ap + (arow + 16) * LDT + k0 * 16 + acol));
            #pragma unroll
            for (int nf = 0; nf < 8; nf++) {
                const __nv_bfloat16* bp = Bp + (bn + nf * 8) * LDT + k0 * 16 + bk;
                uint32_t b0 = *(const uint32_t*)bp;
                uint32_t b1 = *(const uint32_t*)(bp + 8);
                mma16816(acc[0][nf], a0, b0, b1);
                mma16816(acc[1][nf], a1, b0, b1);
            }
        }
    }
}

__global__ __launch_bounds__(256, 1) void mlp_kernel(
    const float* __restrict__ X,
    const int* __restrict__ rowptr, const int* __restrict__ csrc,
    float* __restrict__ H,
    const __nv_bfloat16* __restrict__ W1h, const __nv_bfloat16* __restrict__ W1l,
    const __nv_bfloat16* __restrict__ W2h, const __nv_bfloat16* __restrict__ W2l,
    const float* __restrict__ b1, const float* __restrict__ b2,
    const float* __restrict__ epsp,
    int n, int relu_out, int pool,
    const int* __restrict__ batch, const float* __restrict__ fcw,
    float* __restrict__ gsum, float* __restrict__ gcnt) {
    extern __shared__ char sm[];
    __nv_bfloat16* sB1h = (__nv_bfloat16*)(sm + SM_B1H);
    __nv_bfloat16* sB1l = (__nv_bfloat16*)(sm + SM_B1L);
    __nv_bfloat16* sB2h = (__nv_bfloat16*)(sm + SM_B2H);
    __nv_bfloat16* sB2l = (__nv_bfloat16*)(sm + SM_B2L);
    __nv_bfloat16* sAh  = (__nv_bfloat16*)(sm + SM_AH);
    __nv_bfloat16* sAl  = (__nv_bfloat16*)(sm + SM_AL);
    float* sb1  = (float*)(sm + SM_SB1);
    float* sb2  = (float*)(sm + SM_SB2);
    float* sfw  = (float*)(sm + SM_SFW);
    float* srow = (float*)(sm + SM_SROW);

    int tid = threadIdx.x;
    int lane = tid & 31;
    int wid = tid >> 5;
    int wr = wid & 3, wc = wid >> 2;

    if (tid < 128) {
        sb1[tid] = b1[tid];
        sb2[tid] = b2[tid];
        sfw[tid] = fcw[tid];
        srow[tid] = 0.f;
    }

    // load 4 weight planes into padded smem tiles
    {
        const uint4* p1h = (const uint4*)W1h;
        const uint4* p1l = (const uint4*)W1l;
        const uint4* p2h = (const uint4*)W2h;
        const uint4* p2l = (const uint4*)W2l;
        for (int i = tid; i < 2048; i += 256) {
            int r = i >> 4, c = (i & 15) * 8;
            int d = r * LDT + c;
            *(uint4*)&sB1h[d] = p1h[i];
            *(uint4*)&sB1l[d] = p1l[i];
            *(uint4*)&sB2h[d] = p2h[i];
            *(uint4*)&sB2l[d] = p2l[i];
        }
    }

    // build A = (1+eps)*X[row] + sum_{j in nbrs(row)} X[j]; split bf16 hi/lo.
    // warp-per-row: lane owns columns [lane*4, lane*4+3].
    int row0 = blockIdx.x * 128;
    float s = 1.0f + __ldg(epsp);
    const float4* X4 = (const float4*)X;
    for (int r = wid; r < 128; r += 8) {
        int gr = row0 + r;
        float4 v = make_float4(0.f, 0.f, 0.f, 0.f);
        if (gr < n) {
            float4 xv = X4[(size_t)gr * 32 + lane];
            v.x = s * xv.x; v.y = s * xv.y; v.z = s * xv.z; v.w = s * xv.w;
            int beg = __ldg(&rowptr[gr]);
            int end = __ldg(&rowptr[gr + 1]);
            int j = beg;
            for (; j + 4 <= end; j += 4) {
                int s0 = __ldg(&csrc[j]);
                int s1 = __ldg(&csrc[j + 1]);
                int s2 = __ldg(&csrc[j + 2]);
                int s3 = __ldg(&csrc[j + 3]);
                float4 a0 = X4[(size_t)s0 * 32 + lane];
                float4 a1 = X4[(size_t)s1 * 32 + lane];
                float4 a2 = X4[(size_t)s2 * 32 + lane];
                float4 a3 = X4[(size_t)s3 * 32 + lane];
                v.x += a0.x + a1.x + a2.x + a3.x;
                v.y += a0.y + a1.y + a2.y + a3.y;
                v.z += a0.z + a1.z + a2.z + a3.z;
                v.w += a0.w + a1.w + a2.w + a3.w;
            }
            for (; j < end; j++) {
                int s0 = __ldg(&csrc[j]);
                float4 a0 = X4[(size_t)s0 * 32 + lane];
                v.x += a0.x; v.y += a0.y; v.z += a0.z; v.w += a0.w;
            }
        }
        float r0, r1, r2, r3;
        uint2 hi2, lo2;
        hi2.x = pack_hi(v.x, v.y, r0, r1);
        hi2.y = pack_hi(v.z, v.w, r2, r3);
        lo2.x = pack_lo(r0, r1);
        lo2.y = pack_lo(r2, r3);
        int d = r * LDT + lane * 4;
        *(uint2*)&sAh[d] = hi2;
        *(uint2*)&sAl[d] = lo2;
    }
    __syncthreads();

    float acc[2][8][4];
    #pragma unroll
    for (int i = 0; i < 2; i++)
        #pragma unroll
        for (int j = 0; j < 8; j++)
            #pragma unroll
            for (int q = 0; q < 4; q++) acc[i][j][q] = 0.f;

    // GEMM1
    gemm_tile(sAh, sAl, sB1h, sB1l, acc, wr, wc, lane);
    __syncthreads();  // all reads of sA done

    // epilogue1: T = ReLU(acc + b1) -> split back into sA planes
    #pragma unroll
    for (int rf = 0; rf < 2; rf++) {
        int r = wr * 32 + rf * 16 + (lane >> 2);
        #pragma unroll
        for (int nf = 0; nf < 8; nf++) {
            int c = wc * 64 + nf * 8 + (lane & 3) * 2;
            float* a = acc[rf][nf];
            float v0 = fmaxf(a[0] + sb1[c], 0.f);
            float v1 = fmaxf(a[1] + sb1[c + 1], 0.f);
            float v2 = fmaxf(a[2] + sb1[c], 0.f);
            float v3 = fmaxf(a[3] + sb1[c + 1], 0.f);
            float q0, q1;
            uint32_t h = pack_hi(v0, v1, q0, q1);
            *(uint32_t*)&sAh[r * LDT + c] = h;
            *(uint32_t*)&sAl[r * LDT + c] = pack_lo(q0, q1);
            h = pack_hi(v2, v3, q0, q1);
            *(uint32_t*)&sAh[(r + 8) * LDT + c] = h;
            *(uint32_t*)&sAl[(r + 8) * LDT + c] = pack_lo(q0, q1);
        }
    }
    __syncthreads();

    #pragma unroll
    for (int i = 0; i < 2; i++)
        #pragma unroll
        for (int j = 0; j < 8; j++)
            #pragma unroll
            for (int q = 0; q < 4; q++) acc[i][j][q] = 0.f;

    // GEMM2
    gemm_tile(sAh, sAl, sB2h, sB2l, acc, wr, wc, lane);

    // epilogue2
    if (!pool) {
        #pragma unroll
        for (int rf = 0; rf < 2; rf++) {
            int r = wr * 32 + rf * 16 + (lane >> 2);
            int gr0 = row0 + r, gr1 = gr0 + 8;
            #pragma unroll
            for (int nf = 0; nf < 8; nf++) {
                int c = wc * 64 + nf * 8 + (lane & 3) * 2;
                float* a = acc[rf][nf];
                float v0 = a[0] + sb2[c], v1 = a[1] + sb2[c + 1];
                float v2 = a[2] + sb2[c], v3 = a[3] + sb2[c + 1];
                if (relu_out) {
                    v0 = fmaxf(v0, 0.f); v1 = fmaxf(v1, 0.f);
                    v2 = fmaxf(v2, 0.f); v3 = fmaxf(v3, 0.f);
                }
                if (gr0 < n) *(float2*)&H[(size_t)gr0 * 128 + c] = make_float2(v0, v1);
                if (gr1 < n) *(float2*)&H[(size_t)gr1 * 128 + c] = make_float2(v2, v3);
            }
        }
    } else {
        #pragma unroll
        for (int rf = 0; rf < 2; rf++) {
            int r = wr * 32 + rf * 16 + (lane >> 2);
            float d0 = 0.f, d1 = 0.f;
            #pragma unroll
            for (int nf = 0; nf < 8; nf++) {
                int c = wc * 64 + nf * 8 + (lane & 3) * 2;
                float* a = acc[rf][nf];
                d0 = fmaf(a[0] + sb2[c], sfw[c], d0);
                d0 = fmaf(a[1] + sb2[c + 1], sfw[c + 1], d0);
                d1 = fmaf(a[2] + sb2[c], sfw[c], d1);
                d1 = fmaf(a[3] + sb2[c + 1], sfw[c + 1], d1);
            }
            atomicAdd(&srow[r], d0);
            atomicAdd(&srow[r + 8], d1);
        }
        __syncthreads();
        if (tid < 128) {
            int gr = row0 + tid;
            if (gr < n) {
                int g = batch[gr];
                atomicAdd(&gsum[g], srow[tid]);
                atomicAdd(&gcnt[g], 1.0f);
            }
        }
    }
}

// ---------------- host launcher ----------------
extern "C" void kernel_launch(void* const* d_in, const int* in_sizes, int n_in,
                              void* d_out, int out_size) {
    const float* x     = (const float*)d_in[0];
    const int*   ei    = (const int*)d_in[1];
    const int*   batch = (const int*)d_in[2];
    const float* W1s[3] = {(const float*)d_in[3],  (const float*)d_in[8],  (const float*)d_in[13]};
    const float* b1s[3] = {(const float*)d_in[4],  (const float*)d_in[9],  (const float*)d_in[14]};
    const float* W2s[3] = {(const float*)d_in[5],  (const float*)d_in[10], (const float*)d_in[15]};
    const float* b2s[3] = {(const float*)d_in[6],  (const float*)d_in[11], (const float*)d_in[16]};
    const float* epss[3]= {(const float*)d_in[7],  (const float*)d_in[12], (const float*)d_in[17]};
    const float* fcw   = (const float*)d_in[18];
    const float* fcb   = (const float*)d_in[19];

    int N = in_sizes[2];
    int E = in_sizes[1] / 2;
    int G = out_size;

    float *bufA, *bufB, *gsum, *gcnt;
    int *rowptr, *cursor, *csrc;
    __nv_bfloat16 *wthi, *wtlo;
    cudaGetSymbolAddress((void**)&bufA, g_bufA);
    cudaGetSymbolAddress((void**)&bufB, g_bufB);
    cudaGetSymbolAddress((void**)&gsum, g_gsum);
    cudaGetSymbolAddress((void**)&gcnt, g_gcnt);
    cudaGetSymbolAddress((void**)&rowptr, g_rowptr);
    cudaGetSymbolAddress((void**)&cursor, g_cursor);
    cudaGetSymbolAddress((void**)&csrc, g_csrc);
    cudaGetSymbolAddress((void**)&wthi, g_wthi);
    cudaGetSymbolAddress((void**)&wtlo, g_wtlo);

    cudaFuncSetAttribute(mlp_kernel, cudaFuncAttributeMaxDynamicSharedMemorySize, SM_TOTAL);

    // CSR build (graph constant across layers)
    cudaMemsetAsync(cursor, 0, (size_t)N * sizeof(int));
    count_kernel<<<(E + 255) / 256, 256>>>(ei, cursor, E);
    scan_kernel<<<1, 1024>>>(cursor, rowptr, N);
    fill_kernel<<<(E + 255) / 256, 256>>>(ei, cursor, csrc, E);

    // weight transpose + bf16 split (order: W1_0,W2_0,W1_1,W2_1,W1_2,W2_2)
    wprep_kernel<<<384, 256>>>(W1s[0], W2s[0], W1s[1], W2s[1], W1s[2], W2s[2], wthi, wtlo);

    cudaMemsetAsync(gsum, 0, (size_t)G * sizeof(float));
    cudaMemsetAsync(gcnt, 0, (size_t)G * sizeof(float));

    // ping-pong: layer0 x->bufA, layer1 bufA->bufB, layer2 bufB->pool
    const float* ins[3]  = {x, bufA, bufB};
    float*       outs[3] = {bufA, bufB, bufA /* unused (pool) */};
    int nblk = (N + 127) / 128;
    for (int l = 0; l < 3; l++) {
        mlp_kernel<<<nblk, 256, SM_TOTAL>>>(
            ins[l], rowptr, csrc, outs[l],
            wthi + (2 * l) * 16384, wtlo + (2 * l) * 16384,
            wthi + (2 * l + 1) * 16384, wtlo + (2 * l + 1) * 16384,
            b1s[l], b2s[l], epss[l],
            N, (l < 2) ? 1 : 0, (l == 2) ? 1 : 0,
            batch, fcw, gsum, gcnt);
    }
    final_kernel<<<(G + 255) / 256, 256>>>(gsum, gcnt, fcb, (float*)d_out, G);
}

// round 6
// speedup vs baseline: 1.7582x; 1.0108x over previous
#include <cuda_runtime.h>
#include <cuda_bf16.h>
#include <cstdint>

// ---------------------------------------------------------------------------
// GINRegressor on GB300: CSR gather-aggregation fused into split-bf16 tensor
// MLP (mma.sync m16n8k16). Persistent CTAs (weights loaded once per layer).
// Ping-pong layer buffers. CSR built once per launch.
// ---------------------------------------------------------------------------

#define NMAX 50000
#define EMAX 800000
#define GMAX 500
#define LDT 136  // padded smem tile stride (bf16 elems) -> conflict-free

__device__ float g_bufA[NMAX * 128];
__device__ float g_bufB[NMAX * 128];
__device__ float g_gsum[GMAX];
__device__ float g_gcnt[GMAX];
__device__ int   g_rowptr[NMAX + 1];
__device__ int   g_cursor[NMAX];
__device__ int   g_csrc[EMAX];
__device__ __align__(16) __nv_bfloat16 g_wthi[6 * 16384];  // W^T hi planes
__device__ __align__(16) __nv_bfloat16 g_wtlo[6 * 16384];  // W^T lo planes

// ---------------- helpers ----------------
__device__ __forceinline__ uint32_t smem_u32(const void* p) {
    uint32_t a;
    asm("{ .reg .u64 t; cvta.to.shared.u64 t, %1; cvt.u32.u64 %0, t; }"
        : "=r"(a) : "l"(p));
    return a;
}

__device__ __forceinline__ void ldmA(uint32_t* a, uint32_t addr) {
    asm volatile("ldmatrix.sync.aligned.m8n8.x4.shared.b16 {%0,%1,%2,%3}, [%4];"
                 : "=r"(a[0]), "=r"(a[1]), "=r"(a[2]), "=r"(a[3]) : "r"(addr));
}

__device__ __forceinline__ void mma16816(float* c, const uint32_t* a,
                                         uint32_t b0, uint32_t b1) {
    asm volatile(
        "mma.sync.aligned.m16n8k16.row.col.f32.bf16.bf16.f32 "
        "{%0,%1,%2,%3}, {%4,%5,%6,%7}, {%8,%9}, {%0,%1,%2,%3};"
        : "+f"(c[0]), "+f"(c[1]), "+f"(c[2]), "+f"(c[3])
        : "r"(a[0]), "r"(a[1]), "r"(a[2]), "r"(a[3]), "r"(b0), "r"(b1));
}

__device__ __forceinline__ uint32_t pack_hi(float a, float b, float& ra, float& rb) {
    __nv_bfloat16 ha = __float2bfloat16(a), hb = __float2bfloat16(b);
    ra = a - __bfloat162float(ha);
    rb = b - __bfloat162float(hb);
    return ((uint32_t)__bfloat16_as_ushort(hb) << 16) | __bfloat16_as_ushort(ha);
}
__device__ __forceinline__ uint32_t pack_lo(float a, float b) {
    return ((uint32_t)__bfloat16_as_ushort(__float2bfloat16(b)) << 16) |
           __bfloat16_as_ushort(__float2bfloat16(a));
}

// ---------------- prep: weight transform + zero init ----------------
// grid 384 x 256 = 98304 threads = 6*16384 exactly
__global__ void wprep_kernel(const float* __restrict__ Wa, const float* __restrict__ Wb,
                             const float* __restrict__ Wc, const float* __restrict__ Wd,
                             const float* __restrict__ We, const float* __restrict__ Wf,
                             __nv_bfloat16* __restrict__ hi,
                             __nv_bfloat16* __restrict__ lo,
                             int* __restrict__ cursor, float* __restrict__ gsum,
                             float* __restrict__ gcnt, int N, int G) {
    int t = blockIdx.x * blockDim.x + threadIdx.x;  // 0 .. 6*16384-1
    if (t < N) cursor[t] = 0;
    if (t < G) { gsum[t] = 0.f; gcnt[t] = 0.f; }
    int m = t >> 14;
    int i = t & 16383;
    int n = i >> 7, k = i & 127;
    const float* W = (m == 0) ? Wa : (m == 1) ? Wb : (m == 2) ? Wc
                   : (m == 3) ? Wd : (m == 4) ? We : Wf;
    float v = W[k * 128 + n];
    __nv_bfloat16 h = __float2bfloat16(v);
    hi[t] = h;
    lo[t] = __float2bfloat16(v - __bfloat162float(h));
}

// ---------------- CSR build ----------------
__global__ void count_kernel(const int* __restrict__ ei, int* __restrict__ cnt, int E) {
    int t = blockIdx.x * blockDim.x + threadIdx.x;
    if (t < E) atomicAdd(&cnt[ei[E + t]], 1);
}

// single-block exclusive scan over counts (in cursor) -> rowptr, cursor=excl
__global__ __launch_bounds__(1024) void scan_kernel(int* __restrict__ cursor,
                                                    int* __restrict__ rowptr, int N) {
    __shared__ int warpsums[32];
    __shared__ int s_carry;
    int tid = threadIdx.x, lane = tid & 31, wid = tid >> 5;
    if (tid == 0) s_carry = 0;
    __syncthreads();
    for (int base = 0; base < N; base += 1024) {
        int i = base + tid;
        int v = (i < N) ? cursor[i] : 0;
        int x = v;
        #pragma unroll
        for (int d = 1; d < 32; d <<= 1) {
            int y = __shfl_up_sync(0xffffffffu, x, d);
            if (lane >= d) x += y;
        }
        if (lane == 31) warpsums[wid] = x;
        __syncthreads();
        if (wid == 0) {
            int w = warpsums[lane];
            #pragma unroll
            for (int d = 1; d < 32; d <<= 1) {
                int y = __shfl_up_sync(0xffffffffu, w, d);
                if (lane >= d) w += y;
            }
            warpsums[lane] = w;
        }
        __syncthreads();
        int excl = x - v + ((wid > 0) ? warpsums[wid - 1] : 0) + s_carry;
        if (i < N) { rowptr[i] = excl; cursor[i] = excl; }
        __syncthreads();
        if (tid == 0) s_carry += warpsums[31];
        __syncthreads();
    }
    if (threadIdx.x == 0) rowptr[N] = s_carry;
}

__global__ void fill_kernel(const int* __restrict__ ei, int* __restrict__ cursor,
                            int* __restrict__ csrc, int E) {
    int t = blockIdx.x * blockDim.x + threadIdx.x;
    if (t < E) {
        int d = ei[E + t];
        int p = atomicAdd(&cursor[d], 1);
        csrc[p] = ei[t];
    }
}

__global__ void final_kernel(const float* __restrict__ gsum,
                             const float* __restrict__ gcnt,
                             const float* __restrict__ fcb,
                             float* __restrict__ out, int G) {
    int i = blockIdx.x * blockDim.x + threadIdx.x;
    if (i < G) out[i] = gsum[i] / fmaxf(gcnt[i], 1.0f) + fcb[0];
}

// ---------------- fused aggregate + MLP (persistent) ----------------
// smem byte offsets
#define SM_B1H 0
#define SM_B1L 34816
#define SM_B2H 69632
#define SM_B2L 104448
#define SM_AH  139264
#define SM_AL  174080
#define SM_SB1 208896
#define SM_SB2 209408
#define SM_SFW 209920
#define SM_SROW 210432
#define SM_TOTAL 210944

// split-bf16 GEMM: acc += Ah*Bh + Ah*Bl + Al*Bh  (per-warp 32x64 tile)
__device__ __forceinline__ void gemm_tile(
    const __nv_bfloat16* sAh, const __nv_bfloat16* sAl,
    const __nv_bfloat16* sBh, const __nv_bfloat16* sBl,
    float acc[2][8][4], int wr, int wc, int lane) {
    for (int prod = 0; prod < 3; prod++) {
        const __nv_bfloat16* Ap = (prod == 2) ? sAl : sAh;
        const __nv_bfloat16* Bp = (prod == 1) ? sBl : sBh;
        int arow = wr * 32 + (lane & 15);
        int acol = (lane >> 4) * 8;
        int bn = wc * 64 + (lane >> 2);
        int bk = (lane & 3) * 2;
        #pragma unroll 2
        for (int k0 = 0; k0 < 8; k0++) {
            uint32_t a0[4], a1[4];
            ldmA(a0, smem_u32(Ap + arow * LDT + k0 * 16 + acol));
            ldmA(a1, smem_u32(Ap + (arow + 16) * LDT + k0 * 16 + acol));
            #pragma unroll
            for (int nf = 0; nf < 8; nf++) {
                const __nv_bfloat16* bp = Bp + (bn + nf * 8) * LDT + k0 * 16 + bk;
                uint32_t b0 = *(const uint32_t*)bp;
                uint32_t b1 = *(const uint32_t*)(bp + 8);
                mma16816(acc[0][nf], a0, b0, b1);
                mma16816(acc[1][nf], a1, b0, b1);
            }
        }
    }
}

// accumulate 4 neighbor rows
#define GATHER4(v, J)                                                     \
    do {                                                                  \
        int t0 = __ldg(&csrc[(J)]);                                       \
        int t1 = __ldg(&csrc[(J) + 1]);                                   \
        int t2 = __ldg(&csrc[(J) + 2]);                                   \
        int t3 = __ldg(&csrc[(J) + 3]);                                   \
        float4 m0 = X4[(size_t)t0 * 32 + lane];                           \
        float4 m1 = X4[(size_t)t1 * 32 + lane];                           \
        float4 m2 = X4[(size_t)t2 * 32 + lane];                           \
        float4 m3 = X4[(size_t)t3 * 32 + lane];                           \
        v.x += m0.x + m1.x + m2.x + m3.x;                                 \
        v.y += m0.y + m1.y + m2.y + m3.y;                                 \
        v.z += m0.z + m1.z + m2.z + m3.z;                                 \
        v.w += m0.w + m1.w + m2.w + m3.w;                                 \
    } while (0)

__global__ __launch_bounds__(256, 1) void mlp_kernel(
    const float* __restrict__ X,
    const int* __restrict__ rowptr, const int* __restrict__ csrc,
    float* __restrict__ H,
    const __nv_bfloat16* __restrict__ W1h, const __nv_bfloat16* __restrict__ W1l,
    const __nv_bfloat16* __restrict__ W2h, const __nv_bfloat16* __restrict__ W2l,
    const float* __restrict__ b1, const float* __restrict__ b2,
    const float* __restrict__ epsp,
    int n, int ntiles, int relu_out, int pool,
    const int* __restrict__ batch, const float* __restrict__ fcw,
    float* __restrict__ gsum, float* __restrict__ gcnt) {
    extern __shared__ char sm[];
    __nv_bfloat16* sB1h = (__nv_bfloat16*)(sm + SM_B1H);
    __nv_bfloat16* sB1l = (__nv_bfloat16*)(sm + SM_B1L);
    __nv_bfloat16* sB2h = (__nv_bfloat16*)(sm + SM_B2H);
    __nv_bfloat16* sB2l = (__nv_bfloat16*)(sm + SM_B2L);
    __nv_bfloat16* sAh  = (__nv_bfloat16*)(sm + SM_AH);
    __nv_bfloat16* sAl  = (__nv_bfloat16*)(sm + SM_AL);
    float* sb1  = (float*)(sm + SM_SB1);
    float* sb2  = (float*)(sm + SM_SB2);
    float* sfw  = (float*)(sm + SM_SFW);
    float* srow = (float*)(sm + SM_SROW);

    int tid = threadIdx.x;
    int lane = tid & 31;
    int wid = tid >> 5;
    int wr = wid & 3, wc = wid >> 2;

    if (tid < 128) {
        sb1[tid] = b1[tid];
        sb2[tid] = b2[tid];
        sfw[tid] = fcw[tid];
    }

    // load 4 weight planes once (persistent)
    {
        const uint4* p1h = (const uint4*)W1h;
        const uint4* p1l = (const uint4*)W1l;
        const uint4* p2h = (const uint4*)W2h;
        const uint4* p2l = (const uint4*)W2l;
        for (int i = tid; i < 2048; i += 256) {
            int r = i >> 4, c = (i & 15) * 8;
            int d = r * LDT + c;
            *(uint4*)&sB1h[d] = p1h[i];
            *(uint4*)&sB1l[d] = p1l[i];
            *(uint4*)&sB2h[d] = p2h[i];
            *(uint4*)&sB2l[d] = p2l[i];
        }
    }

    float s = 1.0f + __ldg(epsp);
    const float4* X4 = (const float4*)X;

    for (int tile = blockIdx.x; tile < ntiles; tile += gridDim.x) {
        int row0 = tile * 128;
        if (tid < 128) srow[tid] = 0.f;

        // gather: A = (1+eps)*X[row] + sum_nbrs X[j]; two rows per warp
        // iteration for deeper MLP. lane owns columns [lane*4, lane*4+3].
        for (int r2 = wid; r2 < 64; r2 += 8) {
            int rA = r2, rB = r2 + 64;
            int grA = row0 + rA, grB = row0 + rB;
            float4 va = make_float4(0.f, 0.f, 0.f, 0.f);
            float4 vb = make_float4(0.f, 0.f, 0.f, 0.f);
            int ja = 0, ea = 0, jb = 0, eb = 0;
            if (grA < n) {
                float4 xv = X4[(size_t)grA * 32 + lane];
                va.x = s * xv.x; va.y = s * xv.y; va.z = s * xv.z; va.w = s * xv.w;
                ja = __ldg(&rowptr[grA]); ea = __ldg(&rowptr[grA + 1]);
            }
            if (grB < n) {
                float4 xv = X4[(size_t)grB * 32 + lane];
                vb.x = s * xv.x; vb.y = s * xv.y; vb.z = s * xv.z; vb.w = s * xv.w;
                jb = __ldg(&rowptr[grB]); eb = __ldg(&rowptr[grB + 1]);
            }
            // joint phase: 8 row-loads in flight
            while (ja + 4 <= ea && jb + 4 <= eb) {
                GATHER4(va, ja);
                GATHER4(vb, jb);
                ja += 4; jb += 4;
            }
            // drain A
            for (; ja + 4 <= ea; ja += 4) GATHER4(va, ja);
            for (; ja < ea; ja++) {
                int t0 = __ldg(&csrc[ja]);
                float4 m0 = X4[(size_t)t0 * 32 + lane];
                va.x += m0.x; va.y += m0.y; va.z += m0.z; va.w += m0.w;
            }
            // drain B
            for (; jb + 4 <= eb; jb += 4) GATHER4(vb, jb);
            for (; jb < eb; jb++) {
                int t0 = __ldg(&csrc[jb]);
                float4 m0 = X4[(size_t)t0 * 32 + lane];
                vb.x += m0.x; vb.y += m0.y; vb.z += m0.z; vb.w += m0.w;
            }
            // pack + store both rows
            float q0, q1, q2, q3;
            uint2 hi2, lo2;
            hi2.x = pack_hi(va.x, va.y, q0, q1);
            hi2.y = pack_hi(va.z, va.w, q2, q3);
            lo2.x = pack_lo(q0, q1);
            lo2.y = pack_lo(q2, q3);
            int d = rA * LDT + lane * 4;
            *(uint2*)&sAh[d] = hi2;
            *(uint2*)&sAl[d] = lo2;
            hi2.x = pack_hi(vb.x, vb.y, q0, q1);
            hi2.y = pack_hi(vb.z, vb.w, q2, q3);
            lo2.x = pack_lo(q0, q1);
            lo2.y = pack_lo(q2, q3);
            d = rB * LDT + lane * 4;
            *(uint2*)&sAh[d] = hi2;
            *(uint2*)&sAl[d] = lo2;
        }
        __syncthreads();

        float acc[2][8][4];
        #pragma unroll
        for (int i = 0; i < 2; i++)
            #pragma unroll
            for (int j = 0; j < 8; j++)
                #pragma unroll
                for (int q = 0; q < 4; q++) acc[i][j][q] = 0.f;

        // GEMM1
        gemm_tile(sAh, sAl, sB1h, sB1l, acc, wr, wc, lane);
        __syncthreads();  // all reads of sA done

        // epilogue1: T = ReLU(acc + b1) -> split back into sA planes
        #pragma unroll
        for (int rf = 0; rf < 2; rf++) {
            int r = wr * 32 + rf * 16 + (lane >> 2);
            #pragma unroll
            for (int nf = 0; nf < 8; nf++) {
                int c = wc * 64 + nf * 8 + (lane & 3) * 2;
                float* a = acc[rf][nf];
                float v0 = fmaxf(a[0] + sb1[c], 0.f);
                float v1 = fmaxf(a[1] + sb1[c + 1], 0.f);
                float v2 = fmaxf(a[2] + sb1[c], 0.f);
                float v3 = fmaxf(a[3] + sb1[c + 1], 0.f);
                float q0, q1;
                uint32_t h = pack_hi(v0, v1, q0, q1);
                *(uint32_t*)&sAh[r * LDT + c] = h;
                *(uint32_t*)&sAl[r * LDT + c] = pack_lo(q0, q1);
                h = pack_hi(v2, v3, q0, q1);
                *(uint32_t*)&sAh[(r + 8) * LDT + c] = h;
                *(uint32_t*)&sAl[(r + 8) * LDT + c] = pack_lo(q0, q1);
            }
        }
        __syncthreads();

        #pragma unroll
        for (int i = 0; i < 2; i++)
            #pragma unroll
            for (int j = 0; j < 8; j++)
                #pragma unroll
                for (int q = 0; q < 4; q++) acc[i][j][q] = 0.f;

        // GEMM2
        gemm_tile(sAh, sAl, sB2h, sB2l, acc, wr, wc, lane);

        // epilogue2
        if (!pool) {
            #pragma unroll
            for (int rf = 0; rf < 2; rf++) {
                int r = wr * 32 + rf * 16 + (lane >> 2);
                int gr0 = row0 + r, gr1 = gr0 + 8;
                #pragma unroll
                for (int nf = 0; nf < 8; nf++) {
                    int c = wc * 64 + nf * 8 + (lane & 3) * 2;
                    float* a = acc[rf][nf];
                    float v0 = a[0] + sb2[c], v1 = a[1] + sb2[c + 1];
                    float v2 = a[2] + sb2[c], v3 = a[3] + sb2[c + 1];
                    if (relu_out) {
                        v0 = fmaxf(v0, 0.f); v1 = fmaxf(v1, 0.f);
                        v2 = fmaxf(v2, 0.f); v3 = fmaxf(v3, 0.f);
                    }
                    if (gr0 < n) *(float2*)&H[(size_t)gr0 * 128 + c] = make_float2(v0, v1);
                    if (gr1 < n) *(float2*)&H[(size_t)gr1 * 128 + c] = make_float2(v2, v3);
                }
            }
        } else {
            #pragma unroll
            for (int rf = 0; rf < 2; rf++) {
                int r = wr * 32 + rf * 16 + (lane >> 2);
                float d0 = 0.f, d1 = 0.f;
                #pragma unroll
                for (int nf = 0; nf < 8; nf++) {
                    int c = wc * 64 + nf * 8 + (lane & 3) * 2;
                    float* a = acc[rf][nf];
                    d0 = fmaf(a[0] + sb2[c], sfw[c], d0);
                    d0 = fmaf(a[1] + sb2[c + 1], sfw[c + 1], d0);
                    d1 = fmaf(a[2] + sb2[c], sfw[c], d1);
                    d1 = fmaf(a[3] + sb2[c + 1], sfw[c + 1], d1);
                }
                atomicAdd(&srow[r], d0);
                atomicAdd(&srow[r + 8], d1);
            }
            __syncthreads();
            if (tid < 128) {
                int gr = row0 + tid;
                if (gr < n) {
                    int g = batch[gr];
                    atomicAdd(&gsum[g], srow[tid]);
                    atomicAdd(&gcnt[g], 1.0f);
                }
            }
        }
        __syncthreads();  // protect sA before next tile's gather
    }
}

// ---------------- host launcher ----------------
extern "C" void kernel_launch(void* const* d_in, const int* in_sizes, int n_in,
                              void* d_out, int out_size) {
    const float* x     = (const float*)d_in[0];
    const int*   ei    = (const int*)d_in[1];
    const int*   batch = (const int*)d_in[2];
    const float* W1s[3] = {(const float*)d_in[3],  (const float*)d_in[8],  (const float*)d_in[13]};
    const float* b1s[3] = {(const float*)d_in[4],  (const float*)d_in[9],  (const float*)d_in[14]};
    const float* W2s[3] = {(const float*)d_in[5],  (const float*)d_in[10], (const float*)d_in[15]};
    const float* b2s[3] = {(const float*)d_in[6],  (const float*)d_in[11], (const float*)d_in[16]};
    const float* epss[3]= {(const float*)d_in[7],  (const float*)d_in[12], (const float*)d_in[17]};
    const float* fcw   = (const float*)d_in[18];
    const float* fcb   = (const float*)d_in[19];

    int N = in_sizes[2];
    int E = in_sizes[1] / 2;
    int G = out_size;

    float *bufA, *bufB, *gsum, *gcnt;
    int *rowptr, *cursor, *csrc;
    __nv_bfloat16 *wthi, *wtlo;
    cudaGetSymbolAddress((void**)&bufA, g_bufA);
    cudaGetSymbolAddress((void**)&bufB, g_bufB);
    cudaGetSymbolAddress((void**)&gsum, g_gsum);
    cudaGetSymbolAddress((void**)&gcnt, g_gcnt);
    cudaGetSymbolAddress((void**)&rowptr, g_rowptr);
    cudaGetSymbolAddress((void**)&cursor, g_cursor);
    cudaGetSymbolAddress((void**)&csrc, g_csrc);
    cudaGetSymbolAddress((void**)&wthi, g_wthi);
    cudaGetSymbolAddress((void**)&wtlo, g_wtlo);

    cudaFuncSetAttribute(mlp_kernel, cudaFuncAttributeMaxDynamicSharedMemorySize, SM_TOTAL);

    // 1: weight transform + zero init (cursor/gsum/gcnt)
    wprep_kernel<<<384, 256>>>(W1s[0], W2s[0], W1s[1], W2s[1], W1s[2], W2s[2],
                               wthi, wtlo, cursor, gsum, gcnt, N, G);
    // 2-4: CSR build (graph constant across layers)
    count_kernel<<<(E + 255) / 256, 256>>>(ei, cursor, E);
    scan_kernel<<<1, 1024>>>(cursor, rowptr, N);
    fill_kernel<<<(E + 255) / 256, 256>>>(ei, cursor, csrc, E);

    // ping-pong: layer0 x->bufA, layer1 bufA->bufB, layer2 bufB->pool
    const float* ins[3]  = {x, bufA, bufB};
    float*       outs[3] = {bufA, bufB, bufA /* unused (pool) */};
    int ntiles = (N + 127) / 128;
    for (int l = 0; l < 3; l++) {
        mlp_kernel<<<148, 256, SM_TOTAL>>>(
            ins[l], rowptr, csrc, outs[l],
            wthi + (2 * l) * 16384, wtlo + (2 * l) * 16384,
            wthi + (2 * l + 1) * 16384, wtlo + (2 * l + 1) * 16384,
            b1s[l], b2s[l], epss[l],
            N, ntiles, (l < 2) ? 1 : 0, (l == 2) ? 1 : 0,
            batch, fcw, gsum, gcnt);
    }
    final_kernel<<<(G + 255) / 256, 256>>>(gsum, gcnt, fcb, (float*)d_out, G);
}

// round 7
// speedup vs baseline: 1.8013x; 1.0245x over previous
#include <cuda_runtime.h>
#include <cuda_bf16.h>
#include <cstdint>

// ---------------------------------------------------------------------------
// GINRegressor on GB300: CSR gather-aggregation fused into split-bf16 tensor
// MLP (mma.sync m16n8k16). Persistent CTAs. Ping-pong layer buffers.
// Launch order: prep(1), scan(2), fill(3), mlp0(4), mlp1(5), mlp2(6), final(7).
// State invariant: cursor/gsum/gcnt are zero at kernel_launch entry
// (zero-initialized at module load; final_kernel re-zeroes them each call).
// Layer 2: second GEMM folded into a GEMV via w2fc = W2_2 @ fc_w.
// ---------------------------------------------------------------------------

#define NMAX 50000
#define EMAX 800000
#define GMAX 500
#define LDT 136  // padded smem tile stride (bf16 elems) -> conflict-free

__device__ float g_bufA[NMAX * 128];
__device__ float g_bufB[NMAX * 128];
__device__ float g_gsum[GMAX];
__device__ float g_gcnt[GMAX];
__device__ int   g_rowptr[NMAX + 1];
__device__ int   g_cursor[NMAX];          // zero at entry (invariant)
__device__ int   g_csrc[EMAX];
__device__ float g_w2fc[129];             // [0..127]=W2_2@fc, [128]=b2_2.fc
__device__ __align__(16) __nv_bfloat16 g_wthi[6 * 16384];  // W^T hi planes
__device__ __align__(16) __nv_bfloat16 g_wtlo[6 * 16384];  // W^T lo planes

// ---------------- helpers ----------------
__device__ __forceinline__ uint32_t smem_u32(const void* p) {
    uint32_t a;
    asm("{ .reg .u64 t; cvta.to.shared.u64 t, %1; cvt.u32.u64 %0, t; }"
        : "=r"(a) : "l"(p));
    return a;
}

__device__ __forceinline__ void ldmA(uint32_t* a, uint32_t addr) {
    asm volatile("ldmatrix.sync.aligned.m8n8.x4.shared.b16 {%0,%1,%2,%3}, [%4];"
                 : "=r"(a[0]), "=r"(a[1]), "=r"(a[2]), "=r"(a[3]) : "r"(addr));
}

__device__ __forceinline__ void mma16816(float* c, const uint32_t* a,
                                         uint32_t b0, uint32_t b1) {
    asm volatile(
        "mma.sync.aligned.m16n8k16.row.col.f32.bf16.bf16.f32 "
        "{%0,%1,%2,%3}, {%4,%5,%6,%7}, {%8,%9}, {%0,%1,%2,%3};"
        : "+f"(c[0]), "+f"(c[1]), "+f"(c[2]), "+f"(c[3])
        : "r"(a[0]), "r"(a[1]), "r"(a[2]), "r"(a[3]), "r"(b0), "r"(b1));
}

__device__ __forceinline__ uint32_t pack_hi(float a, float b, float& ra, float& rb) {
    __nv_bfloat16 ha = __float2bfloat16(a), hb = __float2bfloat16(b);
    ra = a - __bfloat162float(ha);
    rb = b - __bfloat162float(hb);
    return ((uint32_t)__bfloat16_as_ushort(hb) << 16) | __bfloat16_as_ushort(ha);
}
__device__ __forceinline__ uint32_t pack_lo(float a, float b) {
    return ((uint32_t)__bfloat16_as_ushort(__float2bfloat16(b)) << 16) |
           __bfloat16_as_ushort(__float2bfloat16(a));
}

// ---------------- prep: weight transform + edge count + w2fc ----------------
// grid covers max(E, 6*16384) threads
__global__ void prep_kernel(const float* __restrict__ Wa, const float* __restrict__ Wb,
                            const float* __restrict__ Wc, const float* __restrict__ Wd,
                            const float* __restrict__ We, const float* __restrict__ Wf,
                            __nv_bfloat16* __restrict__ hi, __nv_bfloat16* __restrict__ lo,
                            const int* __restrict__ ei, int* __restrict__ cnt, int E,
                            const float* __restrict__ fcw, const float* __restrict__ b2f,
                            float* __restrict__ w2fc) {
    int t = blockIdx.x * blockDim.x + threadIdx.x;
    if (t < 6 * 16384) {
        int m = t >> 14;
        int i = t & 16383;
        int n = i >> 7, k = i & 127;
        const float* W = (m == 0) ? Wa : (m == 1) ? Wb : (m == 2) ? Wc
                       : (m == 3) ? Wd : (m == 4) ? We : Wf;
        float v = W[k * 128 + n];
        __nv_bfloat16 h = __float2bfloat16(v);
        hi[t] = h;
        lo[t] = __float2bfloat16(v - __bfloat162float(h));
    } else if (t < 6 * 16384 + 128) {
        // w2fc[k] = sum_c W2_2[k,c] * fc[c]
        int k = t - 6 * 16384;
        float s = 0.f;
        #pragma unroll 4
        for (int c = 0; c < 128; c++) s = fmaf(Wf[k * 128 + c], fcw[c], s);
        w2fc[k] = s;
    } else if (t == 6 * 16384 + 128) {
        float s = 0.f;
        for (int c = 0; c < 128; c++) s = fmaf(b2f[c], fcw[c], s);
        w2fc[128] = s;
    }
    if (t < E) atomicAdd(&cnt[ei[E + t]], 1);
}

// ---------------- CSR build ----------------
// single-block exclusive scan over counts (in cursor) -> rowptr, cursor=excl
__global__ __launch_bounds__(1024) void scan_kernel(int* __restrict__ cursor,
                                                    int* __restrict__ rowptr, int N) {
    __shared__ int warpsums[32];
    __shared__ int s_carry;
    int tid = threadIdx.x, lane = tid & 31, wid = tid >> 5;
    if (tid == 0) s_carry = 0;
    __syncthreads();
    for (int base = 0; base < N; base += 1024) {
        int i = base + tid;
        int v = (i < N) ? cursor[i] : 0;
        int x = v;
        #pragma unroll
        for (int d = 1; d < 32; d <<= 1) {
            int y = __shfl_up_sync(0xffffffffu, x, d);
            if (lane >= d) x += y;
        }
        if (lane == 31) warpsums[wid] = x;
        __syncthreads();
        if (wid == 0) {
            int w = warpsums[lane];
            #pragma unroll
            for (int d = 1; d < 32; d <<= 1) {
                int y = __shfl_up_sync(0xffffffffu, w, d);
                if (lane >= d) w += y;
            }
            warpsums[lane] = w;
        }
        __syncthreads();
        int excl = x - v + ((wid > 0) ? warpsums[wid - 1] : 0) + s_carry;
        if (i < N) { rowptr[i] = excl; cursor[i] = excl; }
        __syncthreads();
        if (tid == 0) s_carry += warpsums[31];
        __syncthreads();
    }
    if (threadIdx.x == 0) rowptr[N] = s_carry;
}

__global__ void fill_kernel(const int* __restrict__ ei, int* __restrict__ cursor,
                            int* __restrict__ csrc, int E) {
    int t = blockIdx.x * blockDim.x + threadIdx.x;
    if (t < E) {
        int d = ei[E + t];
        int p = atomicAdd(&cursor[d], 1);
        csrc[p] = ei[t];
    }
}

// final output + restore invariants (cursor/gsum/gcnt = 0) for next call
__global__ void final_kernel(float* __restrict__ gsum, float* __restrict__ gcnt,
                             const float* __restrict__ fcb,
                             float* __restrict__ out, int G,
                             int* __restrict__ cursor, int N) {
    int i = blockIdx.x * blockDim.x + threadIdx.x;
    if (i < G) {
        out[i] = gsum[i] / fmaxf(gcnt[i], 1.0f) + fcb[0];
        gsum[i] = 0.f;
        gcnt[i] = 0.f;
    }
    if (i < N) cursor[i] = 0;
}

// ---------------- fused aggregate + MLP (persistent) ----------------
// smem byte offsets
#define SM_B1H 0
#define SM_B1L 34816
#define SM_B2H 69632
#define SM_B2L 104448
#define SM_AH  139264
#define SM_AL  174080
#define SM_SB1 208896
#define SM_SB2 209408
#define SM_SFW 209920
#define SM_SROW 210432
#define SM_TOTAL 210944

// split-bf16 GEMM: acc += Ah*Bh + Ah*Bl + Al*Bh  (per-warp 32x64 tile)
__device__ __forceinline__ void gemm_tile(
    const __nv_bfloat16* sAh, const __nv_bfloat16* sAl,
    const __nv_bfloat16* sBh, const __nv_bfloat16* sBl,
    float acc[2][8][4], int wr, int wc, int lane) {
    for (int prod = 0; prod < 3; prod++) {
        const __nv_bfloat16* Ap = (prod == 2) ? sAl : sAh;
        const __nv_bfloat16* Bp = (prod == 1) ? sBl : sBh;
        int arow = wr * 32 + (lane & 15);
        int acol = (lane >> 4) * 8;
        int bn = wc * 64 + (lane >> 2);
        int bk = (lane & 3) * 2;
        #pragma unroll 2
        for (int k0 = 0; k0 < 8; k0++) {
            uint32_t a0[4], a1[4];
            ldmA(a0, smem_u32(Ap + arow * LDT + k0 * 16 + acol));
            ldmA(a1, smem_u32(Ap + (arow + 16) * LDT + k0 * 16 + acol));
            #pragma unroll
            for (int nf = 0; nf < 8; nf++) {
                const __nv_bfloat16* bp = Bp + (bn + nf * 8) * LDT + k0 * 16 + bk;
                uint32_t b0 = *(const uint32_t*)bp;
                uint32_t b1 = *(const uint32_t*)(bp + 8);
                mma16816(acc[0][nf], a0, b0, b1);
                mma16816(acc[1][nf], a1, b0, b1);
            }
        }
    }
}

// accumulate 4 neighbor rows
#define GATHER4(v, J)                                                     \
    do {                                                                  \
        int t0 = __ldg(&csrc[(J)]);                                       \
        int t1 = __ldg(&csrc[(J) + 1]);                                   \
        int t2 = __ldg(&csrc[(J) + 2]);                                   \
        int t3 = __ldg(&csrc[(J) + 3]);                                   \
        float4 m0 = X4[(size_t)t0 * 32 + lane];                           \
        float4 m1 = X4[(size_t)t1 * 32 + lane];                           \
        float4 m2 = X4[(size_t)t2 * 32 + lane];                           \
        float4 m3 = X4[(size_t)t3 * 32 + lane];                           \
        v.x += m0.x + m1.x + m2.x + m3.x;                                 \
        v.y += m0.y + m1.y + m2.y + m3.y;                                 \
        v.z += m0.z + m1.z + m2.z + m3.z;                                 \
        v.w += m0.w + m1.w + m2.w + m3.w;                                 \
    } while (0)

__global__ __launch_bounds__(256, 1) void mlp_kernel(
    const float* __restrict__ X,
    const int* __restrict__ rowptr, const int* __restrict__ csrc,
    float* __restrict__ H,
    const __nv_bfloat16* __restrict__ W1h, const __nv_bfloat16* __restrict__ W1l,
    const __nv_bfloat16* __restrict__ W2h, const __nv_bfloat16* __restrict__ W2l,
    const float* __restrict__ b1, const float* __restrict__ b2,
    const float* __restrict__ epsp,
    int n, int ntiles, int relu_out, int pool,
    const int* __restrict__ batch, const float* __restrict__ w2fc,
    float* __restrict__ gsum, float* __restrict__ gcnt) {
    extern __shared__ char sm[];
    __nv_bfloat16* sB1h = (__nv_bfloat16*)(sm + SM_B1H);
    __nv_bfloat16* sB1l = (__nv_bfloat16*)(sm + SM_B1L);
    __nv_bfloat16* sB2h = (__nv_bfloat16*)(sm + SM_B2H);
    __nv_bfloat16* sB2l = (__nv_bfloat16*)(sm + SM_B2L);
    __nv_bfloat16* sAh  = (__nv_bfloat16*)(sm + SM_AH);
    __nv_bfloat16* sAl  = (__nv_bfloat16*)(sm + SM_AL);
    float* sb1  = (float*)(sm + SM_SB1);
    float* sb2  = (float*)(sm + SM_SB2);
    float* sfw  = (float*)(sm + SM_SFW);   // holds w2fc for pool layer
    float* srow = (float*)(sm + SM_SROW);

    int tid = threadIdx.x;
    int lane = tid & 31;
    int wid = tid >> 5;
    int wr = wid & 3, wc = wid >> 2;

    if (tid < 128) {
        sb1[tid] = b1[tid];
        sb2[tid] = b2[tid];
        sfw[tid] = w2fc[tid];
    }

    // load weight planes once (persistent); pool layer needs only W1 planes
    {
        const uint4* p1h = (const uint4*)W1h;
        const uint4* p1l = (const uint4*)W1l;
        const uint4* p2h = (const uint4*)W2h;
        const uint4* p2l = (const uint4*)W2l;
        for (int i = tid; i < 2048; i += 256) {
            int r = i >> 4, c = (i & 15) * 8;
            int d = r * LDT + c;
            *(uint4*)&sB1h[d] = p1h[i];
            *(uint4*)&sB1l[d] = p1l[i];
            if (!pool) {
                *(uint4*)&sB2h[d] = p2h[i];
                *(uint4*)&sB2l[d] = p2l[i];
            }
        }
    }

    float s = 1.0f + __ldg(epsp);
    float bconst = __ldg(&w2fc[128]);
    const float4* X4 = (const float4*)X;

    for (int tile = blockIdx.x; tile < ntiles; tile += gridDim.x) {
        int row0 = tile * 128;
        if (tid < 128) srow[tid] = 0.f;

        // gather: A = (1+eps)*X[row] + sum_nbrs X[j]; two rows per warp
        for (int r2 = wid; r2 < 64; r2 += 8) {
            int rA = r2, rB = r2 + 64;
            int grA = row0 + rA, grB = row0 + rB;
            float4 va = make_float4(0.f, 0.f, 0.f, 0.f);
            float4 vb = make_float4(0.f, 0.f, 0.f, 0.f);
            int ja = 0, ea = 0, jb = 0, eb = 0;
            if (grA < n) {
                float4 xv = X4[(size_t)grA * 32 + lane];
                va.x = s * xv.x; va.y = s * xv.y; va.z = s * xv.z; va.w = s * xv.w;
                ja = __ldg(&rowptr[grA]); ea = __ldg(&rowptr[grA + 1]);
            }
            if (grB < n) {
                float4 xv = X4[(size_t)grB * 32 + lane];
                vb.x = s * xv.x; vb.y = s * xv.y; vb.z = s * xv.z; vb.w = s * xv.w;
                jb = __ldg(&rowptr[grB]); eb = __ldg(&rowptr[grB + 1]);
            }
            while (ja + 4 <= ea && jb + 4 <= eb) {
                GATHER4(va, ja);
                GATHER4(vb, jb);
                ja += 4; jb += 4;
            }
            for (; ja + 4 <= ea; ja += 4) GATHER4(va, ja);
            for (; ja < ea; ja++) {
                int t0 = __ldg(&csrc[ja]);
                float4 m0 = X4[(size_t)t0 * 32 + lane];
                va.x += m0.x; va.y += m0.y; va.z += m0.z; va.w += m0.w;
            }
            for (; jb + 4 <= eb; jb += 4) GATHER4(vb, jb);
            for (; jb < eb; jb++) {
                int t0 = __ldg(&csrc[jb]);
                float4 m0 = X4[(size_t)t0 * 32 + lane];
                vb.x += m0.x; vb.y += m0.y; vb.z += m0.z; vb.w += m0.w;
            }
            float q0, q1, q2, q3;
            uint2 hi2, lo2;
            hi2.x = pack_hi(va.x, va.y, q0, q1);
            hi2.y = pack_hi(va.z, va.w, q2, q3);
            lo2.x = pack_lo(q0, q1);
            lo2.y = pack_lo(q2, q3);
            int d = rA * LDT + lane * 4;
            *(uint2*)&sAh[d] = hi2;
            *(uint2*)&sAl[d] = lo2;
            hi2.x = pack_hi(vb.x, vb.y, q0, q1);
            hi2.y = pack_hi(vb.z, vb.w, q2, q3);
            lo2.x = pack_lo(q0, q1);
            lo2.y = pack_lo(q2, q3);
            d = rB * LDT + lane * 4;
            *(uint2*)&sAh[d] = hi2;
            *(uint2*)&sAl[d] = lo2;
        }
        __syncthreads();

        float acc[2][8][4];
        #pragma unroll
        for (int i = 0; i < 2; i++)
            #pragma unroll
            for (int j = 0; j < 8; j++)
                #pragma unroll
                for (int q = 0; q < 4; q++) acc[i][j][q] = 0.f;

        // GEMM1
        gemm_tile(sAh, sAl, sB1h, sB1l, acc, wr, wc, lane);

        if (pool) {
            // layer 2: h.fc = ReLU(acc+b1) @ w2fc (+ bconst per node)
            #pragma unroll
            for (int rf = 0; rf < 2; rf++) {
                int r = wr * 32 + rf * 16 + (lane >> 2);
                float d0 = 0.f, d1 = 0.f;
                #pragma unroll
                for (int nf = 0; nf < 8; nf++) {
                    int c = wc * 64 + nf * 8 + (lane & 3) * 2;
                    float* a = acc[rf][nf];
                    float v0 = fmaxf(a[0] + sb1[c], 0.f);
                    float v1 = fmaxf(a[1] + sb1[c + 1], 0.f);
                    float v2 = fmaxf(a[2] + sb1[c], 0.f);
                    float v3 = fmaxf(a[3] + sb1[c + 1], 0.f);
                    d0 = fmaf(v0, sfw[c], d0);
                    d0 = fmaf(v1, sfw[c + 1], d0);
                    d1 = fmaf(v2, sfw[c], d1);
                    d1 = fmaf(v3, sfw[c + 1], d1);
                }
                atomicAdd(&srow[r], d0);
                atomicAdd(&srow[r + 8], d1);
            }
            __syncthreads();
            if (tid < 128) {
                int gr = row0 + tid;
                if (gr < n) {
                    int g = batch[gr];
                    atomicAdd(&gsum[g], srow[tid] + bconst);
                    atomicAdd(&gcnt[g], 1.0f);
                }
            }
            __syncthreads();
            continue;
        }

        __syncthreads();  // all reads of sA done before overwrite

        // epilogue1: T = ReLU(acc + b1) -> split back into sA planes
        #pragma unroll
        for (int rf = 0; rf < 2; rf++) {
            int r = wr * 32 + rf * 16 + (lane >> 2);
            #pragma unroll
            for (int nf = 0; nf < 8; nf++) {
                int c = wc * 64 + nf * 8 + (lane & 3) * 2;
                float* a = acc[rf][nf];
                float v0 = fmaxf(a[0] + sb1[c], 0.f);
                float v1 = fmaxf(a[1] + sb1[c + 1], 0.f);
                float v2 = fmaxf(a[2] + sb1[c], 0.f);
                float v3 = fmaxf(a[3] + sb1[c + 1], 0.f);
                float q0, q1;
                uint32_t h = pack_hi(v0, v1, q0, q1);
                *(uint32_t*)&sAh[r * LDT + c] = h;
                *(uint32_t*)&sAl[r * LDT + c] = pack_lo(q0, q1);
                h = pack_hi(v2, v3, q0, q1);
                *(uint32_t*)&sAh[(r + 8) * LDT + c] = h;
                *(uint32_t*)&sAl[(r + 8) * LDT + c] = pack_lo(q0, q1);
            }
        }
        __syncthreads();

        #pragma unroll
        for (int i = 0; i < 2; i++)
            #pragma unroll
            for (int j = 0; j < 8; j++)
                #pragma unroll
                for (int q = 0; q < 4; q++) acc[i][j][q] = 0.f;

        // GEMM2
        gemm_tile(sAh, sAl, sB2h, sB2l, acc, wr, wc, lane);

        // epilogue2: out = acc + b2 (+ReLU) -> H
        #pragma unroll
        for (int rf = 0; rf < 2; rf++) {
            int r = wr * 32 + rf * 16 + (lane >> 2);
            int gr0 = row0 + r, gr1 = gr0 + 8;
            #pragma unroll
            for (int nf = 0; nf < 8; nf++) {
                int c = wc * 64 + nf * 8 + (lane & 3) * 2;
                float* a = acc[rf][nf];
                float v0 = a[0] + sb2[c], v1 = a[1] + sb2[c + 1];
                float v2 = a[2] + sb2[c], v3 = a[3] + sb2[c + 1];
                if (relu_out) {
                    v0 = fmaxf(v0, 0.f); v1 = fmaxf(v1, 0.f);
                    v2 = fmaxf(v2, 0.f); v3 = fmaxf(v3, 0.f);
                }
                if (gr0 < n) *(float2*)&H[(size_t)gr0 * 128 + c] = make_float2(v0, v1);
                if (gr1 < n) *(float2*)&H[(size_t)gr1 * 128 + c] = make_float2(v2, v3);
            }
        }
        __syncthreads();  // protect sA before next tile's gather
    }
}

// ---------------- host launcher ----------------
extern "C" void kernel_launch(void* const* d_in, const int* in_sizes, int n_in,
                              void* d_out, int out_size) {
    const float* x     = (const float*)d_in[0];
    const int*   ei    = (const int*)d_in[1];
    const int*   batch = (const int*)d_in[2];
    const float* W1s[3] = {(const float*)d_in[3],  (const float*)d_in[8],  (const float*)d_in[13]};
    const float* b1s[3] = {(const float*)d_in[4],  (const float*)d_in[9],  (const float*)d_in[14]};
    const float* W2s[3] = {(const float*)d_in[5],  (const float*)d_in[10], (const float*)d_in[15]};
    const float* b2s[3] = {(const float*)d_in[6],  (const float*)d_in[11], (const float*)d_in[16]};
    const float* epss[3]= {(const float*)d_in[7],  (const float*)d_in[12], (const float*)d_in[17]};
    const float* fcw   = (const float*)d_in[18];
    const float* fcb   = (const float*)d_in[19];

    int N = in_sizes[2];
    int E = in_sizes[1] / 2;
    int G = out_size;

    float *bufA, *bufB, *gsum, *gcnt, *w2fc;
    int *rowptr, *cursor, *csrc;
    __nv_bfloat16 *wthi, *wtlo;
    cudaGetSymbolAddress((void**)&bufA, g_bufA);
    cudaGetSymbolAddress((void**)&bufB, g_bufB);
    cudaGetSymbolAddress((void**)&gsum, g_gsum);
    cudaGetSymbolAddress((void**)&gcnt, g_gcnt);
    cudaGetSymbolAddress((void**)&rowptr, g_rowptr);
    cudaGetSymbolAddress((void**)&cursor, g_cursor);
    cudaGetSymbolAddress((void**)&csrc, g_csrc);
    cudaGetSymbolAddress((void**)&w2fc, g_w2fc);
    cudaGetSymbolAddress((void**)&wthi, g_wthi);
    cudaGetSymbolAddress((void**)&wtlo, g_wtlo);

    cudaFuncSetAttribute(mlp_kernel, cudaFuncAttributeMaxDynamicSharedMemorySize, SM_TOTAL);

    int prep_threads = (E > 6 * 16384 + 129) ? E : (6 * 16384 + 129);
    // 1: weight transform + edge count + w2fc (cursor==0 invariant at entry)
    prep_kernel<<<(prep_threads + 255) / 256, 256>>>(
        W1s[0], W2s[0], W1s[1], W2s[1], W1s[2], W2s[2],
        wthi, wtlo, ei, cursor, E, fcw, b2s[2], w2fc);
    // 2-3: CSR scan + fill
    scan_kernel<<<1, 1024>>>(cursor, rowptr, N);
    fill_kernel<<<(E + 255) / 256, 256>>>(ei, cursor, csrc, E);

    // 4-6: ping-pong layers; layer2 pools (no GEMM2)
    const float* ins[3]  = {x, bufA, bufB};
    float*       outs[3] = {bufA, bufB, bufA /* unused (pool) */};
    int ntiles = (N + 127) / 128;
    for (int l = 0; l < 3; l++) {
        mlp_kernel<<<148, 256, SM_TOTAL>>>(
            ins[l], rowptr, csrc, outs[l],
            wthi + (2 * l) * 16384, wtlo + (2 * l) * 16384,
            wthi + (2 * l + 1) * 16384, wtlo + (2 * l + 1) * 16384,
            b1s[l], b2s[l], epss[l],
            N, ntiles, (l < 2) ? 1 : 0, (l == 2) ? 1 : 0,
            batch, w2fc, gsum, gcnt);
    }
    // 7: output + restore invariants (cursor/gsum/gcnt -> 0)
    final_kernel<<<(N + 255) / 256, 256>>>(gsum, gcnt, fcb, (float*)d_out, G, cursor, N);
}

// round 8
// speedup vs baseline: 2.3437x; 1.3011x over previous
#include <cuda_runtime.h>
#include <cuda_bf16.h>
#include <cstdint>

// ---------------------------------------------------------------------------
// GINRegressor on GB300: CSR gather fused into split-bf16 tensor MLP.
// 512 threads/CTA (16 warps) for latency hiding; persistent CTAs; ping-pong
// buffers; layer2 second GEMM folded to GEMV (w2fc = W2_2 @ fc_w).
// Launch order: prep(1), scan(2), fill(3), mlp0(4), mlp1(5), mlp2(6), final(7).
// Invariant: cursor/gsum/gcnt zero at entry (final_kernel restores).
// ---------------------------------------------------------------------------

#define NMAX 50000
#define EMAX 800000
#define GMAX 500
#define LDT 136  // padded smem tile stride (bf16 elems) -> conflict-free

__device__ float g_bufA[NMAX * 128];
__device__ float g_bufB[NMAX * 128];
__device__ float g_gsum[GMAX];
__device__ float g_gcnt[GMAX];
__device__ int   g_rowptr[NMAX + 1];
__device__ int   g_cursor[NMAX];          // zero at entry (invariant)
__device__ int   g_csrc[EMAX];
__device__ float g_w2fc[129];             // [0..127]=W2_2@fc, [128]=b2_2.fc
__device__ __align__(16) __nv_bfloat16 g_wthi[6 * 16384];  // W^T hi planes
__device__ __align__(16) __nv_bfloat16 g_wtlo[6 * 16384];  // W^T lo planes

// ---------------- helpers ----------------
__device__ __forceinline__ uint32_t smem_u32(const void* p) {
    uint32_t a;
    asm("{ .reg .u64 t; cvta.to.shared.u64 t, %1; cvt.u32.u64 %0, t; }"
        : "=r"(a) : "l"(p));
    return a;
}

__device__ __forceinline__ void ldmA(uint32_t* a, uint32_t addr) {
    asm volatile("ldmatrix.sync.aligned.m8n8.x4.shared.b16 {%0,%1,%2,%3}, [%4];"
                 : "=r"(a[0]), "=r"(a[1]), "=r"(a[2]), "=r"(a[3]) : "r"(addr));
}

__device__ __forceinline__ void mma16816(float* c, const uint32_t* a,
                                         uint32_t b0, uint32_t b1) {
    asm volatile(
        "mma.sync.aligned.m16n8k16.row.col.f32.bf16.bf16.f32 "
        "{%0,%1,%2,%3}, {%4,%5,%6,%7}, {%8,%9}, {%0,%1,%2,%3};"
        : "+f"(c[0]), "+f"(c[1]), "+f"(c[2]), "+f"(c[3])
        : "r"(a[0]), "r"(a[1]), "r"(a[2]), "r"(a[3]), "r"(b0), "r"(b1));
}

__device__ __forceinline__ uint32_t pack_hi(float a, float b, float& ra, float& rb) {
    __nv_bfloat16 ha = __float2bfloat16(a), hb = __float2bfloat16(b);
    ra = a - __bfloat162float(ha);
    rb = b - __bfloat162float(hb);
    return ((uint32_t)__bfloat16_as_ushort(hb) << 16) | __bfloat16_as_ushort(ha);
}
__device__ __forceinline__ uint32_t pack_lo(float a, float b) {
    return ((uint32_t)__bfloat16_as_ushort(__float2bfloat16(b)) << 16) |
           __bfloat16_as_ushort(__float2bfloat16(a));
}

// ---------------- prep: weight transform + edge count + w2fc ----------------
__global__ void prep_kernel(const float* __restrict__ Wa, const float* __restrict__ Wb,
                            const float* __restrict__ Wc, const float* __restrict__ Wd,
                            const float* __restrict__ We, const float* __restrict__ Wf,
                            __nv_bfloat16* __restrict__ hi, __nv_bfloat16* __restrict__ lo,
                            const int* __restrict__ ei, int* __restrict__ cnt, int E,
                            const float* __restrict__ fcw, const float* __restrict__ b2f,
                            float* __restrict__ w2fc) {
    int t = blockIdx.x * blockDim.x + threadIdx.x;
    if (t < 6 * 16384) {
        int m = t >> 14;
        int i = t & 16383;
        int n = i >> 7, k = i & 127;
        const float* W = (m == 0) ? Wa : (m == 1) ? Wb : (m == 2) ? Wc
                       : (m == 3) ? Wd : (m == 4) ? We : Wf;
        float v = W[k * 128 + n];
        __nv_bfloat16 h = __float2bfloat16(v);
        hi[t] = h;
        lo[t] = __float2bfloat16(v - __bfloat162float(h));
    } else if (t < 6 * 16384 + 128) {
        int k = t - 6 * 16384;
        float s = 0.f;
        #pragma unroll 4
        for (int c = 0; c < 128; c++) s = fmaf(Wf[k * 128 + c], fcw[c], s);
        w2fc[k] = s;
    } else if (t == 6 * 16384 + 128) {
        float s = 0.f;
        for (int c = 0; c < 128; c++) s = fmaf(b2f[c], fcw[c], s);
        w2fc[128] = s;
    }
    if (t < E) atomicAdd(&cnt[ei[E + t]], 1);
}

// ---------------- CSR build ----------------
__global__ __launch_bounds__(1024) void scan_kernel(int* __restrict__ cursor,
                                                    int* __restrict__ rowptr, int N) {
    __shared__ int warpsums[32];
    __shared__ int s_carry;
    int tid = threadIdx.x, lane = tid & 31, wid = tid >> 5;
    if (tid == 0) s_carry = 0;
    __syncthreads();
    for (int base = 0; base < N; base += 1024) {
        int i = base + tid;
        int v = (i < N) ? cursor[i] : 0;
        int x = v;
        #pragma unroll
        for (int d = 1; d < 32; d <<= 1) {
            int y = __shfl_up_sync(0xffffffffu, x, d);
            if (lane >= d) x += y;
        }
        if (lane == 31) warpsums[wid] = x;
        __syncthreads();
        if (wid == 0) {
            int w = warpsums[lane];
            #pragma unroll
            for (int d = 1; d < 32; d <<= 1) {
                int y = __shfl_up_sync(0xffffffffu, w, d);
                if (lane >= d) w += y;
            }
            warpsums[lane] = w;
        }
        __syncthreads();
        int excl = x - v + ((wid > 0) ? warpsums[wid - 1] : 0) + s_carry;
        if (i < N) { rowptr[i] = excl; cursor[i] = excl; }
        __syncthreads();
        if (tid == 0) s_carry += warpsums[31];
        __syncthreads();
    }
    if (threadIdx.x == 0) rowptr[N] = s_carry;
}

__global__ void fill_kernel(const int* __restrict__ ei, int* __restrict__ cursor,
                            int* __restrict__ csrc, int E) {
    int t = blockIdx.x * blockDim.x + threadIdx.x;
    if (t < E) {
        int d = ei[E + t];
        int p = atomicAdd(&cursor[d], 1);
        csrc[p] = ei[t];
    }
}

// final output + restore invariants (cursor/gsum/gcnt = 0)
__global__ void final_kernel(float* __restrict__ gsum, float* __restrict__ gcnt,
                             const float* __restrict__ fcb,
                             float* __restrict__ out, int G,
                             int* __restrict__ cursor, int N) {
    int i = blockIdx.x * blockDim.x + threadIdx.x;
    if (i < G) {
        out[i] = gsum[i] / fmaxf(gcnt[i], 1.0f) + fcb[0];
        gsum[i] = 0.f;
        gcnt[i] = 0.f;
    }
    if (i < N) cursor[i] = 0;
}

// ---------------- fused aggregate + MLP (persistent, 512 thr) ----------------
#define SM_B1H 0
#define SM_B1L 34816
#define SM_B2H 69632
#define SM_B2L 104448
#define SM_AH  139264
#define SM_AL  174080
#define SM_SB1 208896
#define SM_SB2 209408
#define SM_SFW 209920
#define SM_SROW 210432
#define SM_TOTAL 210944

// split-bf16 GEMM: acc += Ah*Bh + Ah*Bl + Al*Bh  (per-warp 32x32 tile)
__device__ __forceinline__ void gemm_tile(
    const __nv_bfloat16* sAh, const __nv_bfloat16* sAl,
    const __nv_bfloat16* sBh, const __nv_bfloat16* sBl,
    float acc[2][4][4], int wr, int wc, int lane) {
    for (int prod = 0; prod < 3; prod++) {
        const __nv_bfloat16* Ap = (prod == 2) ? sAl : sAh;
        const __nv_bfloat16* Bp = (prod == 1) ? sBl : sBh;
        int arow = wr * 32 + (lane & 15);
        int acol = (lane >> 4) * 8;
        int bn = wc * 32 + (lane >> 2);
        int bk = (lane & 3) * 2;
        #pragma unroll 2
        for (int k0 = 0; k0 < 8; k0++) {
            uint32_t a0[4], a1[4];
            ldmA(a0, smem_u32(Ap + arow * LDT + k0 * 16 + acol));
            ldmA(a1, smem_u32(Ap + (arow + 16) * LDT + k0 * 16 + acol));
            #pragma unroll
            for (int nf = 0; nf < 4; nf++) {
                const __nv_bfloat16* bp = Bp + (bn + nf * 8) * LDT + k0 * 16 + bk;
                uint32_t b0 = *(const uint32_t*)bp;
                uint32_t b1 = *(const uint32_t*)(bp + 8);
                mma16816(acc[0][nf], a0, b0, b1);
                mma16816(acc[1][nf], a1, b0, b1);
            }
        }
    }
}

// accumulate 4 neighbor rows
#define GATHER4(v, J)                                                     \
    do {                                                                  \
        int t0 = __ldg(&csrc[(J)]);                                       \
        int t1 = __ldg(&csrc[(J) + 1]);                                   \
        int t2 = __ldg(&csrc[(J) + 2]);                                   \
        int t3 = __ldg(&csrc[(J) + 3]);                                   \
        float4 m0 = X4[(size_t)t0 * 32 + lane];                           \
        float4 m1 = X4[(size_t)t1 * 32 + lane];                           \
        float4 m2 = X4[(size_t)t2 * 32 + lane];                           \
        float4 m3 = X4[(size_t)t3 * 32 + lane];                           \
        v.x += m0.x + m1.x + m2.x + m3.x;                                 \
        v.y += m0.y + m1.y + m2.y + m3.y;                                 \
        v.z += m0.z + m1.z + m2.z + m3.z;                                 \
        v.w += m0.w + m1.w + m2.w + m3.w;                                 \
    } while (0)

__global__ __launch_bounds__(512, 1) void mlp_kernel(
    const float* __restrict__ X,
    const int* __restrict__ rowptr, const int* __restrict__ csrc,
    float* __restrict__ H,
    const __nv_bfloat16* __restrict__ W1h, const __nv_bfloat16* __restrict__ W1l,
    const __nv_bfloat16* __restrict__ W2h, const __nv_bfloat16* __restrict__ W2l,
    const float* __restrict__ b1, const float* __restrict__ b2,
    const float* __restrict__ epsp,
    int n, int ntiles, int relu_out, int pool,
    const int* __restrict__ batch, const float* __restrict__ w2fc,
    float* __restrict__ gsum, float* __restrict__ gcnt) {
    extern __shared__ char sm[];
    __nv_bfloat16* sB1h = (__nv_bfloat16*)(sm + SM_B1H);
    __nv_bfloat16* sB1l = (__nv_bfloat16*)(sm + SM_B1L);
    __nv_bfloat16* sB2h = (__nv_bfloat16*)(sm + SM_B2H);
    __nv_bfloat16* sB2l = (__nv_bfloat16*)(sm + SM_B2L);
    __nv_bfloat16* sAh  = (__nv_bfloat16*)(sm + SM_AH);
    __nv_bfloat16* sAl  = (__nv_bfloat16*)(sm + SM_AL);
    float* sb1  = (float*)(sm + SM_SB1);
    float* sb2  = (float*)(sm + SM_SB2);
    float* sfw  = (float*)(sm + SM_SFW);   // w2fc for pool layer
    float* srow = (float*)(sm + SM_SROW);

    int tid = threadIdx.x;
    int lane = tid & 31;
    int wid = tid >> 5;           // 0..15
    int wr = wid & 3;             // row group (32 rows)
    int wc = wid >> 2;            // col group (32 cols)

    if (tid < 128) {
        sb1[tid] = b1[tid];
        sb2[tid] = b2[tid];
        sfw[tid] = w2fc[tid];
    }

    // load weight planes once (persistent); pool layer skips B2
    {
        const uint4* p1h = (const uint4*)W1h;
        const uint4* p1l = (const uint4*)W1l;
        const uint4* p2h = (const uint4*)W2h;
        const uint4* p2l = (const uint4*)W2l;
        for (int i = tid; i < 2048; i += 512) {
            int r = i >> 4, c = (i & 15) * 8;
            int d = r * LDT + c;
            *(uint4*)&sB1h[d] = p1h[i];
            *(uint4*)&sB1l[d] = p1l[i];
            if (!pool) {
                *(uint4*)&sB2h[d] = p2h[i];
                *(uint4*)&sB2l[d] = p2l[i];
            }
        }
    }

    float s = 1.0f + __ldg(epsp);
    float bconst = __ldg(&w2fc[128]);
    const float4* X4 = (const float4*)X;

    for (int tile = blockIdx.x; tile < ntiles; tile += gridDim.x) {
        int row0 = tile * 128;
        if (tid < 128) srow[tid] = 0.f;

        // gather: A = (1+eps)*X[row] + sum_nbrs X[j]; 2 rows per warp iter
        for (int r2 = wid; r2 < 64; r2 += 16) {
            int rA = r2, rB = r2 + 64;
            int grA = row0 + rA, grB = row0 + rB;
            float4 va = make_float4(0.f, 0.f, 0.f, 0.f);
            float4 vb = make_float4(0.f, 0.f, 0.f, 0.f);
            int ja = 0, ea = 0, jb = 0, eb = 0;
            if (grA < n) {
                float4 xv = X4[(size_t)grA * 32 + lane];
                va.x = s * xv.x; va.y = s * xv.y; va.z = s * xv.z; va.w = s * xv.w;
                ja = __ldg(&rowptr[grA]); ea = __ldg(&rowptr[grA + 1]);
            }
            if (grB < n) {
                float4 xv = X4[(size_t)grB * 32 + lane];
                vb.x = s * xv.x; vb.y = s * xv.y; vb.z = s * xv.z; vb.w = s * xv.w;
                jb = __ldg(&rowptr[grB]); eb = __ldg(&rowptr[grB + 1]);
            }
            while (ja + 4 <= ea && jb + 4 <= eb) {
                GATHER4(va, ja);
                GATHER4(vb, jb);
                ja += 4; jb += 4;
            }
            for (; ja + 4 <= ea; ja += 4) GATHER4(va, ja);
            for (; ja < ea; ja++) {
                int t0 = __ldg(&csrc[ja]);
                float4 m0 = X4[(size_t)t0 * 32 + lane];
                va.x += m0.x; va.y += m0.y; va.z += m0.z; va.w += m0.w;
            }
            for (; jb + 4 <= eb; jb += 4) GATHER4(vb, jb);
            for (; jb < eb; jb++) {
                int t0 = __ldg(&csrc[jb]);
                float4 m0 = X4[(size_t)t0 * 32 + lane];
                vb.x += m0.x; vb.y += m0.y; vb.z += m0.z; vb.w += m0.w;
            }
            float q0, q1, q2, q3;
            uint2 hi2, lo2;
            hi2.x = pack_hi(va.x, va.y, q0, q1);
            hi2.y = pack_hi(va.z, va.w, q2, q3);
            lo2.x = pack_lo(q0, q1);
            lo2.y = pack_lo(q2, q3);
            int d = rA * LDT + lane * 4;
            *(uint2*)&sAh[d] = hi2;
            *(uint2*)&sAl[d] = lo2;
            hi2.x = pack_hi(vb.x, vb.y, q0, q1);
            hi2.y = pack_hi(vb.z, vb.w, q2, q3);
            lo2.x = pack_lo(q0, q1);
            lo2.y = pack_lo(q2, q3);
            d = rB * LDT + lane * 4;
            *(uint2*)&sAh[d] = hi2;
            *(uint2*)&sAl[d] = lo2;
        }
        __syncthreads();

        float acc[2][4][4];
        #pragma unroll
        for (int i = 0; i < 2; i++)
            #pragma unroll
            for (int j = 0; j < 4; j++)
                #pragma unroll
                for (int q = 0; q < 4; q++) acc[i][j][q] = 0.f;

        // GEMM1
        gemm_tile(sAh, sAl, sB1h, sB1l, acc, wr, wc, lane);

        if (pool) {
            // layer 2: h.fc = ReLU(acc+b1) @ w2fc (+ bconst per node)
            #pragma unroll
            for (int rf = 0; rf < 2; rf++) {
                int r = wr * 32 + rf * 16 + (lane >> 2);
                float d0 = 0.f, d1 = 0.f;
                #pragma unroll
                for (int nf = 0; nf < 4; nf++) {
                    int c = wc * 32 + nf * 8 + (lane & 3) * 2;
                    float* a = acc[rf][nf];
                    d0 = fmaf(fmaxf(a[0] + sb1[c], 0.f), sfw[c], d0);
                    d0 = fmaf(fmaxf(a[1] + sb1[c + 1], 0.f), sfw[c + 1], d0);
                    d1 = fmaf(fmaxf(a[2] + sb1[c], 0.f), sfw[c], d1);
                    d1 = fmaf(fmaxf(a[3] + sb1[c + 1], 0.f), sfw[c + 1], d1);
                }
                atomicAdd(&srow[r], d0);
                atomicAdd(&srow[r + 8], d1);
            }
            __syncthreads();
            if (tid < 128) {
                int gr = row0 + tid;
                if (gr < n) {
                    int g = batch[gr];
                    atomicAdd(&gsum[g], srow[tid] + bconst);
                    atomicAdd(&gcnt[g], 1.0f);
                }
            }
            __syncthreads();
            continue;
        }

        __syncthreads();  // all reads of sA done before overwrite

        // epilogue1: T = ReLU(acc + b1) -> split back into sA planes
        #pragma unroll
        for (int rf = 0; rf < 2; rf++) {
            int r = wr * 32 + rf * 16 + (lane >> 2);
            #pragma unroll
            for (int nf = 0; nf < 4; nf++) {
                int c = wc * 32 + nf * 8 + (lane & 3) * 2;
                float* a = acc[rf][nf];
                float v0 = fmaxf(a[0] + sb1[c], 0.f);
                float v1 = fmaxf(a[1] + sb1[c + 1], 0.f);
                float v2 = fmaxf(a[2] + sb1[c], 0.f);
                float v3 = fmaxf(a[3] + sb1[c + 1], 0.f);
                float q0, q1;
                uint32_t h = pack_hi(v0, v1, q0, q1);
                *(uint32_t*)&sAh[r * LDT + c] = h;
                *(uint32_t*)&sAl[r * LDT + c] = pack_lo(q0, q1);
                h = pack_hi(v2, v3, q0, q1);
                *(uint32_t*)&sAh[(r + 8) * LDT + c] = h;
                *(uint32_t*)&sAl[(r + 8) * LDT + c] = pack_lo(q0, q1);
            }
        }
        __syncthreads();

        #pragma unroll
        for (int i = 0; i < 2; i++)
            #pragma unroll
            for (int j = 0; j < 4; j++)
                #pragma unroll
                for (int q = 0; q < 4; q++) acc[i][j][q] = 0.f;

        // GEMM2
        gemm_tile(sAh, sAl, sB2h, sB2l, acc, wr, wc, lane);

        // epilogue2: out = acc + b2 (+ReLU) -> H
        #pragma unroll
        for (int rf = 0; rf < 2; rf++) {
            int r = wr * 32 + rf * 16 + (lane >> 2);
            int gr0 = row0 + r, gr1 = gr0 + 8;
            #pragma unroll
            for (int nf = 0; nf < 4; nf++) {
                int c = wc * 32 + nf * 8 + (lane & 3) * 2;
                float* a = acc[rf][nf];
                float v0 = a[0] + sb2[c], v1 = a[1] + sb2[c + 1];
                float v2 = a[2] + sb2[c], v3 = a[3] + sb2[c + 1];
                if (relu_out) {
                    v0 = fmaxf(v0, 0.f); v1 = fmaxf(v1, 0.f);
                    v2 = fmaxf(v2, 0.f); v3 = fmaxf(v3, 0.f);
                }
                if (gr0 < n) *(float2*)&H[(size_t)gr0 * 128 + c] = make_float2(v0, v1);
                if (gr1 < n) *(float2*)&H[(size_t)gr1 * 128 + c] = make_float2(v2, v3);
            }
        }
        __syncthreads();  // protect sA before next tile's gather
    }
}

// ---------------- host launcher ----------------
extern "C" void kernel_launch(void* const* d_in, const int* in_sizes, int n_in,
                              void* d_out, int out_size) {
    const float* x     = (const float*)d_in[0];
    const int*   ei    = (const int*)d_in[1];
    const int*   batch = (const int*)d_in[2];
    const float* W1s[3] = {(const float*)d_in[3],  (const float*)d_in[8],  (const float*)d_in[13]};
    const float* b1s[3] = {(const float*)d_in[4],  (const float*)d_in[9],  (const float*)d_in[14]};
    const float* W2s[3] = {(const float*)d_in[5],  (const float*)d_in[10], (const float*)d_in[15]};
    const float* b2s[3] = {(const float*)d_in[6],  (const float*)d_in[11], (const float*)d_in[16]};
    const float* epss[3]= {(const float*)d_in[7],  (const float*)d_in[12], (const float*)d_in[17]};
    const float* fcw   = (const float*)d_in[18];
    const float* fcb   = (const float*)d_in[19];

    int N = in_sizes[2];
    int E = in_sizes[1] / 2;
    int G = out_size;

    float *bufA, *bufB, *gsum, *gcnt, *w2fc;
    int *rowptr, *cursor, *csrc;
    __nv_bfloat16 *wthi, *wtlo;
    cudaGetSymbolAddress((void**)&bufA, g_bufA);
    cudaGetSymbolAddress((void**)&bufB, g_bufB);
    cudaGetSymbolAddress((void**)&gsum, g_gsum);
    cudaGetSymbolAddress((void**)&gcnt, g_gcnt);
    cudaGetSymbolAddress((void**)&rowptr, g_rowptr);
    cudaGetSymbolAddress((void**)&cursor, g_cursor);
    cudaGetSymbolAddress((void**)&csrc, g_csrc);
    cudaGetSymbolAddress((void**)&w2fc, g_w2fc);
    cudaGetSymbolAddress((void**)&wthi, g_wthi);
    cudaGetSymbolAddress((void**)&wtlo, g_wtlo);

    cudaFuncSetAttribute(mlp_kernel, cudaFuncAttributeMaxDynamicSharedMemorySize, SM_TOTAL);

    int prep_threads = (E > 6 * 16384 + 129) ? E : (6 * 16384 + 129);
    // 1: weight transform + edge count + w2fc (cursor==0 at entry)
    prep_kernel<<<(prep_threads + 255) / 256, 256>>>(
        W1s[0], W2s[0], W1s[1], W2s[1], W1s[2], W2s[2],
        wthi, wtlo, ei, cursor, E, fcw, b2s[2], w2fc);
    // 2-3: CSR scan + fill
    scan_kernel<<<1, 1024>>>(cursor, rowptr, N);
    fill_kernel<<<(E + 255) / 256, 256>>>(ei, cursor, csrc, E);

    // 4-6: ping-pong layers; layer2 pools (no GEMM2)
    const float* ins[3]  = {x, bufA, bufB};
    float*       outs[3] = {bufA, bufB, bufA /* unused (pool) */};
    int ntiles = (N + 127) / 128;
    for (int l = 0; l < 3; l++) {
        mlp_kernel<<<148, 512, SM_TOTAL>>>(
            ins[l], rowptr, csrc, outs[l],
            wthi + (2 * l) * 16384, wtlo + (2 * l) * 16384,
            wthi + (2 * l + 1) * 16384, wtlo + (2 * l + 1) * 16384,
            b1s[l], b2s[l], epss[l],
            N, ntiles, (l < 2) ? 1 : 0, (l == 2) ? 1 : 0,
            batch, w2fc, gsum, gcnt);
    }
    // 7: output + restore invariants
    final_kernel<<<(N + 255) / 256, 256>>>(gsum, gcnt, fcb, (float*)d_out, G, cursor, N);
}

// round 9
// speedup vs baseline: 2.5078x; 1.0700x over previous
#include <cuda_runtime.h>
#include <cuda_bf16.h>
#include <cstdint>

// ---------------------------------------------------------------------------
// GINRegressor on GB300: CSR gather fused into split-bf16 tensor MLP.
// 1024 threads/CTA (32 warps) for latency hiding; persistent CTAs; ping-pong
// buffers; layer2 second GEMM folded to GEMV (w2fc = W2_2 @ fc_w).
// Launch order: prep(1), scan(2), fill(3), mlp0(4), mlp1(5), mlp2(6), final(7).
// Invariant: cursor/gsum/gcnt zero at entry (final_kernel restores).
// ---------------------------------------------------------------------------

#define NMAX 50000
#define EMAX 800000
#define GMAX 500
#define LDT 136  // padded smem tile stride (bf16 elems) -> conflict-free

__device__ float g_bufA[NMAX * 128];
__device__ float g_bufB[NMAX * 128];
__device__ float g_gsum[GMAX];
__device__ float g_gcnt[GMAX];
__device__ int   g_rowptr[NMAX + 1];
__device__ int   g_cursor[NMAX];          // zero at entry (invariant)
__device__ int   g_csrc[EMAX];
__device__ float g_w2fc[129];             // [0..127]=W2_2@fc, [128]=b2_2.fc
__device__ __align__(16) __nv_bfloat16 g_wthi[6 * 16384];  // W^T hi planes
__device__ __align__(16) __nv_bfloat16 g_wtlo[6 * 16384];  // W^T lo planes

// ---------------- helpers ----------------
__device__ __forceinline__ uint32_t smem_u32(const void* p) {
    uint32_t a;
    asm("{ .reg .u64 t; cvta.to.shared.u64 t, %1; cvt.u32.u64 %0, t; }"
        : "=r"(a) : "l"(p));
    return a;
}

__device__ __forceinline__ void ldmA(uint32_t* a, uint32_t addr) {
    asm volatile("ldmatrix.sync.aligned.m8n8.x4.shared.b16 {%0,%1,%2,%3}, [%4];"
                 : "=r"(a[0]), "=r"(a[1]), "=r"(a[2]), "=r"(a[3]) : "r"(addr));
}

__device__ __forceinline__ void mma16816(float* c, const uint32_t* a,
                                         uint32_t b0, uint32_t b1) {
    asm volatile(
        "mma.sync.aligned.m16n8k16.row.col.f32.bf16.bf16.f32 "
        "{%0,%1,%2,%3}, {%4,%5,%6,%7}, {%8,%9}, {%0,%1,%2,%3};"
        : "+f"(c[0]), "+f"(c[1]), "+f"(c[2]), "+f"(c[3])
        : "r"(a[0]), "r"(a[1]), "r"(a[2]), "r"(a[3]), "r"(b0), "r"(b1));
}

__device__ __forceinline__ uint32_t pack_hi(float a, float b, float& ra, float& rb) {
    __nv_bfloat16 ha = __float2bfloat16(a), hb = __float2bfloat16(b);
    ra = a - __bfloat162float(ha);
    rb = b - __bfloat162float(hb);
    return ((uint32_t)__bfloat16_as_ushort(hb) << 16) | __bfloat16_as_ushort(ha);
}
__device__ __forceinline__ uint32_t pack_lo(float a, float b) {
    return ((uint32_t)__bfloat16_as_ushort(__float2bfloat16(b)) << 16) |
           __bfloat16_as_ushort(__float2bfloat16(a));
}

// ---------------- prep: weight transform + edge count + w2fc ----------------
__global__ void prep_kernel(const float* __restrict__ Wa, const float* __restrict__ Wb,
                            const float* __restrict__ Wc, const float* __restrict__ Wd,
                            const float* __restrict__ We, const float* __restrict__ Wf,
                            __nv_bfloat16* __restrict__ hi, __nv_bfloat16* __restrict__ lo,
                            const int* __restrict__ ei, int* __restrict__ cnt, int E,
                            const float* __restrict__ fcw, const float* __restrict__ b2f,
                            float* __restrict__ w2fc) {
    int t = blockIdx.x * blockDim.x + threadIdx.x;
    if (t < 6 * 16384) {
        int m = t >> 14;
        int i = t & 16383;
        int n = i >> 7, k = i & 127;
        const float* W = (m == 0) ? Wa : (m == 1) ? Wb : (m == 2) ? Wc
                       : (m == 3) ? Wd : (m == 4) ? We : Wf;
        float v = W[k * 128 + n];
        __nv_bfloat16 h = __float2bfloat16(v);
        hi[t] = h;
        lo[t] = __float2bfloat16(v - __bfloat162float(h));
    } else if (t < 6 * 16384 + 128) {
        int k = t - 6 * 16384;
        float s = 0.f;
        #pragma unroll 4
        for (int c = 0; c < 128; c++) s = fmaf(Wf[k * 128 + c], fcw[c], s);
        w2fc[k] = s;
    } else if (t == 6 * 16384 + 128) {
        float s = 0.f;
        for (int c = 0; c < 128; c++) s = fmaf(b2f[c], fcw[c], s);
        w2fc[128] = s;
    }
    if (t < E) atomicAdd(&cnt[ei[E + t]], 1);
}

// ---------------- CSR build ----------------
__global__ __launch_bounds__(1024) void scan_kernel(int* __restrict__ cursor,
                                                    int* __restrict__ rowptr, int N) {
    __shared__ int warpsums[32];
    __shared__ int s_carry;
    int tid = threadIdx.x, lane = tid & 31, wid = tid >> 5;
    if (tid == 0) s_carry = 0;
    __syncthreads();
    for (int base = 0; base < N; base += 1024) {
        int i = base + tid;
        int v = (i < N) ? cursor[i] : 0;
        int x = v;
        #pragma unroll
        for (int d = 1; d < 32; d <<= 1) {
            int y = __shfl_up_sync(0xffffffffu, x, d);
            if (lane >= d) x += y;
        }
        if (lane == 31) warpsums[wid] = x;
        __syncthreads();
        if (wid == 0) {
            int w = warpsums[lane];
            #pragma unroll
            for (int d = 1; d < 32; d <<= 1) {
                int y = __shfl_up_sync(0xffffffffu, w, d);
                if (lane >= d) w += y;
            }
            warpsums[lane] = w;
        }
        __syncthreads();
        int excl = x - v + ((wid > 0) ? warpsums[wid - 1] : 0) + s_carry;
        if (i < N) { rowptr[i] = excl; cursor[i] = excl; }
        __syncthreads();
        if (tid == 0) s_carry += warpsums[31];
        __syncthreads();
    }
    if (threadIdx.x == 0) rowptr[N] = s_carry;
}

__global__ void fill_kernel(const int* __restrict__ ei, int* __restrict__ cursor,
                            int* __restrict__ csrc, int E) {
    int t = blockIdx.x * blockDim.x + threadIdx.x;
    if (t < E) {
        int d = ei[E + t];
        int p = atomicAdd(&cursor[d], 1);
        csrc[p] = ei[t];
    }
}

// final output + restore invariants (cursor/gsum/gcnt = 0)
__global__ void final_kernel(float* __restrict__ gsum, float* __restrict__ gcnt,
                             const float* __restrict__ fcb,
                             float* __restrict__ out, int G,
                             int* __restrict__ cursor, int N) {
    int i = blockIdx.x * blockDim.x + threadIdx.x;
    if (i < G) {
        out[i] = gsum[i] / fmaxf(gcnt[i], 1.0f) + fcb[0];
        gsum[i] = 0.f;
        gcnt[i] = 0.f;
    }
    if (i < N) cursor[i] = 0;
}

// ---------------- fused aggregate + MLP (persistent, 1024 thr) ----------------
#define SM_B1H 0
#define SM_B1L 34816
#define SM_B2H 69632
#define SM_B2L 104448
#define SM_AH  139264
#define SM_AL  174080
#define SM_SB1 208896
#define SM_SB2 209408
#define SM_SFW 209920
#define SM_SROW 210432
#define SM_TOTAL 210944

// split-bf16 GEMM: acc += Ah*Bh + Ah*Bl + Al*Bh  (per-warp 16x32 tile)
__device__ __forceinline__ void gemm_tile(
    const __nv_bfloat16* sAh, const __nv_bfloat16* sAl,
    const __nv_bfloat16* sBh, const __nv_bfloat16* sBl,
    float acc[4][4], int wr, int wc, int lane) {
    for (int prod = 0; prod < 3; prod++) {
        const __nv_bfloat16* Ap = (prod == 2) ? sAl : sAh;
        const __nv_bfloat16* Bp = (prod == 1) ? sBl : sBh;
        int arow = wr * 16 + (lane & 15);
        int acol = (lane >> 4) * 8;
        int bn = wc * 32 + (lane >> 2);
        int bk = (lane & 3) * 2;
        #pragma unroll 2
        for (int k0 = 0; k0 < 8; k0++) {
            uint32_t a0[4];
            ldmA(a0, smem_u32(Ap + arow * LDT + k0 * 16 + acol));
            #pragma unroll
            for (int nf = 0; nf < 4; nf++) {
                const __nv_bfloat16* bp = Bp + (bn + nf * 8) * LDT + k0 * 16 + bk;
                uint32_t b0 = *(const uint32_t*)bp;
                uint32_t b1 = *(const uint32_t*)(bp + 8);
                mma16816(acc[nf], a0, b0, b1);
            }
        }
    }
}

// accumulate 4 neighbor rows
#define GATHER4(v, J)                                                     \
    do {                                                                  \
        int t0 = __ldg(&csrc[(J)]);                                       \
        int t1 = __ldg(&csrc[(J) + 1]);                                   \
        int t2 = __ldg(&csrc[(J) + 2]);                                   \
        int t3 = __ldg(&csrc[(J) + 3]);                                   \
        float4 m0 = X4[(size_t)t0 * 32 + lane];                           \
        float4 m1 = X4[(size_t)t1 * 32 + lane];                           \
        float4 m2 = X4[(size_t)t2 * 32 + lane];                           \
        float4 m3 = X4[(size_t)t3 * 32 + lane];                           \
        v.x += m0.x + m1.x + m2.x + m3.x;                                 \
        v.y += m0.y + m1.y + m2.y + m3.y;                                 \
        v.z += m0.z + m1.z + m2.z + m3.z;                                 \
        v.w += m0.w + m1.w + m2.w + m3.w;                                 \
    } while (0)

__global__ __launch_bounds__(1024, 1) void mlp_kernel(
    const float* __restrict__ X,
    const int* __restrict__ rowptr, const int* __restrict__ csrc,
    float* __restrict__ H,
    const __nv_bfloat16* __restrict__ W1h, const __nv_bfloat16* __restrict__ W1l,
    const __nv_bfloat16* __restrict__ W2h, const __nv_bfloat16* __restrict__ W2l,
    const float* __restrict__ b1, const float* __restrict__ b2,
    const float* __restrict__ epsp,
    int n, int ntiles, int relu_out, int pool,
    const int* __restrict__ batch, const float* __restrict__ w2fc,
    float* __restrict__ gsum, float* __restrict__ gcnt) {
    extern __shared__ char sm[];
    __nv_bfloat16* sB1h = (__nv_bfloat16*)(sm + SM_B1H);
    __nv_bfloat16* sB1l = (__nv_bfloat16*)(sm + SM_B1L);
    __nv_bfloat16* sB2h = (__nv_bfloat16*)(sm + SM_B2H);
    __nv_bfloat16* sB2l = (__nv_bfloat16*)(sm + SM_B2L);
    __nv_bfloat16* sAh  = (__nv_bfloat16*)(sm + SM_AH);
    __nv_bfloat16* sAl  = (__nv_bfloat16*)(sm + SM_AL);
    float* sb1  = (float*)(sm + SM_SB1);
    float* sb2  = (float*)(sm + SM_SB2);
    float* sfw  = (float*)(sm + SM_SFW);   // w2fc for pool layer
    float* srow = (float*)(sm + SM_SROW);

    int tid = threadIdx.x;
    int lane = tid & 31;
    int wid = tid >> 5;           // 0..31
    int wr = wid & 7;             // row group (16 rows)
    int wc = wid >> 3;            // col group (32 cols)

    if (tid < 128) {
        sb1[tid] = b1[tid];
        sb2[tid] = b2[tid];
        sfw[tid] = w2fc[tid];
    }

    // load weight planes once (persistent); pool layer skips B2
    {
        const uint4* p1h = (const uint4*)W1h;
        const uint4* p1l = (const uint4*)W1l;
        const uint4* p2h = (const uint4*)W2h;
        const uint4* p2l = (const uint4*)W2l;
        for (int i = tid; i < 2048; i += 1024) {
            int r = i >> 4, c = (i & 15) * 8;
            int d = r * LDT + c;
            *(uint4*)&sB1h[d] = p1h[i];
            *(uint4*)&sB1l[d] = p1l[i];
            if (!pool) {
                *(uint4*)&sB2h[d] = p2h[i];
                *(uint4*)&sB2l[d] = p2l[i];
            }
        }
    }

    float s = 1.0f + __ldg(epsp);
    float bconst = __ldg(&w2fc[128]);
    const float4* X4 = (const float4*)X;

    for (int tile = blockIdx.x; tile < ntiles; tile += gridDim.x) {
        int row0 = tile * 128;
        if (tid < 128) srow[tid] = 0.f;

        // gather: A = (1+eps)*X[row] + sum_nbrs X[j]; 2 rows per warp iter
        for (int r2 = wid; r2 < 64; r2 += 32) {
            int rA = r2, rB = r2 + 64;
            int grA = row0 + rA, grB = row0 + rB;
            float4 va = make_float4(0.f, 0.f, 0.f, 0.f);
            float4 vb = make_float4(0.f, 0.f, 0.f, 0.f);
            int ja = 0, ea = 0, jb = 0, eb = 0;
            if (grA < n) {
                float4 xv = X4[(size_t)grA * 32 + lane];
                va.x = s * xv.x; va.y = s * xv.y; va.z = s * xv.z; va.w = s * xv.w;
                ja = __ldg(&rowptr[grA]); ea = __ldg(&rowptr[grA + 1]);
            }
            if (grB < n) {
                float4 xv = X4[(size_t)grB * 32 + lane];
                vb.x = s * xv.x; vb.y = s * xv.y; vb.z = s * xv.z; vb.w = s * xv.w;
                jb = __ldg(&rowptr[grB]); eb = __ldg(&rowptr[grB + 1]);
            }
            while (ja + 4 <= ea && jb + 4 <= eb) {
                GATHER4(va, ja);
                GATHER4(vb, jb);
                ja += 4; jb += 4;
            }
            for (; ja + 4 <= ea; ja += 4) GATHER4(va, ja);
            for (; ja < ea; ja++) {
                int t0 = __ldg(&csrc[ja]);
                float4 m0 = X4[(size_t)t0 * 32 + lane];
                va.x += m0.x; va.y += m0.y; va.z += m0.z; va.w += m0.w;
            }
            for (; jb + 4 <= eb; jb += 4) GATHER4(vb, jb);
            for (; jb < eb; jb++) {
                int t0 = __ldg(&csrc[jb]);
                float4 m0 = X4[(size_t)t0 * 32 + lane];
                vb.x += m0.x; vb.y += m0.y; vb.z += m0.z; vb.w += m0.w;
            }
            float q0, q1, q2, q3;
            uint2 hi2, lo2;
            hi2.x = pack_hi(va.x, va.y, q0, q1);
            hi2.y = pack_hi(va.z, va.w, q2, q3);
            lo2.x = pack_lo(q0, q1);
            lo2.y = pack_lo(q2, q3);
            int d = rA * LDT + lane * 4;
            *(uint2*)&sAh[d] = hi2;
            *(uint2*)&sAl[d] = lo2;
            hi2.x = pack_hi(vb.x, vb.y, q0, q1);
            hi2.y = pack_hi(vb.z, vb.w, q2, q3);
            lo2.x = pack_lo(q0, q1);
            lo2.y = pack_lo(q2, q3);
            d = rB * LDT + lane * 4;
            *(uint2*)&sAh[d] = hi2;
            *(uint2*)&sAl[d] = lo2;
        }
        __syncthreads();

        float acc[4][4];
        #pragma unroll
        for (int j = 0; j < 4; j++)
            #pragma unroll
            for (int q = 0; q < 4; q++) acc[j][q] = 0.f;

        // GEMM1
        gemm_tile(sAh, sAl, sB1h, sB1l, acc, wr, wc, lane);

        if (pool) {
            // layer 2: h.fc = ReLU(acc+b1) @ w2fc (+ bconst per node)
            int r = wr * 16 + (lane >> 2);
            float d0 = 0.f, d1 = 0.f;
            #pragma unroll
            for (int nf = 0; nf < 4; nf++) {
                int c = wc * 32 + nf * 8 + (lane & 3) * 2;
                float* a = acc[nf];
                d0 = fmaf(fmaxf(a[0] + sb1[c], 0.f), sfw[c], d0);
                d0 = fmaf(fmaxf(a[1] + sb1[c + 1], 0.f), sfw[c + 1], d0);
                d1 = fmaf(fmaxf(a[2] + sb1[c], 0.f), sfw[c], d1);
                d1 = fmaf(fmaxf(a[3] + sb1[c + 1], 0.f), sfw[c + 1], d1);
            }
            atomicAdd(&srow[r], d0);
            atomicAdd(&srow[r + 8], d1);
            __syncthreads();
            if (tid < 128) {
                int gr = row0 + tid;
                if (gr < n) {
                    int g = batch[gr];
                    atomicAdd(&gsum[g], srow[tid] + bconst);
                    atomicAdd(&gcnt[g], 1.0f);
                }
            }
            __syncthreads();
            continue;
        }

        __syncthreads();  // all reads of sA done before overwrite

        // epilogue1: T = ReLU(acc + b1) -> split back into sA planes
        {
            int r = wr * 16 + (lane >> 2);
            #pragma unroll
            for (int nf = 0; nf < 4; nf++) {
                int c = wc * 32 + nf * 8 + (lane & 3) * 2;
                float* a = acc[nf];
                float v0 = fmaxf(a[0] + sb1[c], 0.f);
                float v1 = fmaxf(a[1] + sb1[c + 1], 0.f);
                float v2 = fmaxf(a[2] + sb1[c], 0.f);
                float v3 = fmaxf(a[3] + sb1[c + 1], 0.f);
                float q0, q1;
                uint32_t h = pack_hi(v0, v1, q0, q1);
                *(uint32_t*)&sAh[r * LDT + c] = h;
                *(uint32_t*)&sAl[r * LDT + c] = pack_lo(q0, q1);
                h = pack_hi(v2, v3, q0, q1);
                *(uint32_t*)&sAh[(r + 8) * LDT + c] = h;
                *(uint32_t*)&sAl[(r + 8) * LDT + c] = pack_lo(q0, q1);
            }
        }
        __syncthreads();

        #pragma unroll
        for (int j = 0; j < 4; j++)
            #pragma unroll
            for (int q = 0; q < 4; q++) acc[j][q] = 0.f;

        // GEMM2
        gemm_tile(sAh, sAl, sB2h, sB2l, acc, wr, wc, lane);

        // epilogue2: out = acc + b2 (+ReLU) -> H
        {
            int r = wr * 16 + (lane >> 2);
            int gr0 = row0 + r, gr1 = gr0 + 8;
            #pragma unroll
            for (int nf = 0; nf < 4; nf++) {
                int c = wc * 32 + nf * 8 + (lane & 3) * 2;
                float* a = acc[nf];
                float v0 = a[0] + sb2[c], v1 = a[1] + sb2[c + 1];
                float v2 = a[2] + sb2[c], v3 = a[3] + sb2[c + 1];
                if (relu_out) {
                    v0 = fmaxf(v0, 0.f); v1 = fmaxf(v1, 0.f);
                    v2 = fmaxf(v2, 0.f); v3 = fmaxf(v3, 0.f);
                }
                if (gr0 < n) *(float2*)&H[(size_t)gr0 * 128 + c] = make_float2(v0, v1);
                if (gr1 < n) *(float2*)&H[(size_t)gr1 * 128 + c] = make_float2(v2, v3);
            }
        }
        __syncthreads();  // protect sA before next tile's gather
    }
}

// ---------------- host launcher ----------------
extern "C" void kernel_launch(void* const* d_in, const int* in_sizes, int n_in,
                              void* d_out, int out_size) {
    const float* x     = (const float*)d_in[0];
    const int*   ei    = (const int*)d_in[1];
    const int*   batch = (const int*)d_in[2];
    const float* W1s[3] = {(const float*)d_in[3],  (const float*)d_in[8],  (const float*)d_in[13]};
    const float* b1s[3] = {(const float*)d_in[4],  (const float*)d_in[9],  (const float*)d_in[14]};
    const float* W2s[3] = {(const float*)d_in[5],  (const float*)d_in[10], (const float*)d_in[15]};
    const float* b2s[3] = {(const float*)d_in[6],  (const float*)d_in[11], (const float*)d_in[16]};
    const float* epss[3]= {(const float*)d_in[7],  (const float*)d_in[12], (const float*)d_in[17]};
    const float* fcw   = (const float*)d_in[18];
    const float* fcb   = (const float*)d_in[19];

    int N = in_sizes[2];
    int E = in_sizes[1] / 2;
    int G = out_size;

    float *bufA, *bufB, *gsum, *gcnt, *w2fc;
    int *rowptr, *cursor, *csrc;
    __nv_bfloat16 *wthi, *wtlo;
    cudaGetSymbolAddress((void**)&bufA, g_bufA);
    cudaGetSymbolAddress((void**)&bufB, g_bufB);
    cudaGetSymbolAddress((void**)&gsum, g_gsum);
    cudaGetSymbolAddress((void**)&gcnt, g_gcnt);
    cudaGetSymbolAddress((void**)&rowptr, g_rowptr);
    cudaGetSymbolAddress((void**)&cursor, g_cursor);
    cudaGetSymbolAddress((void**)&csrc, g_csrc);
    cudaGetSymbolAddress((void**)&w2fc, g_w2fc);
    cudaGetSymbolAddress((void**)&wthi, g_wthi);
    cudaGetSymbolAddress((void**)&wtlo, g_wtlo);

    cudaFuncSetAttribute(mlp_kernel, cudaFuncAttributeMaxDynamicSharedMemorySize, SM_TOTAL);

    int prep_threads = (E > 6 * 16384 + 129) ? E : (6 * 16384 + 129);
    // 1: weight transform + edge count + w2fc (cursor==0 at entry)
    prep_kernel<<<(prep_threads + 255) / 256, 256>>>(
        W1s[0], W2s[0], W1s[1], W2s[1], W1s[2], W2s[2],
        wthi, wtlo, ei, cursor, E, fcw, b2s[2], w2fc);
    // 2-3: CSR scan + fill
    scan_kernel<<<1, 1024>>>(cursor, rowptr, N);
    fill_kernel<<<(E + 255) / 256, 256>>>(ei, cursor, csrc, E);

    // 4-6: ping-pong layers; layer2 pools (no GEMM2)
    const float* ins[3]  = {x, bufA, bufB};
    float*       outs[3] = {bufA, bufB, bufA /* unused (pool) */};
    int ntiles = (N + 127) / 128;
    for (int l = 0; l < 3; l++) {
        mlp_kernel<<<148, 1024, SM_TOTAL>>>(
            ins[l], rowptr, csrc, outs[l],
            wthi + (2 * l) * 16384, wtlo + (2 * l) * 16384,
            wthi + (2 * l + 1) * 16384, wtlo + (2 * l + 1) * 16384,
            b1s[l], b2s[l], epss[l],
            N, ntiles, (l < 2) ? 1 : 0, (l == 2) ? 1 : 0,
            batch, w2fc, gsum, gcnt);
    }
    // 7: output + restore invariants
    final_kernel<<<(N + 255) / 256, 256>>>(gsum, gcnt, fcb, (float*)d_out, G, cursor, N);
}

// round 10
// speedup vs baseline: 2.6677x; 1.0638x over previous
#include <cuda_runtime.h>
#include <cuda_bf16.h>
#include <cstdint>

// ---------------------------------------------------------------------------
// GINRegressor on GB300: CSR gather fused into split-bf16 tensor MLP.
// 1024 threads/CTA; persistent CTAs; ping-pong buffers; layer2 GEMM2 folded
// to GEMV. GEMM uses ldmatrix.x4 for BOTH operands (48 shared ops / 96 MMAs).
// Launch order: prep(1), scan(2), fill(3), mlp0(4), mlp1(5), mlp2(6), final(7).
// Invariant: cursor/gsum/gcnt zero at entry (final_kernel restores).
// ---------------------------------------------------------------------------

#define NMAX 50000
#define EMAX 800000
#define GMAX 500
#define LDT 136  // padded smem tile stride (bf16 elems) -> conflict-free

__device__ float g_bufA[NMAX * 128];
__device__ float g_bufB[NMAX * 128];
__device__ float g_gsum[GMAX];
__device__ float g_gcnt[GMAX];
__device__ int   g_rowptr[NMAX + 1];
__device__ int   g_cursor[NMAX];          // zero at entry (invariant)
__device__ int   g_csrc[EMAX];
__device__ float g_w2fc[129];             // [0..127]=W2_2@fc, [128]=b2_2.fc
__device__ __align__(16) __nv_bfloat16 g_wthi[6 * 16384];  // W^T hi planes
__device__ __align__(16) __nv_bfloat16 g_wtlo[6 * 16384];  // W^T lo planes

// ---------------- helpers ----------------
__device__ __forceinline__ uint32_t smem_u32(const void* p) {
    uint32_t a;
    asm("{ .reg .u64 t; cvta.to.shared.u64 t, %1; cvt.u32.u64 %0, t; }"
        : "=r"(a) : "l"(p));
    return a;
}

__device__ __forceinline__ void ldm4(uint32_t* a, uint32_t addr) {
    asm volatile("ldmatrix.sync.aligned.m8n8.x4.shared.b16 {%0,%1,%2,%3}, [%4];"
                 : "=r"(a[0]), "=r"(a[1]), "=r"(a[2]), "=r"(a[3]) : "r"(addr));
}

__device__ __forceinline__ void mma16816(float* c, const uint32_t* a,
                                         uint32_t b0, uint32_t b1) {
    asm volatile(
        "mma.sync.aligned.m16n8k16.row.col.f32.bf16.bf16.f32 "
        "{%0,%1,%2,%3}, {%4,%5,%6,%7}, {%8,%9}, {%0,%1,%2,%3};"
        : "+f"(c[0]), "+f"(c[1]), "+f"(c[2]), "+f"(c[3])
        : "r"(a[0]), "r"(a[1]), "r"(a[2]), "r"(a[3]), "r"(b0), "r"(b1));
}

__device__ __forceinline__ uint32_t pack_hi(float a, float b, float& ra, float& rb) {
    __nv_bfloat16 ha = __float2bfloat16(a), hb = __float2bfloat16(b);
    ra = a - __bfloat162float(ha);
    rb = b - __bfloat162float(hb);
    return ((uint32_t)__bfloat16_as_ushort(hb) << 16) | __bfloat16_as_ushort(ha);
}
__device__ __forceinline__ uint32_t pack_lo(float a, float b) {
    return ((uint32_t)__bfloat16_as_ushort(__float2bfloat16(b)) << 16) |
           __bfloat16_as_ushort(__float2bfloat16(a));
}

// ---------------- prep: weight transform + edge count + w2fc ----------------
__global__ void prep_kernel(const float* __restrict__ Wa, const float* __restrict__ Wb,
                            const float* __restrict__ Wc, const float* __restrict__ Wd,
                            const float* __restrict__ We, const float* __restrict__ Wf,
                            __nv_bfloat16* __restrict__ hi, __nv_bfloat16* __restrict__ lo,
                            const int* __restrict__ ei, int* __restrict__ cnt, int E,
                            const float* __restrict__ fcw, const float* __restrict__ b2f,
                            float* __restrict__ w2fc) {
    int t = blockIdx.x * blockDim.x + threadIdx.x;
    if (t < 6 * 16384) {
        int m = t >> 14;
        int i = t & 16383;
        int n = i >> 7, k = i & 127;
        const float* W = (m == 0) ? Wa : (m == 1) ? Wb : (m == 2) ? Wc
                       : (m == 3) ? Wd : (m == 4) ? We : Wf;
        float v = W[k * 128 + n];
        __nv_bfloat16 h = __float2bfloat16(v);
        hi[t] = h;
        lo[t] = __float2bfloat16(v - __bfloat162float(h));
    } else if (t < 6 * 16384 + 128) {
        int k = t - 6 * 16384;
        float s = 0.f;
        #pragma unroll 4
        for (int c = 0; c < 128; c++) s = fmaf(Wf[k * 128 + c], fcw[c], s);
        w2fc[k] = s;
    } else if (t == 6 * 16384 + 128) {
        float s = 0.f;
        for (int c = 0; c < 128; c++) s = fmaf(b2f[c], fcw[c], s);
        w2fc[128] = s;
    }
    if (t < E) atomicAdd(&cnt[ei[E + t]], 1);
}

// ---------------- CSR build ----------------
__global__ __launch_bounds__(1024) void scan_kernel(int* __restrict__ cursor,
                                                    int* __restrict__ rowptr, int N) {
    __shared__ int warpsums[32];
    __shared__ int s_carry;
    int tid = threadIdx.x, lane = tid & 31, wid = tid >> 5;
    if (tid == 0) s_carry = 0;
    __syncthreads();
    for (int base = 0; base < N; base += 1024) {
        int i = base + tid;
        int v = (i < N) ? cursor[i] : 0;
        int x = v;
        #pragma unroll
        for (int d = 1; d < 32; d <<= 1) {
            int y = __shfl_up_sync(0xffffffffu, x, d);
            if (lane >= d) x += y;
        }
        if (lane == 31) warpsums[wid] = x;
        __syncthreads();
        if (wid == 0) {
            int w = warpsums[lane];
            #pragma unroll
            for (int d = 1; d < 32; d <<= 1) {
                int y = __shfl_up_sync(0xffffffffu, w, d);
                if (lane >= d) w += y;
            }
            warpsums[lane] = w;
        }
        __syncthreads();
        int excl = x - v + ((wid > 0) ? warpsums[wid - 1] : 0) + s_carry;
        if (i < N) { rowptr[i] = excl; cursor[i] = excl; }
        __syncthreads();
        if (tid == 0) s_carry += warpsums[31];
        __syncthreads();
    }
    if (threadIdx.x == 0) rowptr[N] = s_carry;
}

__global__ void fill_kernel(const int* __restrict__ ei, int* __restrict__ cursor,
                            int* __restrict__ csrc, int E) {
    int t = blockIdx.x * blockDim.x + threadIdx.x;
    if (t < E) {
        int d = ei[E + t];
        int p = atomicAdd(&cursor[d], 1);
        csrc[p] = ei[t];
    }
}

// final output + restore invariants (cursor/gsum/gcnt = 0)
__global__ void final_kernel(float* __restrict__ gsum, float* __restrict__ gcnt,
                             const float* __restrict__ fcb,
                             float* __restrict__ out, int G,
                             int* __restrict__ cursor, int N) {
    int i = blockIdx.x * blockDim.x + threadIdx.x;
    if (i < G) {
        out[i] = gsum[i] / fmaxf(gcnt[i], 1.0f) + fcb[0];
        gsum[i] = 0.f;
        gcnt[i] = 0.f;
    }
    if (i < N) cursor[i] = 0;
}

// ---------------- fused aggregate + MLP (persistent, 1024 thr) ----------------
#define SM_B1H 0
#define SM_B1L 34816
#define SM_B2H 69632
#define SM_B2L 104448
#define SM_AH  139264
#define SM_AL  174080
#define SM_SB1 208896
#define SM_SB2 209408
#define SM_SFW 209920
#define SM_SROW 210432
#define SM_TOTAL 210944

// split-bf16 GEMM: acc += Ah*Bh + Ah*Bl + Al*Bh  (per-warp 16x32 tile)
// Single k-pass; A and B fragments both via ldmatrix.x4.
__device__ __forceinline__ void gemm_tile(
    const __nv_bfloat16* sAh, const __nv_bfloat16* sAl,
    const __nv_bfloat16* sBh, const __nv_bfloat16* sBl,
    float acc[4][4], int wr, int wc, int lane) {
    int arow = wr * 16 + (lane & 15);
    int acol = (lane >> 4) * 8;
    // B ldmatrix.x4 lane mapping: matrix j = lane>>3;
    //   n-group = (j>>1)*8 + (lane&7), k-half = (j&1)*8
    int bn = wc * 32 + ((lane >> 4) << 3) + (lane & 7);
    int bk = ((lane >> 3) & 1) << 3;
    const __nv_bfloat16* ah_base = sAh + arow * LDT + acol;
    const __nv_bfloat16* al_base = sAl + arow * LDT + acol;
    const __nv_bfloat16* bh_base = sBh + bn * LDT + bk;
    const __nv_bfloat16* bl_base = sBl + bn * LDT + bk;
    #pragma unroll
    for (int k0 = 0; k0 < 8; k0++) {
        uint32_t ah[4], al[4];
        ldm4(ah, smem_u32(ah_base + k0 * 16));
        ldm4(al, smem_u32(al_base + k0 * 16));
        #pragma unroll
        for (int p = 0; p < 2; p++) {
            int nfp = p * 2;
            uint32_t bh[4], bl[4];
            ldm4(bh, smem_u32(bh_base + nfp * 8 * LDT + k0 * 16));
            ldm4(bl, smem_u32(bl_base + nfp * 8 * LDT + k0 * 16));
            mma16816(acc[nfp],     ah, bh[0], bh[1]);
            mma16816(acc[nfp + 1], ah, bh[2], bh[3]);
            mma16816(acc[nfp],     ah, bl[0], bl[1]);
            mma16816(acc[nfp + 1], ah, bl[2], bl[3]);
            mma16816(acc[nfp],     al, bh[0], bh[1]);
            mma16816(acc[nfp + 1], al, bh[2], bh[3]);
        }
    }
}

// accumulate 4 neighbor rows
#define GATHER4(v, J)                                                     \
    do {                                                                  \
        int t0 = __ldg(&csrc[(J)]);                                       \
        int t1 = __ldg(&csrc[(J) + 1]);                                   \
        int t2 = __ldg(&csrc[(J) + 2]);                                   \
        int t3 = __ldg(&csrc[(J) + 3]);                                   \
        float4 m0 = X4[(size_t)t0 * 32 + lane];                           \
        float4 m1 = X4[(size_t)t1 * 32 + lane];                           \
        float4 m2 = X4[(size_t)t2 * 32 + lane];                           \
        float4 m3 = X4[(size_t)t3 * 32 + lane];                           \
        v.x += m0.x + m1.x + m2.x + m3.x;                                 \
        v.y += m0.y + m1.y + m2.y + m3.y;                                 \
        v.z += m0.z + m1.z + m2.z + m3.z;                                 \
        v.w += m0.w + m1.w + m2.w + m3.w;                                 \
    } while (0)

__global__ __launch_bounds__(1024, 1) void mlp_kernel(
    const float* __restrict__ X,
    const int* __restrict__ rowptr, const int* __restrict__ csrc,
    float* __restrict__ H,
    const __nv_bfloat16* __restrict__ W1h, const __nv_bfloat16* __restrict__ W1l,
    const __nv_bfloat16* __restrict__ W2h, const __nv_bfloat16* __restrict__ W2l,
    const float* __restrict__ b1, const float* __restrict__ b2,
    const float* __restrict__ epsp,
    int n, int ntiles, int relu_out, int pool,
    const int* __restrict__ batch, const float* __restrict__ w2fc,
    float* __restrict__ gsum, float* __restrict__ gcnt) {
    extern __shared__ char sm[];
    __nv_bfloat16* sB1h = (__nv_bfloat16*)(sm + SM_B1H);
    __nv_bfloat16* sB1l = (__nv_bfloat16*)(sm + SM_B1L);
    __nv_bfloat16* sB2h = (__nv_bfloat16*)(sm + SM_B2H);
    __nv_bfloat16* sB2l = (__nv_bfloat16*)(sm + SM_B2L);
    __nv_bfloat16* sAh  = (__nv_bfloat16*)(sm + SM_AH);
    __nv_bfloat16* sAl  = (__nv_bfloat16*)(sm + SM_AL);
    float* sb1  = (float*)(sm + SM_SB1);
    float* sb2  = (float*)(sm + SM_SB2);
    float* sfw  = (float*)(sm + SM_SFW);   // w2fc for pool layer
    float* srow = (float*)(sm + SM_SROW);

    int tid = threadIdx.x;
    int lane = tid & 31;
    int wid = tid >> 5;           // 0..31
    int wr = wid & 7;             // row group (16 rows)
    int wc = wid >> 3;            // col group (32 cols)

    if (tid < 128) {
        sb1[tid] = b1[tid];
        sb2[tid] = b2[tid];
        sfw[tid] = w2fc[tid];
    }

    // load weight planes once (persistent); pool layer skips B2
    {
        const uint4* p1h = (const uint4*)W1h;
        const uint4* p1l = (const uint4*)W1l;
        const uint4* p2h = (const uint4*)W2h;
        const uint4* p2l = (const uint4*)W2l;
        for (int i = tid; i < 2048; i += 1024) {
            int r = i >> 4, c = (i & 15) * 8;
            int d = r * LDT + c;
            *(uint4*)&sB1h[d] = p1h[i];
            *(uint4*)&sB1l[d] = p1l[i];
            if (!pool) {
                *(uint4*)&sB2h[d] = p2h[i];
                *(uint4*)&sB2l[d] = p2l[i];
            }
        }
    }

    float s = 1.0f + __ldg(epsp);
    float bconst = __ldg(&w2fc[128]);
    const float4* X4 = (const float4*)X;

    for (int tile = blockIdx.x; tile < ntiles; tile += gridDim.x) {
        int row0 = tile * 128;
        if (tid < 128) srow[tid] = 0.f;

        // gather: A = (1+eps)*X[row] + sum_nbrs X[j]; 2 rows per warp iter
        for (int r2 = wid; r2 < 64; r2 += 32) {
            int rA = r2, rB = r2 + 64;
            int grA = row0 + rA, grB = row0 + rB;
            float4 va = make_float4(0.f, 0.f, 0.f, 0.f);
            float4 vb = make_float4(0.f, 0.f, 0.f, 0.f);
            int ja = 0, ea = 0, jb = 0, eb = 0;
            if (grA < n) {
                float4 xv = X4[(size_t)grA * 32 + lane];
                va.x = s * xv.x; va.y = s * xv.y; va.z = s * xv.z; va.w = s * xv.w;
                ja = __ldg(&rowptr[grA]); ea = __ldg(&rowptr[grA + 1]);
            }
            if (grB < n) {
                float4 xv = X4[(size_t)grB * 32 + lane];
                vb.x = s * xv.x; vb.y = s * xv.y; vb.z = s * xv.z; vb.w = s * xv.w;
                jb = __ldg(&rowptr[grB]); eb = __ldg(&rowptr[grB + 1]);
            }
            while (ja + 4 <= ea && jb + 4 <= eb) {
                GATHER4(va, ja);
                GATHER4(vb, jb);
                ja += 4; jb += 4;
            }
            for (; ja + 4 <= ea; ja += 4) GATHER4(va, ja);
            for (; ja < ea; ja++) {
                int t0 = __ldg(&csrc[ja]);
                float4 m0 = X4[(size_t)t0 * 32 + lane];
                va.x += m0.x; va.y += m0.y; va.z += m0.z; va.w += m0.w;
            }
            for (; jb + 4 <= eb; jb += 4) GATHER4(vb, jb);
            for (; jb < eb; jb++) {
                int t0 = __ldg(&csrc[jb]);
                float4 m0 = X4[(size_t)t0 * 32 + lane];
                vb.x += m0.x; vb.y += m0.y; vb.z += m0.z; vb.w += m0.w;
            }
            float q0, q1, q2, q3;
            uint2 hi2, lo2;
            hi2.x = pack_hi(va.x, va.y, q0, q1);
            hi2.y = pack_hi(va.z, va.w, q2, q3);
            lo2.x = pack_lo(q0, q1);
            lo2.y = pack_lo(q2, q3);
            int d = rA * LDT + lane * 4;
            *(uint2*)&sAh[d] = hi2;
            *(uint2*)&sAl[d] = lo2;
            hi2.x = pack_hi(vb.x, vb.y, q0, q1);
            hi2.y = pack_hi(vb.z, vb.w, q2, q3);
            lo2.x = pack_lo(q0, q1);
            lo2.y = pack_lo(q2, q3);
            d = rB * LDT + lane * 4;
            *(uint2*)&sAh[d] = hi2;
            *(uint2*)&sAl[d] = lo2;
        }
        __syncthreads();

        float acc[4][4];
        #pragma unroll
        for (int j = 0; j < 4; j++)
            #pragma unroll
            for (int q = 0; q < 4; q++) acc[j][q] = 0.f;

        // GEMM1
        gemm_tile(sAh, sAl, sB1h, sB1l, acc, wr, wc, lane);

        if (pool) {
            // layer 2: h.fc = ReLU(acc+b1) @ w2fc (+ bconst per node)
            int r = wr * 16 + (lane >> 2);
            float d0 = 0.f, d1 = 0.f;
            #pragma unroll
            for (int nf = 0; nf < 4; nf++) {
                int c = wc * 32 + nf * 8 + (lane & 3) * 2;
                float* a = acc[nf];
                d0 = fmaf(fmaxf(a[0] + sb1[c], 0.f), sfw[c], d0);
                d0 = fmaf(fmaxf(a[1] + sb1[c + 1], 0.f), sfw[c + 1], d0);
                d1 = fmaf(fmaxf(a[2] + sb1[c], 0.f), sfw[c], d1);
                d1 = fmaf(fmaxf(a[3] + sb1[c + 1], 0.f), sfw[c + 1], d1);
            }
            atomicAdd(&srow[r], d0);
            atomicAdd(&srow[r + 8], d1);
            __syncthreads();
            if (tid < 128) {
                int gr = row0 + tid;
                if (gr < n) {
                    int g = batch[gr];
                    atomicAdd(&gsum[g], srow[tid] + bconst);
                    atomicAdd(&gcnt[g], 1.0f);
                }
            }
            __syncthreads();
            continue;
        }

        __syncthreads();  // all reads of sA done before overwrite

        // epilogue1: T = ReLU(acc + b1) -> split back into sA planes
        {
            int r = wr * 16 + (lane >> 2);
            #pragma unroll
            for (int nf = 0; nf < 4; nf++) {
                int c = wc * 32 + nf * 8 + (lane & 3) * 2;
                float* a = acc[nf];
                float v0 = fmaxf(a[0] + sb1[c], 0.f);
                float v1 = fmaxf(a[1] + sb1[c + 1], 0.f);
                float v2 = fmaxf(a[2] + sb1[c], 0.f);
                float v3 = fmaxf(a[3] + sb1[c + 1], 0.f);
                float q0, q1;
                uint32_t h = pack_hi(v0, v1, q0, q1);
                *(uint32_t*)&sAh[r * LDT + c] = h;
                *(uint32_t*)&sAl[r * LDT + c] = pack_lo(q0, q1);
                h = pack_hi(v2, v3, q0, q1);
                *(uint32_t*)&sAh[(r + 8) * LDT + c] = h;
                *(uint32_t*)&sAl[(r + 8) * LDT + c] = pack_lo(q0, q1);
            }
        }
        __syncthreads();

        #pragma unroll
        for (int j = 0; j < 4; j++)
            #pragma unroll
            for (int q = 0; q < 4; q++) acc[j][q] = 0.f;

        // GEMM2
        gemm_tile(sAh, sAl, sB2h, sB2l, acc, wr, wc, lane);

        // epilogue2: out = acc + b2 (+ReLU) -> H
        {
            int r = wr * 16 + (lane >> 2);
            int gr0 = row0 + r, gr1 = gr0 + 8;
            #pragma unroll
            for (int nf = 0; nf < 4; nf++) {
                int c = wc * 32 + nf * 8 + (lane & 3) * 2;
                float* a = acc[nf];
                float v0 = a[0] + sb2[c], v1 = a[1] + sb2[c + 1];
                float v2 = a[2] + sb2[c], v3 = a[3] + sb2[c + 1];
                if (relu_out) {
                    v0 = fmaxf(v0, 0.f); v1 = fmaxf(v1, 0.f);
                    v2 = fmaxf(v2, 0.f); v3 = fmaxf(v3, 0.f);
                }
                if (gr0 < n) *(float2*)&H[(size_t)gr0 * 128 + c] = make_float2(v0, v1);
                if (gr1 < n) *(float2*)&H[(size_t)gr1 * 128 + c] = make_float2(v2, v3);
            }
        }
        __syncthreads();  // protect sA before next tile's gather
    }
}

// ---------------- host launcher ----------------
extern "C" void kernel_launch(void* const* d_in, const int* in_sizes, int n_in,
                              void* d_out, int out_size) {
    const float* x     = (const float*)d_in[0];
    const int*   ei    = (const int*)d_in[1];
    const int*   batch = (const int*)d_in[2];
    const float* W1s[3] = {(const float*)d_in[3],  (const float*)d_in[8],  (const float*)d_in[13]};
    const float* b1s[3] = {(const float*)d_in[4],  (const float*)d_in[9],  (const float*)d_in[14]};
    const float* W2s[3] = {(const float*)d_in[5],  (const float*)d_in[10], (const float*)d_in[15]};
    const float* b2s[3] = {(const float*)d_in[6],  (const float*)d_in[11], (const float*)d_in[16]};
    const float* epss[3]= {(const float*)d_in[7],  (const float*)d_in[12], (const float*)d_in[17]};
    const float* fcw   = (const float*)d_in[18];
    const float* fcb   = (const float*)d_in[19];

    int N = in_sizes[2];
    int E = in_sizes[1] / 2;
    int G = out_size;

    float *bufA, *bufB, *gsum, *gcnt, *w2fc;
    int *rowptr, *cursor, *csrc;
    __nv_bfloat16 *wthi, *wtlo;
    cudaGetSymbolAddress((void**)&bufA, g_bufA);
    cudaGetSymbolAddress((void**)&bufB, g_bufB);
    cudaGetSymbolAddress((void**)&gsum, g_gsum);
    cudaGetSymbolAddress((void**)&gcnt, g_gcnt);
    cudaGetSymbolAddress((void**)&rowptr, g_rowptr);
    cudaGetSymbolAddress((void**)&cursor, g_cursor);
    cudaGetSymbolAddress((void**)&csrc, g_csrc);
    cudaGetSymbolAddress((void**)&w2fc, g_w2fc);
    cudaGetSymbolAddress((void**)&wthi, g_wthi);
    cudaGetSymbolAddress((void**)&wtlo, g_wtlo);

    cudaFuncSetAttribute(mlp_kernel, cudaFuncAttributeMaxDynamicSharedMemorySize, SM_TOTAL);

    int prep_threads = (E > 6 * 16384 + 129) ? E : (6 * 16384 + 129);
    // 1: weight transform + edge count + w2fc (cursor==0 at entry)
    prep_kernel<<<(prep_threads + 255) / 256, 256>>>(
        W1s[0], W2s[0], W1s[1], W2s[1], W1s[2], W2s[2],
        wthi, wtlo, ei, cursor, E, fcw, b2s[2], w2fc);
    // 2-3: CSR scan + fill
    scan_kernel<<<1, 1024>>>(cursor, rowptr, N);
    fill_kernel<<<(E + 255) / 256, 256>>>(ei, cursor, csrc, E);

    // 4-6: ping-pong layers; layer2 pools (no GEMM2)
    const float* ins[3]  = {x, bufA, bufB};
    float*       outs[3] = {bufA, bufB, bufA /* unused (pool) */};
    int ntiles = (N + 127) / 128;
    for (int l = 0; l < 3; l++) {
        mlp_kernel<<<148, 1024, SM_TOTAL>>>(
            ins[l], rowptr, csrc, outs[l],
            wthi + (2 * l) * 16384, wtlo + (2 * l) * 16384,
            wthi + (2 * l + 1) * 16384, wtlo + (2 * l + 1) * 16384,
            b1s[l], b2s[l], epss[l],
            N, ntiles, (l < 2) ? 1 : 0, (l == 2) ? 1 : 0,
            batch, w2fc, gsum, gcnt);
    }
    // 7: output + restore invariants
    final_kernel<<<(N + 255) / 256, 256>>>(gsum, gcnt, fcb, (float*)d_out, G, cursor, N);
}

// round 11
// speedup vs baseline: 2.8275x; 1.0599x over previous
#include <cuda_runtime.h>
#include <cuda_bf16.h>
#include <cuda_fp16.h>
#include <cstdint>

// ---------------------------------------------------------------------------
// GINRegressor on GB300: CSR gather fused into split-bf16 tensor MLP.
// Inter-layer activations stored fp16 (halves gather + store traffic).
// 1024 threads/CTA; persistent CTAs; ping-pong buffers; layer2 GEMM2 folded
// to GEMV (w2fc = W2_2 @ fc_w).
// Launch order: prep(1), scan(2), fill(3), mlp0(4), mlp1(5), mlp2(6), final(7).
// Invariant: cursor/gsum/gcnt zero at entry (final_kernel restores).
// ---------------------------------------------------------------------------

#define NMAX 50000
#define EMAX 800000
#define GMAX 500
#define LDT 136  // padded smem tile stride (bf16 elems) -> conflict-free

__device__ __half g_bufA[NMAX * 128];
__device__ __half g_bufB[NMAX * 128];
__device__ float g_gsum[GMAX];
__device__ float g_gcnt[GMAX];
__device__ int   g_rowptr[NMAX + 1];
__device__ int   g_cursor[NMAX];          // zero at entry (invariant)
__device__ int   g_csrc[EMAX];
__device__ float g_w2fc[129];             // [0..127]=W2_2@fc, [128]=b2_2.fc
__device__ __align__(16) __nv_bfloat16 g_wthi[6 * 16384];  // W^T hi planes
__device__ __align__(16) __nv_bfloat16 g_wtlo[6 * 16384];  // W^T lo planes

// ---------------- helpers ----------------
__device__ __forceinline__ uint32_t smem_u32(const void* p) {
    uint32_t a;
    asm("{ .reg .u64 t; cvta.to.shared.u64 t, %1; cvt.u32.u64 %0, t; }"
        : "=r"(a) : "l"(p));
    return a;
}

__device__ __forceinline__ void ldm4(uint32_t* a, uint32_t addr) {
    asm volatile("ldmatrix.sync.aligned.m8n8.x4.shared.b16 {%0,%1,%2,%3}, [%4];"
                 : "=r"(a[0]), "=r"(a[1]), "=r"(a[2]), "=r"(a[3]) : "r"(addr));
}

__device__ __forceinline__ void mma16816(float* c, const uint32_t* a,
                                         uint32_t b0, uint32_t b1) {
    asm volatile(
        "mma.sync.aligned.m16n8k16.row.col.f32.bf16.bf16.f32 "
        "{%0,%1,%2,%3}, {%4,%5,%6,%7}, {%8,%9}, {%0,%1,%2,%3};"
        : "+f"(c[0]), "+f"(c[1]), "+f"(c[2]), "+f"(c[3])
        : "r"(a[0]), "r"(a[1]), "r"(a[2]), "r"(a[3]), "r"(b0), "r"(b1));
}

__device__ __forceinline__ uint32_t pack_hi(float a, float b, float& ra, float& rb) {
    __nv_bfloat16 ha = __float2bfloat16(a), hb = __float2bfloat16(b);
    ra = a - __bfloat162float(ha);
    rb = b - __bfloat162float(hb);
    return ((uint32_t)__bfloat16_as_ushort(hb) << 16) | __bfloat16_as_ushort(ha);
}
__device__ __forceinline__ uint32_t pack_lo(float a, float b) {
    return ((uint32_t)__bfloat16_as_ushort(__float2bfloat16(b)) << 16) |
           __bfloat16_as_ushort(__float2bfloat16(a));
}

// ---------------- prep: weight transform + edge count + w2fc ----------------
__global__ void prep_kernel(const float* __restrict__ Wa, const float* __restrict__ Wb,
                            const float* __restrict__ Wc, const float* __restrict__ Wd,
                            const float* __restrict__ We, const float* __restrict__ Wf,
                            __nv_bfloat16* __restrict__ hi, __nv_bfloat16* __restrict__ lo,
                            const int* __restrict__ ei, int* __restrict__ cnt, int E,
                            const float* __restrict__ fcw, const float* __restrict__ b2f,
                            float* __restrict__ w2fc) {
    int t = blockIdx.x * blockDim.x + threadIdx.x;
    if (t < 6 * 16384) {
        int m = t >> 14;
        int i = t & 16383;
        int n = i >> 7, k = i & 127;
        const float* W = (m == 0) ? Wa : (m == 1) ? Wb : (m == 2) ? Wc
                       : (m == 3) ? Wd : (m == 4) ? We : Wf;
        float v = W[k * 128 + n];
        __nv_bfloat16 h = __float2bfloat16(v);
        hi[t] = h;
        lo[t] = __float2bfloat16(v - __bfloat162float(h));
    } else if (t < 6 * 16384 + 128) {
        int k = t - 6 * 16384;
        float s = 0.f;
        #pragma unroll 4
        for (int c = 0; c < 128; c++) s = fmaf(Wf[k * 128 + c], fcw[c], s);
        w2fc[k] = s;
    } else if (t == 6 * 16384 + 128) {
        float s = 0.f;
        for (int c = 0; c < 128; c++) s = fmaf(b2f[c], fcw[c], s);
        w2fc[128] = s;
    }
    if (t < E) atomicAdd(&cnt[ei[E + t]], 1);
}

// ---------------- CSR build ----------------
__global__ __launch_bounds__(1024) void scan_kernel(int* __restrict__ cursor,
                                                    int* __restrict__ rowptr, int N) {
    __shared__ int warpsums[32];
    __shared__ int s_carry;
    int tid = threadIdx.x, lane = tid & 31, wid = tid >> 5;
    if (tid == 0) s_carry = 0;
    __syncthreads();
    for (int base = 0; base < N; base += 1024) {
        int i = base + tid;
        int v = (i < N) ? cursor[i] : 0;
        int x = v;
        #pragma unroll
        for (int d = 1; d < 32; d <<= 1) {
            int y = __shfl_up_sync(0xffffffffu, x, d);
            if (lane >= d) x += y;
        }
        if (lane == 31) warpsums[wid] = x;
        __syncthreads();
        if (wid == 0) {
            int w = warpsums[lane];
            #pragma unroll
            for (int d = 1; d < 32; d <<= 1) {
                int y = __shfl_up_sync(0xffffffffu, w, d);
                if (lane >= d) w += y;
            }
            warpsums[lane] = w;
        }
        __syncthreads();
        int excl = x - v + ((wid > 0) ? warpsums[wid - 1] : 0) + s_carry;
        if (i < N) { rowptr[i] = excl; cursor[i] = excl; }
        __syncthreads();
        if (tid == 0) s_carry += warpsums[31];
        __syncthreads();
    }
    if (threadIdx.x == 0) rowptr[N] = s_carry;
}

__global__ void fill_kernel(const int* __restrict__ ei, int* __restrict__ cursor,
                            int* __restrict__ csrc, int E) {
    int t = blockIdx.x * blockDim.x + threadIdx.x;
    if (t < E) {
        int d = ei[E + t];
        int p = atomicAdd(&cursor[d], 1);
        csrc[p] = ei[t];
    }
}

// final output + restore invariants (cursor/gsum/gcnt = 0)
__global__ void final_kernel(float* __restrict__ gsum, float* __restrict__ gcnt,
                             const float* __restrict__ fcb,
                             float* __restrict__ out, int G,
                             int* __restrict__ cursor, int N) {
    int i = blockIdx.x * blockDim.x + threadIdx.x;
    if (i < G) {
        out[i] = gsum[i] / fmaxf(gcnt[i], 1.0f) + fcb[0];
        gsum[i] = 0.f;
        gcnt[i] = 0.f;
    }
    if (i < N) cursor[i] = 0;
}

// ---------------- fused aggregate + MLP (persistent, 1024 thr) ----------------
#define SM_B1H 0
#define SM_B1L 34816
#define SM_B2H 69632
#define SM_B2L 104448
#define SM_AH  139264
#define SM_AL  174080
#define SM_SB1 208896
#define SM_SB2 209408
#define SM_SFW 209920
#define SM_SROW 210432
#define SM_TOTAL 210944

// split-bf16 GEMM: acc += Ah*Bh + Ah*Bl + Al*Bh  (per-warp 16x32 tile)
// Single k-pass; A and B fragments both via ldmatrix.x4.
__device__ __forceinline__ void gemm_tile(
    const __nv_bfloat16* sAh, const __nv_bfloat16* sAl,
    const __nv_bfloat16* sBh, const __nv_bfloat16* sBl,
    float acc[4][4], int wr, int wc, int lane) {
    int arow = wr * 16 + (lane & 15);
    int acol = (lane >> 4) * 8;
    int bn = wc * 32 + ((lane >> 4) << 3) + (lane & 7);
    int bk = ((lane >> 3) & 1) << 3;
    const __nv_bfloat16* ah_base = sAh + arow * LDT + acol;
    const __nv_bfloat16* al_base = sAl + arow * LDT + acol;
    const __nv_bfloat16* bh_base = sBh + bn * LDT + bk;
    const __nv_bfloat16* bl_base = sBl + bn * LDT + bk;
    #pragma unroll
    for (int k0 = 0; k0 < 8; k0++) {
        uint32_t ah[4], al[4];
        ldm4(ah, smem_u32(ah_base + k0 * 16));
        ldm4(al, smem_u32(al_base + k0 * 16));
        #pragma unroll
        for (int p = 0; p < 2; p++) {
            int nfp = p * 2;
            uint32_t bh[4], bl[4];
            ldm4(bh, smem_u32(bh_base + nfp * 8 * LDT + k0 * 16));
            ldm4(bl, smem_u32(bl_base + nfp * 8 * LDT + k0 * 16));
            mma16816(acc[nfp],     ah, bh[0], bh[1]);
            mma16816(acc[nfp + 1], ah, bh[2], bh[3]);
            mma16816(acc[nfp],     ah, bl[0], bl[1]);
            mma16816(acc[nfp + 1], ah, bl[2], bl[3]);
            mma16816(acc[nfp],     al, bh[0], bh[1]);
            mma16816(acc[nfp + 1], al, bh[2], bh[3]);
        }
    }
}

// accumulate 4 neighbor rows (fp32 source)
#define GATHER4(v, J)                                                     \
    do {                                                                  \
        int t0 = __ldg(&csrc[(J)]);                                       \
        int t1 = __ldg(&csrc[(J) + 1]);                                   \
        int t2 = __ldg(&csrc[(J) + 2]);                                   \
        int t3 = __ldg(&csrc[(J) + 3]);                                   \
        float4 m0 = X4[(size_t)t0 * 32 + lane];                           \
        float4 m1 = X4[(size_t)t1 * 32 + lane];                           \
        float4 m2 = X4[(size_t)t2 * 32 + lane];                           \
        float4 m3 = X4[(size_t)t3 * 32 + lane];                           \
        v.x += m0.x + m1.x + m2.x + m3.x;                                 \
        v.y += m0.y + m1.y + m2.y + m3.y;                                 \
        v.z += m0.z + m1.z + m2.z + m3.z;                                 \
        v.w += m0.w + m1.w + m2.w + m3.w;                                 \
    } while (0)

// accumulate 4 neighbor rows (fp16 source; lane owns 4 halves = uint2)
#define GATHER4H(v, J)                                                    \
    do {                                                                  \
        int t0 = __ldg(&csrc[(J)]);                                       \
        int t1 = __ldg(&csrc[(J) + 1]);                                   \
        int t2 = __ldg(&csrc[(J) + 2]);                                   \
        int t3 = __ldg(&csrc[(J) + 3]);                                   \
        uint2 w0 = Xh[(size_t)t0 * 32 + lane];                            \
        uint2 w1 = Xh[(size_t)t1 * 32 + lane];                            \
        uint2 w2 = Xh[(size_t)t2 * 32 + lane];                            \
        uint2 w3 = Xh[(size_t)t3 * 32 + lane];                            \
        float2 f;                                                         \
        f = __half22float2(*(__half2*)&w0.x); v.x += f.x; v.y += f.y;     \
        f = __half22float2(*(__half2*)&w0.y); v.z += f.x; v.w += f.y;     \
        f = __half22float2(*(__half2*)&w1.x); v.x += f.x; v.y += f.y;     \
        f = __half22float2(*(__half2*)&w1.y); v.z += f.x; v.w += f.y;     \
        f = __half22float2(*(__half2*)&w2.x); v.x += f.x; v.y += f.y;     \
        f = __half22float2(*(__half2*)&w2.y); v.z += f.x; v.w += f.y;     \
        f = __half22float2(*(__half2*)&w3.x); v.x += f.x; v.y += f.y;     \
        f = __half22float2(*(__half2*)&w3.y); v.z += f.x; v.w += f.y;     \
    } while (0)

__global__ __launch_bounds__(1024, 1) void mlp_kernel(
    const void* __restrict__ Xv, int in_half,
    const int* __restrict__ rowptr, const int* __restrict__ csrc,
    __half* __restrict__ H,
    const __nv_bfloat16* __restrict__ W1h, const __nv_bfloat16* __restrict__ W1l,
    const __nv_bfloat16* __restrict__ W2h, const __nv_bfloat16* __restrict__ W2l,
    const float* __restrict__ b1, const float* __restrict__ b2,
    const float* __restrict__ epsp,
    int n, int ntiles, int relu_out, int pool,
    const int* __restrict__ batch, const float* __restrict__ w2fc,
    float* __restrict__ gsum, float* __restrict__ gcnt) {
    extern __shared__ char sm[];
    __nv_bfloat16* sB1h = (__nv_bfloat16*)(sm + SM_B1H);
    __nv_bfloat16* sB1l = (__nv_bfloat16*)(sm + SM_B1L);
    __nv_bfloat16* sB2h = (__nv_bfloat16*)(sm + SM_B2H);
    __nv_bfloat16* sB2l = (__nv_bfloat16*)(sm + SM_B2L);
    __nv_bfloat16* sAh  = (__nv_bfloat16*)(sm + SM_AH);
    __nv_bfloat16* sAl  = (__nv_bfloat16*)(sm + SM_AL);
    float* sb1  = (float*)(sm + SM_SB1);
    float* sb2  = (float*)(sm + SM_SB2);
    float* sfw  = (float*)(sm + SM_SFW);   // w2fc for pool layer
    float* srow = (float*)(sm + SM_SROW);

    int tid = threadIdx.x;
    int lane = tid & 31;
    int wid = tid >> 5;           // 0..31
    int wr = wid & 7;             // row group (16 rows)
    int wc = wid >> 3;            // col group (32 cols)

    if (tid < 128) {
        sb1[tid] = b1[tid];
        sb2[tid] = b2[tid];
        sfw[tid] = w2fc[tid];
    }

    // load weight planes once (persistent); pool layer skips B2
    {
        const uint4* p1h = (const uint4*)W1h;
        const uint4* p1l = (const uint4*)W1l;
        const uint4* p2h = (const uint4*)W2h;
        const uint4* p2l = (const uint4*)W2l;
        for (int i = tid; i < 2048; i += 1024) {
            int r = i >> 4, c = (i & 15) * 8;
            int d = r * LDT + c;
            *(uint4*)&sB1h[d] = p1h[i];
            *(uint4*)&sB1l[d] = p1l[i];
            if (!pool) {
                *(uint4*)&sB2h[d] = p2h[i];
                *(uint4*)&sB2l[d] = p2l[i];
            }
        }
    }

    float s = 1.0f + __ldg(epsp);
    float bconst = __ldg(&w2fc[128]);
    const float4* X4 = (const float4*)Xv;
    const uint2*  Xh = (const uint2*)Xv;

    for (int tile = blockIdx.x; tile < ntiles; tile += gridDim.x) {
        int row0 = tile * 128;
        if (tid < 128) srow[tid] = 0.f;

        // gather: A = (1+eps)*X[row] + sum_nbrs X[j]; 2 rows per warp iter
        for (int r2 = wid; r2 < 64; r2 += 32) {
            int rA = r2, rB = r2 + 64;
            int grA = row0 + rA, grB = row0 + rB;
            float4 va = make_float4(0.f, 0.f, 0.f, 0.f);
            float4 vb = make_float4(0.f, 0.f, 0.f, 0.f);
            int ja = 0, ea = 0, jb = 0, eb = 0;
            if (in_half) {
                if (grA < n) {
                    uint2 w = Xh[(size_t)grA * 32 + lane];
                    float2 f0 = __half22float2(*(__half2*)&w.x);
                    float2 f1 = __half22float2(*(__half2*)&w.y);
                    va.x = s * f0.x; va.y = s * f0.y;
                    va.z = s * f1.x; va.w = s * f1.y;
                    ja = __ldg(&rowptr[grA]); ea = __ldg(&rowptr[grA + 1]);
                }
                if (grB < n) {
                    uint2 w = Xh[(size_t)grB * 32 + lane];
                    float2 f0 = __half22float2(*(__half2*)&w.x);
                    float2 f1 = __half22float2(*(__half2*)&w.y);
                    vb.x = s * f0.x; vb.y = s * f0.y;
                    vb.z = s * f1.x; vb.w = s * f1.y;
                    jb = __ldg(&rowptr[grB]); eb = __ldg(&rowptr[grB + 1]);
                }
                while (ja + 4 <= ea && jb + 4 <= eb) {
                    GATHER4H(va, ja);
                    GATHER4H(vb, jb);
                    ja += 4; jb += 4;
                }
                for (; ja + 4 <= ea; ja += 4) GATHER4H(va, ja);
                for (; ja < ea; ja++) {
                    int t0 = __ldg(&csrc[ja]);
                    uint2 w = Xh[(size_t)t0 * 32 + lane];
                    float2 f0 = __half22float2(*(__half2*)&w.x);
                    float2 f1 = __half22float2(*(__half2*)&w.y);
                    va.x += f0.x; va.y += f0.y; va.z += f1.x; va.w += f1.y;
                }
                for (; jb + 4 <= eb; jb += 4) GATHER4H(vb, jb);
                for (; jb < eb; jb++) {
                    int t0 = __ldg(&csrc[jb]);
                    uint2 w = Xh[(size_t)t0 * 32 + lane];
                    float2 f0 = __half22float2(*(__half2*)&w.x);
                    float2 f1 = __half22float2(*(__half2*)&w.y);
                    vb.x += f0.x; vb.y += f0.y; vb.z += f1.x; vb.w += f1.y;
                }
            } else {
                if (grA < n) {
                    float4 xv = X4[(size_t)grA * 32 + lane];
                    va.x = s * xv.x; va.y = s * xv.y; va.z = s * xv.z; va.w = s * xv.w;
                    ja = __ldg(&rowptr[grA]); ea = __ldg(&rowptr[grA + 1]);
                }
                if (grB < n) {
                    float4 xv = X4[(size_t)grB * 32 + lane];
                    vb.x = s * xv.x; vb.y = s * xv.y; vb.z = s * xv.z; vb.w = s * xv.w;
                    jb = __ldg(&rowptr[grB]); eb = __ldg(&rowptr[grB + 1]);
                }
                while (ja + 4 <= ea && jb + 4 <= eb) {
                    GATHER4(va, ja);
                    GATHER4(vb, jb);
                    ja += 4; jb += 4;
                }
                for (; ja + 4 <= ea; ja += 4) GATHER4(va, ja);
                for (; ja < ea; ja++) {
                    int t0 = __ldg(&csrc[ja]);
                    float4 m0 = X4[(size_t)t0 * 32 + lane];
                    va.x += m0.x; va.y += m0.y; va.z += m0.z; va.w += m0.w;
                }
                for (; jb + 4 <= eb; jb += 4) GATHER4(vb, jb);
                for (; jb < eb; jb++) {
                    int t0 = __ldg(&csrc[jb]);
                    float4 m0 = X4[(size_t)t0 * 32 + lane];
                    vb.x += m0.x; vb.y += m0.y; vb.z += m0.z; vb.w += m0.w;
                }
            }
            float q0, q1, q2, q3;
            uint2 hi2, lo2;
            hi2.x = pack_hi(va.x, va.y, q0, q1);
            hi2.y = pack_hi(va.z, va.w, q2, q3);
            lo2.x = pack_lo(q0, q1);
            lo2.y = pack_lo(q2, q3);
            int d = rA * LDT + lane * 4;
            *(uint2*)&sAh[d] = hi2;
            *(uint2*)&sAl[d] = lo2;
            hi2.x = pack_hi(vb.x, vb.y, q0, q1);
            hi2.y = pack_hi(vb.z, vb.w, q2, q3);
            lo2.x = pack_lo(q0, q1);
            lo2.y = pack_lo(q2, q3);
            d = rB * LDT + lane * 4;
            *(uint2*)&sAh[d] = hi2;
            *(uint2*)&sAl[d] = lo2;
        }
        __syncthreads();

        float acc[4][4];
        #pragma unroll
        for (int j = 0; j < 4; j++)
            #pragma unroll
            for (int q = 0; q < 4; q++) acc[j][q] = 0.f;

        // GEMM1
        gemm_tile(sAh, sAl, sB1h, sB1l, acc, wr, wc, lane);

        if (pool) {
            // layer 2: h.fc = ReLU(acc+b1) @ w2fc (+ bconst per node)
            int r = wr * 16 + (lane >> 2);
            float d0 = 0.f, d1 = 0.f;
            #pragma unroll
            for (int nf = 0; nf < 4; nf++) {
                int c = wc * 32 + nf * 8 + (lane & 3) * 2;
                float* a = acc[nf];
                d0 = fmaf(fmaxf(a[0] + sb1[c], 0.f), sfw[c], d0);
                d0 = fmaf(fmaxf(a[1] + sb1[c + 1], 0.f), sfw[c + 1], d0);
                d1 = fmaf(fmaxf(a[2] + sb1[c], 0.f), sfw[c], d1);
                d1 = fmaf(fmaxf(a[3] + sb1[c + 1], 0.f), sfw[c + 1], d1);
            }
            atomicAdd(&srow[r], d0);
            atomicAdd(&srow[r + 8], d1);
            __syncthreads();
            if (tid < 128) {
                int gr = row0 + tid;
                if (gr < n) {
                    int g = batch[gr];
                    atomicAdd(&gsum[g], srow[tid] + bconst);
                    atomicAdd(&gcnt[g], 1.0f);
                }
            }
            __syncthreads();
            continue;
        }

        __syncthreads();  // all reads of sA done before overwrite

        // epilogue1: T = ReLU(acc + b1) -> split back into sA planes
        {
            int r = wr * 16 + (lane >> 2);
            #pragma unroll
            for (int nf = 0; nf < 4; nf++) {
                int c = wc * 32 + nf * 8 + (lane & 3) * 2;
                float* a = acc[nf];
                float v0 = fmaxf(a[0] + sb1[c], 0.f);
                float v1 = fmaxf(a[1] + sb1[c + 1], 0.f);
                float v2 = fmaxf(a[2] + sb1[c], 0.f);
                float v3 = fmaxf(a[3] + sb1[c + 1], 0.f);
                float q0, q1;
                uint32_t h = pack_hi(v0, v1, q0, q1);
                *(uint32_t*)&sAh[r * LDT + c] = h;
                *(uint32_t*)&sAl[r * LDT + c] = pack_lo(q0, q1);
                h = pack_hi(v2, v3, q0, q1);
                *(uint32_t*)&sAh[(r + 8) * LDT + c] = h;
                *(uint32_t*)&sAl[(r + 8) * LDT + c] = pack_lo(q0, q1);
            }
        }
        __syncthreads();

        #pragma unroll
        for (int j = 0; j < 4; j++)
            #pragma unroll
            for (int q = 0; q < 4; q++) acc[j][q] = 0.f;

        // GEMM2
        gemm_tile(sAh, sAl, sB2h, sB2l, acc, wr, wc, lane);

        // epilogue2: out = acc + b2 (+ReLU) -> H (fp16)
        {
            int r = wr * 16 + (lane >> 2);
            int gr0 = row0 + r, gr1 = gr0 + 8;
            #pragma unroll
            for (int nf = 0; nf < 4; nf++) {
                int c = wc * 32 + nf * 8 + (lane & 3) * 2;
                float* a = acc[nf];
                float v0 = a[0] + sb2[c], v1 = a[1] + sb2[c + 1];
                float v2 = a[2] + sb2[c], v3 = a[3] + sb2[c + 1];
                if (relu_out) {
                    v0 = fmaxf(v0, 0.f); v1 = fmaxf(v1, 0.f);
                    v2 = fmaxf(v2, 0.f); v3 = fmaxf(v3, 0.f);
                }
                if (gr0 < n)
                    *(__half2*)&H[(size_t)gr0 * 128 + c] = __floats2half2_rn(v0, v1);
                if (gr1 < n)
                    *(__half2*)&H[(size_t)gr1 * 128 + c] = __floats2half2_rn(v2, v3);
            }
        }
        __syncthreads();  // protect sA before next tile's gather
    }
}

// ---------------- host launcher ----------------
extern "C" void kernel_launch(void* const* d_in, const int* in_sizes, int n_in,
                              void* d_out, int out_size) {
    const float* x     = (const float*)d_in[0];
    const int*   ei    = (const int*)d_in[1];
    const int*   batch = (const int*)d_in[2];
    const float* W1s[3] = {(const float*)d_in[3],  (const float*)d_in[8],  (const float*)d_in[13]};
    const float* b1s[3] = {(const float*)d_in[4],  (const float*)d_in[9],  (const float*)d_in[14]};
    const float* W2s[3] = {(const float*)d_in[5],  (const float*)d_in[10], (const float*)d_in[15]};
    const float* b2s[3] = {(const float*)d_in[6],  (const float*)d_in[11], (const float*)d_in[16]};
    const float* epss[3]= {(const float*)d_in[7],  (const float*)d_in[12], (const float*)d_in[17]};
    const float* fcw   = (const float*)d_in[18];
    const float* fcb   = (const float*)d_in[19];

    int N = in_sizes[2];
    int E = in_sizes[1] / 2;
    int G = out_size;

    float *gsum, *gcnt, *w2fc;
    __half *bufA, *bufB;
    int *rowptr, *cursor, *csrc;
    __nv_bfloat16 *wthi, *wtlo;
    cudaGetSymbolAddress((void**)&bufA, g_bufA);
    cudaGetSymbolAddress((void**)&bufB, g_bufB);
    cudaGetSymbolAddress((void**)&gsum, g_gsum);
    cudaGetSymbolAddress((void**)&gcnt, g_gcnt);
    cudaGetSymbolAddress((void**)&rowptr, g_rowptr);
    cudaGetSymbolAddress((void**)&cursor, g_cursor);
    cudaGetSymbolAddress((void**)&csrc, g_csrc);
    cudaGetSymbolAddress((void**)&w2fc, g_w2fc);
    cudaGetSymbolAddress((void**)&wthi, g_wthi);
    cudaGetSymbolAddress((void**)&wtlo, g_wtlo);

    cudaFuncSetAttribute(mlp_kernel, cudaFuncAttributeMaxDynamicSharedMemorySize, SM_TOTAL);

    int prep_threads = (E > 6 * 16384 + 129) ? E : (6 * 16384 + 129);
    // 1: weight transform + edge count + w2fc (cursor==0 at entry)
    prep_kernel<<<(prep_threads + 255) / 256, 256>>>(
        W1s[0], W2s[0], W1s[1], W2s[1], W1s[2], W2s[2],
        wthi, wtlo, ei, cursor, E, fcw, b2s[2], w2fc);
    // 2-3: CSR scan + fill
    scan_kernel<<<1, 1024>>>(cursor, rowptr, N);
    fill_kernel<<<(E + 255) / 256, 256>>>(ei, cursor, csrc, E);

    // 4-6: ping-pong layers (fp16 intermediates); layer2 pools (no GEMM2)
    const void* ins[3]  = {(const void*)x, (const void*)bufA, (const void*)bufB};
    int         inh[3]  = {0, 1, 1};
    __half*     outs[3] = {bufA, bufB, bufA /* unused (pool) */};
    int ntiles = (N + 127) / 128;
    for (int l = 0; l < 3; l++) {
        mlp_kernel<<<148, 1024, SM_TOTAL>>>(
            ins[l], inh[l], rowptr, csrc, outs[l],
            wthi + (2 * l) * 16384, wtlo + (2 * l) * 16384,
            wthi + (2 * l + 1) * 16384, wtlo + (2 * l + 1) * 16384,
            b1s[l], b2s[l], epss[l],
            N, ntiles, (l < 2) ? 1 : 0, (l == 2) ? 1 : 0,
            batch, w2fc, gsum, gcnt);
    }
    // 7: output + restore invariants
    final_kernel<<<(N + 255) / 256, 256>>>(gsum, gcnt, fcb, (float*)d_out, G, cursor, N);
}

// round 12
// speedup vs baseline: 2.9567x; 1.0457x over previous
#include <cuda_runtime.h>
#include <cuda_bf16.h>
#include <cuda_fp16.h>
#include <cstdint>

// ---------------------------------------------------------------------------
// GINRegressor on GB300: CSR gather (fp16 everywhere) fused into split-bf16
// tensor MLP. x converted to fp16 once in prep. CSR stores pre-scaled row
// offsets (src*32) to kill gather address IMADs. 1024 thr/CTA persistent.
// Layer2 GEMM2 folded to GEMV (w2fc = W2_2 @ fc_w).
// Launch order: prep(1), scan(2), fill(3), mlp0(4), mlp1(5), mlp2(6), final(7).
// Invariant: cursor/gsum/gcnt zero at entry (final_kernel restores).
// ---------------------------------------------------------------------------

#define NMAX 50000
#define EMAX 800000
#define GMAX 500
#define LDT 136  // padded smem tile stride (bf16 elems) -> conflict-free

__device__ __half g_xh[NMAX * 128];       // fp16 copy of input x
__device__ __half g_bufA[NMAX * 128];
__device__ __half g_bufB[NMAX * 128];
__device__ float g_gsum[GMAX];
__device__ float g_gcnt[GMAX];
__device__ int   g_rowptr[NMAX + 1];
__device__ int   g_cursor[NMAX];          // zero at entry (invariant)
__device__ int   g_csrc[EMAX];            // pre-scaled: src*32 (uint2 rows)
__device__ float g_w2fc[129];             // [0..127]=W2_2@fc, [128]=b2_2.fc
__device__ __align__(16) __nv_bfloat16 g_wthi[6 * 16384];  // W^T hi planes
__device__ __align__(16) __nv_bfloat16 g_wtlo[6 * 16384];  // W^T lo planes

// ---------------- helpers ----------------
__device__ __forceinline__ uint32_t smem_u32(const void* p) {
    uint32_t a;
    asm("{ .reg .u64 t; cvta.to.shared.u64 t, %1; cvt.u32.u64 %0, t; }"
        : "=r"(a) : "l"(p));
    return a;
}

__device__ __forceinline__ void ldm4(uint32_t* a, uint32_t addr) {
    asm volatile("ldmatrix.sync.aligned.m8n8.x4.shared.b16 {%0,%1,%2,%3}, [%4];"
                 : "=r"(a[0]), "=r"(a[1]), "=r"(a[2]), "=r"(a[3]) : "r"(addr));
}

__device__ __forceinline__ void mma16816(float* c, const uint32_t* a,
                                         uint32_t b0, uint32_t b1) {
    asm volatile(
        "mma.sync.aligned.m16n8k16.row.col.f32.bf16.bf16.f32 "
        "{%0,%1,%2,%3}, {%4,%5,%6,%7}, {%8,%9}, {%0,%1,%2,%3};"
        : "+f"(c[0]), "+f"(c[1]), "+f"(c[2]), "+f"(c[3])
        : "r"(a[0]), "r"(a[1]), "r"(a[2]), "r"(a[3]), "r"(b0), "r"(b1));
}

__device__ __forceinline__ uint32_t pack_hi(float a, float b, float& ra, float& rb) {
    __nv_bfloat16 ha = __float2bfloat16(a), hb = __float2bfloat16(b);
    ra = a - __bfloat162float(ha);
    rb = b - __bfloat162float(hb);
    return ((uint32_t)__bfloat16_as_ushort(hb) << 16) | __bfloat16_as_ushort(ha);
}
__device__ __forceinline__ uint32_t pack_lo(float a, float b) {
    return ((uint32_t)__bfloat16_as_ushort(__float2bfloat16(b)) << 16) |
           __bfloat16_as_ushort(__float2bfloat16(a));
}

// ---------------- prep: weights + x->fp16 + edge count + w2fc ----------------
__global__ void prep_kernel(const float* __restrict__ Wa, const float* __restrict__ Wb,
                            const float* __restrict__ Wc, const float* __restrict__ Wd,
                            const float* __restrict__ We, const float* __restrict__ Wf,
                            __nv_bfloat16* __restrict__ hi, __nv_bfloat16* __restrict__ lo,
                            const float* __restrict__ x, __half* __restrict__ xh, int N,
                            const int* __restrict__ ei, int* __restrict__ cnt, int E,
                            const float* __restrict__ fcw, const float* __restrict__ b2f,
                            float* __restrict__ w2fc) {
    int t = blockIdx.x * blockDim.x + threadIdx.x;
    if (t < 6 * 16384) {
        int m = t >> 14;
        int i = t & 16383;
        int n = i >> 7, k = i & 127;
        const float* W = (m == 0) ? Wa : (m == 1) ? Wb : (m == 2) ? Wc
                       : (m == 3) ? Wd : (m == 4) ? We : Wf;
        float v = W[k * 128 + n];
        __nv_bfloat16 h = __float2bfloat16(v);
        hi[t] = h;
        lo[t] = __float2bfloat16(v - __bfloat162float(h));
    } else if (t < 6 * 16384 + 128) {
        int k = t - 6 * 16384;
        float s = 0.f;
        #pragma unroll 4
        for (int c = 0; c < 128; c++) s = fmaf(Wf[k * 128 + c], fcw[c], s);
        w2fc[k] = s;
    } else if (t == 6 * 16384 + 128) {
        float s = 0.f;
        for (int c = 0; c < 128; c++) s = fmaf(b2f[c], fcw[c], s);
        w2fc[128] = s;
    }
    // x -> fp16 (8 elements per thread)
    if (t < N * 16) {
        const float4* x4 = (const float4*)x;
        float4 a = x4[t * 2];
        float4 b = x4[t * 2 + 1];
        uint4 o;
        *(__half2*)&o.x = __floats2half2_rn(a.x, a.y);
        *(__half2*)&o.y = __floats2half2_rn(a.z, a.w);
        *(__half2*)&o.z = __floats2half2_rn(b.x, b.y);
        *(__half2*)&o.w = __floats2half2_rn(b.z, b.w);
        ((uint4*)xh)[t] = o;
    }
    if (t < E) atomicAdd(&cnt[ei[E + t]], 1);
}

// ---------------- CSR build ----------------
__global__ __launch_bounds__(1024) void scan_kernel(int* __restrict__ cursor,
                                                    int* __restrict__ rowptr, int N) {
    __shared__ int warpsums[32];
    __shared__ int s_carry;
    int tid = threadIdx.x, lane = tid & 31, wid = tid >> 5;
    if (tid == 0) s_carry = 0;
    __syncthreads();
    for (int base = 0; base < N; base += 1024) {
        int i = base + tid;
        int v = (i < N) ? cursor[i] : 0;
        int x = v;
        #pragma unroll
        for (int d = 1; d < 32; d <<= 1) {
            int y = __shfl_up_sync(0xffffffffu, x, d);
            if (lane >= d) x += y;
        }
        if (lane == 31) warpsums[wid] = x;
        __syncthreads();
        if (wid == 0) {
            int w = warpsums[lane];
            #pragma unroll
            for (int d = 1; d < 32; d <<= 1) {
                int y = __shfl_up_sync(0xffffffffu, w, d);
                if (lane >= d) w += y;
            }
            warpsums[lane] = w;
        }
        __syncthreads();
        int excl = x - v + ((wid > 0) ? warpsums[wid - 1] : 0) + s_carry;
        if (i < N) { rowptr[i] = excl; cursor[i] = excl; }
        __syncthreads();
        if (tid == 0) s_carry += warpsums[31];
        __syncthreads();
    }
    if (threadIdx.x == 0) rowptr[N] = s_carry;
}

__global__ void fill_kernel(const int* __restrict__ ei, int* __restrict__ cursor,
                            int* __restrict__ csrc, int E) {
    int t = blockIdx.x * blockDim.x + threadIdx.x;
    if (t < E) {
        int d = ei[E + t];
        int p = atomicAdd(&cursor[d], 1);
        csrc[p] = ei[t] << 5;   // pre-scale: row offset in uint2 units
    }
}

// final output + restore invariants (cursor/gsum/gcnt = 0)
__global__ void final_kernel(float* __restrict__ gsum, float* __restrict__ gcnt,
                             const float* __restrict__ fcb,
                             float* __restrict__ out, int G,
                             int* __restrict__ cursor, int N) {
    int i = blockIdx.x * blockDim.x + threadIdx.x;
    if (i < G) {
        out[i] = gsum[i] / fmaxf(gcnt[i], 1.0f) + fcb[0];
        gsum[i] = 0.f;
        gcnt[i] = 0.f;
    }
    if (i < N) cursor[i] = 0;
}

// ---------------- fused aggregate + MLP (persistent, 1024 thr) ----------------
#define SM_B1H 0
#define SM_B1L 34816
#define SM_B2H 69632
#define SM_B2L 104448
#define SM_AH  139264
#define SM_AL  174080
#define SM_SB1 208896
#define SM_SB2 209408
#define SM_SFW 209920
#define SM_SROW 210432
#define SM_TOTAL 210944

// split-bf16 GEMM: acc += Ah*Bh + Ah*Bl + Al*Bh  (per-warp 16x32 tile)
__device__ __forceinline__ void gemm_tile(
    const __nv_bfloat16* sAh, const __nv_bfloat16* sAl,
    const __nv_bfloat16* sBh, const __nv_bfloat16* sBl,
    float acc[4][4], int wr, int wc, int lane) {
    int arow = wr * 16 + (lane & 15);
    int acol = (lane >> 4) * 8;
    int bn = wc * 32 + ((lane >> 4) << 3) + (lane & 7);
    int bk = ((lane >> 3) & 1) << 3;
    const __nv_bfloat16* ah_base = sAh + arow * LDT + acol;
    const __nv_bfloat16* al_base = sAl + arow * LDT + acol;
    const __nv_bfloat16* bh_base = sBh + bn * LDT + bk;
    const __nv_bfloat16* bl_base = sBl + bn * LDT + bk;
    #pragma unroll
    for (int k0 = 0; k0 < 8; k0++) {
        uint32_t ah[4], al[4];
        ldm4(ah, smem_u32(ah_base + k0 * 16));
        ldm4(al, smem_u32(al_base + k0 * 16));
        #pragma unroll
        for (int p = 0; p < 2; p++) {
            int nfp = p * 2;
            uint32_t bh[4], bl[4];
            ldm4(bh, smem_u32(bh_base + nfp * 8 * LDT + k0 * 16));
            ldm4(bl, smem_u32(bl_base + nfp * 8 * LDT + k0 * 16));
            mma16816(acc[nfp],     ah, bh[0], bh[1]);
            mma16816(acc[nfp + 1], ah, bh[2], bh[3]);
            mma16816(acc[nfp],     ah, bl[0], bl[1]);
            mma16816(acc[nfp + 1], ah, bl[2], bl[3]);
            mma16816(acc[nfp],     al, bh[0], bh[1]);
            mma16816(acc[nfp + 1], al, bh[2], bh[3]);
        }
    }
}

// accumulate 4 neighbor rows (fp16; csrc holds pre-scaled row offsets)
#define GATHER4H(v, J)                                                    \
    do {                                                                  \
        int o0 = __ldg(&csrc[(J)]);                                       \
        int o1 = __ldg(&csrc[(J) + 1]);                                   \
        int o2 = __ldg(&csrc[(J) + 2]);                                   \
        int o3 = __ldg(&csrc[(J) + 3]);                                   \
        uint2 w0 = Xh[o0 + lane];                                         \
        uint2 w1 = Xh[o1 + lane];                                         \
        uint2 w2 = Xh[o2 + lane];                                         \
        uint2 w3 = Xh[o3 + lane];                                         \
        float2 f;                                                         \
        f = __half22float2(*(__half2*)&w0.x); v.x += f.x; v.y += f.y;     \
        f = __half22float2(*(__half2*)&w0.y); v.z += f.x; v.w += f.y;     \
        f = __half22float2(*(__half2*)&w1.x); v.x += f.x; v.y += f.y;     \
        f = __half22float2(*(__half2*)&w1.y); v.z += f.x; v.w += f.y;     \
        f = __half22float2(*(__half2*)&w2.x); v.x += f.x; v.y += f.y;     \
        f = __half22float2(*(__half2*)&w2.y); v.z += f.x; v.w += f.y;     \
        f = __half22float2(*(__half2*)&w3.x); v.x += f.x; v.y += f.y;     \
        f = __half22float2(*(__half2*)&w3.y); v.z += f.x; v.w += f.y;     \
    } while (0)

__global__ __launch_bounds__(1024, 1) void mlp_kernel(
    const __half* __restrict__ X,
    const int* __restrict__ rowptr, const int* __restrict__ csrc,
    __half* __restrict__ H,
    const __nv_bfloat16* __restrict__ W1h, const __nv_bfloat16* __restrict__ W1l,
    const __nv_bfloat16* __restrict__ W2h, const __nv_bfloat16* __restrict__ W2l,
    const float* __restrict__ b1, const float* __restrict__ b2,
    const float* __restrict__ epsp,
    int n, int ntiles, int relu_out, int pool,
    const int* __restrict__ batch, const float* __restrict__ w2fc,
    float* __restrict__ gsum, float* __restrict__ gcnt) {
    extern __shared__ char sm[];
    __nv_bfloat16* sB1h = (__nv_bfloat16*)(sm + SM_B1H);
    __nv_bfloat16* sB1l = (__nv_bfloat16*)(sm + SM_B1L);
    __nv_bfloat16* sB2h = (__nv_bfloat16*)(sm + SM_B2H);
    __nv_bfloat16* sB2l = (__nv_bfloat16*)(sm + SM_B2L);
    __nv_bfloat16* sAh  = (__nv_bfloat16*)(sm + SM_AH);
    __nv_bfloat16* sAl  = (__nv_bfloat16*)(sm + SM_AL);
    float* sb1  = (float*)(sm + SM_SB1);
    float* sb2  = (float*)(sm + SM_SB2);
    float* sfw  = (float*)(sm + SM_SFW);   // w2fc for pool layer
    float* srow = (float*)(sm + SM_SROW);

    int tid = threadIdx.x;
    int lane = tid & 31;
    int wid = tid >> 5;           // 0..31
    int wr = wid & 7;             // row group (16 rows)
    int wc = wid >> 3;            // col group (32 cols)

    if (tid < 128) {
        sb1[tid] = b1[tid];
        sb2[tid] = b2[tid];
        sfw[tid] = w2fc[tid];
    }

    // load weight planes once (persistent); pool layer skips B2
    {
        const uint4* p1h = (const uint4*)W1h;
        const uint4* p1l = (const uint4*)W1l;
        const uint4* p2h = (const uint4*)W2h;
        const uint4* p2l = (const uint4*)W2l;
        for (int i = tid; i < 2048; i += 1024) {
            int r = i >> 4, c = (i & 15) * 8;
            int d = r * LDT + c;
            *(uint4*)&sB1h[d] = p1h[i];
            *(uint4*)&sB1l[d] = p1l[i];
            if (!pool) {
                *(uint4*)&sB2h[d] = p2h[i];
                *(uint4*)&sB2l[d] = p2l[i];
            }
        }
    }

    float s = 1.0f + __ldg(epsp);
    float bconst = __ldg(&w2fc[128]);
    const uint2* Xh = (const uint2*)X;

    for (int tile = blockIdx.x; tile < ntiles; tile += gridDim.x) {
        int row0 = tile * 128;
        if (tid < 128) srow[tid] = 0.f;

        // gather: A = (1+eps)*X[row] + sum_nbrs X[j]; 2 rows per warp iter
        for (int r2 = wid; r2 < 64; r2 += 32) {
            int rA = r2, rB = r2 + 64;
            int grA = row0 + rA, grB = row0 + rB;
            float4 va = make_float4(0.f, 0.f, 0.f, 0.f);
            float4 vb = make_float4(0.f, 0.f, 0.f, 0.f);
            int ja = 0, ea = 0, jb = 0, eb = 0;
            if (grA < n) {
                uint2 w = Xh[grA * 32 + lane];
                float2 f0 = __half22float2(*(__half2*)&w.x);
                float2 f1 = __half22float2(*(__half2*)&w.y);
                va.x = s * f0.x; va.y = s * f0.y;
                va.z = s * f1.x; va.w = s * f1.y;
                ja = __ldg(&rowptr[grA]); ea = __ldg(&rowptr[grA + 1]);
            }
            if (grB < n) {
                uint2 w = Xh[grB * 32 + lane];
                float2 f0 = __half22float2(*(__half2*)&w.x);
                float2 f1 = __half22float2(*(__half2*)&w.y);
                vb.x = s * f0.x; vb.y = s * f0.y;
                vb.z = s * f1.x; vb.w = s * f1.y;
                jb = __ldg(&rowptr[grB]); eb = __ldg(&rowptr[grB + 1]);
            }
            while (ja + 4 <= ea && jb + 4 <= eb) {
                GATHER4H(va, ja);
                GATHER4H(vb, jb);
                ja += 4; jb += 4;
            }
            for (; ja + 4 <= ea; ja += 4) GATHER4H(va, ja);
            for (; ja < ea; ja++) {
                int o0 = __ldg(&csrc[ja]);
                uint2 w = Xh[o0 + lane];
                float2 f0 = __half22float2(*(__half2*)&w.x);
                float2 f1 = __half22float2(*(__half2*)&w.y);
                va.x += f0.x; va.y += f0.y; va.z += f1.x; va.w += f1.y;
            }
            for (; jb + 4 <= eb; jb += 4) GATHER4H(vb, jb);
            for (; jb < eb; jb++) {
                int o0 = __ldg(&csrc[jb]);
                uint2 w = Xh[o0 + lane];
                float2 f0 = __half22float2(*(__half2*)&w.x);
                float2 f1 = __half22float2(*(__half2*)&w.y);
                vb.x += f0.x; vb.y += f0.y; vb.z += f1.x; vb.w += f1.y;
            }
            float q0, q1, q2, q3;
            uint2 hi2, lo2;
            hi2.x = pack_hi(va.x, va.y, q0, q1);
            hi2.y = pack_hi(va.z, va.w, q2, q3);
            lo2.x = pack_lo(q0, q1);
            lo2.y = pack_lo(q2, q3);
            int d = rA * LDT + lane * 4;
            *(uint2*)&sAh[d] = hi2;
            *(uint2*)&sAl[d] = lo2;
            hi2.x = pack_hi(vb.x, vb.y, q0, q1);
            hi2.y = pack_hi(vb.z, vb.w, q2, q3);
            lo2.x = pack_lo(q0, q1);
            lo2.y = pack_lo(q2, q3);
            d = rB * LDT + lane * 4;
            *(uint2*)&sAh[d] = hi2;
            *(uint2*)&sAl[d] = lo2;
        }
        __syncthreads();

        float acc[4][4];
        #pragma unroll
        for (int j = 0; j < 4; j++)
            #pragma unroll
            for (int q = 0; q < 4; q++) acc[j][q] = 0.f;

        // GEMM1
        gemm_tile(sAh, sAl, sB1h, sB1l, acc, wr, wc, lane);

        if (pool) {
            // layer 2: h.fc = ReLU(acc+b1) @ w2fc (+ bconst per node)
            int r = wr * 16 + (lane >> 2);
            float d0 = 0.f, d1 = 0.f;
            #pragma unroll
            for (int nf = 0; nf < 4; nf++) {
                int c = wc * 32 + nf * 8 + (lane & 3) * 2;
                float* a = acc[nf];
                d0 = fmaf(fmaxf(a[0] + sb1[c], 0.f), sfw[c], d0);
                d0 = fmaf(fmaxf(a[1] + sb1[c + 1], 0.f), sfw[c + 1], d0);
                d1 = fmaf(fmaxf(a[2] + sb1[c], 0.f), sfw[c], d1);
                d1 = fmaf(fmaxf(a[3] + sb1[c + 1], 0.f), sfw[c + 1], d1);
            }
            atomicAdd(&srow[r], d0);
            atomicAdd(&srow[r + 8], d1);
            __syncthreads();
            if (tid < 128) {
                int gr = row0 + tid;
                if (gr < n) {
                    int g = batch[gr];
                    atomicAdd(&gsum[g], srow[tid] + bconst);
                    atomicAdd(&gcnt[g], 1.0f);
                }
            }
            __syncthreads();
            continue;
        }

        __syncthreads();  // all reads of sA done before overwrite

        // epilogue1: T = ReLU(acc + b1) -> split back into sA planes
        {
            int r = wr * 16 + (lane >> 2);
            #pragma unroll
            for (int nf = 0; nf < 4; nf++) {
                int c = wc * 32 + nf * 8 + (lane & 3) * 2;
                float* a = acc[nf];
                float v0 = fmaxf(a[0] + sb1[c], 0.f);
                float v1 = fmaxf(a[1] + sb1[c + 1], 0.f);
                float v2 = fmaxf(a[2] + sb1[c], 0.f);
                float v3 = fmaxf(a[3] + sb1[c + 1], 0.f);
                float q0, q1;
                uint32_t h = pack_hi(v0, v1, q0, q1);
                *(uint32_t*)&sAh[r * LDT + c] = h;
                *(uint32_t*)&sAl[r * LDT + c] = pack_lo(q0, q1);
                h = pack_hi(v2, v3, q0, q1);
                *(uint32_t*)&sAh[(r + 8) * LDT + c] = h;
                *(uint32_t*)&sAl[(r + 8) * LDT + c] = pack_lo(q0, q1);
            }
        }
        __syncthreads();

        #pragma unroll
        for (int j = 0; j < 4; j++)
            #pragma unroll
            for (int q = 0; q < 4; q++) acc[j][q] = 0.f;

        // GEMM2
        gemm_tile(sAh, sAl, sB2h, sB2l, acc, wr, wc, lane);

        // epilogue2: out = acc + b2 (+ReLU) -> H (fp16)
        {
            int r = wr * 16 + (lane >> 2);
            int gr0 = row0 + r, gr1 = gr0 + 8;
            #pragma unroll
            for (int nf = 0; nf < 4; nf++) {
                int c = wc * 32 + nf * 8 + (lane & 3) * 2;
                float* a = acc[nf];
                float v0 = a[0] + sb2[c], v1 = a[1] + sb2[c + 1];
                float v2 = a[2] + sb2[c], v3 = a[3] + sb2[c + 1];
                if (relu_out) {
                    v0 = fmaxf(v0, 0.f); v1 = fmaxf(v1, 0.f);
                    v2 = fmaxf(v2, 0.f); v3 = fmaxf(v3, 0.f);
                }
                if (gr0 < n)
                    *(__half2*)&H[(size_t)gr0 * 128 + c] = __floats2half2_rn(v0, v1);
                if (gr1 < n)
                    *(__half2*)&H[(size_t)gr1 * 128 + c] = __floats2half2_rn(v2, v3);
            }
        }
        __syncthreads();  // protect sA before next tile's gather
    }
}

// ---------------- host launcher ----------------
extern "C" void kernel_launch(void* const* d_in, const int* in_sizes, int n_in,
                              void* d_out, int out_size) {
    const float* x     = (const float*)d_in[0];
    const int*   ei    = (const int*)d_in[1];
    const int*   batch = (const int*)d_in[2];
    const float* W1s[3] = {(const float*)d_in[3],  (const float*)d_in[8],  (const float*)d_in[13]};
    const float* b1s[3] = {(const float*)d_in[4],  (const float*)d_in[9],  (const float*)d_in[14]};
    const float* W2s[3] = {(const float*)d_in[5],  (const float*)d_in[10], (const float*)d_in[15]};
    const float* b2s[3] = {(const float*)d_in[6],  (const float*)d_in[11], (const float*)d_in[16]};
    const float* epss[3]= {(const float*)d_in[7],  (const float*)d_in[12], (const float*)d_in[17]};
    const float* fcw   = (const float*)d_in[18];
    const float* fcb   = (const float*)d_in[19];

    int N = in_sizes[2];
    int E = in_sizes[1] / 2;
    int G = out_size;

    float *gsum, *gcnt, *w2fc;
    __half *xh, *bufA, *bufB;
    int *rowptr, *cursor, *csrc;
    __nv_bfloat16 *wthi, *wtlo;
    cudaGetSymbolAddress((void**)&xh,   g_xh);
    cudaGetSymbolAddress((void**)&bufA, g_bufA);
    cudaGetSymbolAddress((void**)&bufB, g_bufB);
    cudaGetSymbolAddress((void**)&gsum, g_gsum);
    cudaGetSymbolAddress((void**)&gcnt, g_gcnt);
    cudaGetSymbolAddress((void**)&rowptr, g_rowptr);
    cudaGetSymbolAddress((void**)&cursor, g_cursor);
    cudaGetSymbolAddress((void**)&csrc, g_csrc);
    cudaGetSymbolAddress((void**)&w2fc, g_w2fc);
    cudaGetSymbolAddress((void**)&wthi, g_wthi);
    cudaGetSymbolAddress((void**)&wtlo, g_wtlo);

    cudaFuncSetAttribute(mlp_kernel, cudaFuncAttributeMaxDynamicSharedMemorySize, SM_TOTAL);

    int prep_threads = E;
    if (N * 16 > prep_threads) prep_threads = N * 16;
    if (6 * 16384 + 129 > prep_threads) prep_threads = 6 * 16384 + 129;
    // 1: weight transform + x->fp16 + edge count + w2fc (cursor==0 at entry)
    prep_kernel<<<(prep_threads + 255) / 256, 256>>>(
        W1s[0], W2s[0], W1s[1], W2s[1], W1s[2], W2s[2],
        wthi, wtlo, x, xh, N, ei, cursor, E, fcw, b2s[2], w2fc);
    // 2-3: CSR scan + fill (pre-scaled offsets)
    scan_kernel<<<1, 1024>>>(cursor, rowptr, N);
    fill_kernel<<<(E + 255) / 256, 256>>>(ei, cursor, csrc, E);

    // 4-6: ping-pong layers (fp16 everywhere); layer2 pools (no GEMM2)
    const __half* ins[3]  = {xh, bufA, bufB};
    __half*       outs[3] = {bufA, bufB, bufA /* unused (pool) */};
    int ntiles = (N + 127) / 128;
    for (int l = 0; l < 3; l++) {
        mlp_kernel<<<148, 1024, SM_TOTAL>>>(
            ins[l], rowptr, csrc, outs[l],
            wthi + (2 * l) * 16384, wtlo + (2 * l) * 16384,
            wthi + (2 * l + 1) * 16384, wtlo + (2 * l + 1) * 16384,
            b1s[l], b2s[l], epss[l],
            N, ntiles, (l < 2) ? 1 : 0, (l == 2) ? 1 : 0,
            batch, w2fc, gsum, gcnt);
    }
    // 7: output + restore invariants
    final_kernel<<<(N + 255) / 256, 256>>>(gsum, gcnt, fcb, (float*)d_out, G, cursor, N);
}

// round 13
// speedup vs baseline: 3.3357x; 1.1282x over previous
#include <cuda_runtime.h>
#include <cuda_bf16.h>
#include <cuda_fp16.h>
#include <cstdint>

// ---------------------------------------------------------------------------
// GINRegressor on GB300: CSR gather (fp16) fused into 2-product fp16 tensor
// MLP: D = A*Bh + A*Bl with A=fp16(gather sum), Bh=fp16(W), Bl=fp16(W-Bh).
// 1024 thr/CTA persistent; ping-pong fp16 buffers; pre-scaled CSR offsets;
// layer2 GEMM2 folded to GEMV (w2fc = W2_2 @ fc_w).
// Launch order: prep(1), scan(2), fill(3), mlp0(4), mlp1(5), mlp2(6), final(7).
// Invariant: cursor/gsum/gcnt zero at entry (final_kernel restores).
// ---------------------------------------------------------------------------

#define NMAX 50000
#define EMAX 800000
#define GMAX 500
#define LDT 136  // padded smem tile stride (fp16 elems) -> conflict-free

__device__ __half g_xh[NMAX * 128];       // fp16 copy of input x
__device__ __half g_bufA[NMAX * 128];
__device__ __half g_bufB[NMAX * 128];
__device__ float g_gsum[GMAX];
__device__ float g_gcnt[GMAX];
__device__ int   g_rowptr[NMAX + 1];
__device__ int   g_cursor[NMAX];          // zero at entry (invariant)
__device__ int   g_csrc[EMAX];            // pre-scaled: src*32 (uint2 rows)
__device__ float g_w2fc[129];             // [0..127]=W2_2@fc, [128]=b2_2.fc
__device__ __align__(16) __half g_wthi[6 * 16384];  // W^T fp16-hi planes
__device__ __align__(16) __half g_wtlo[6 * 16384];  // W^T fp16-lo planes

// ---------------- helpers ----------------
__device__ __forceinline__ uint32_t smem_u32(const void* p) {
    uint32_t a;
    asm("{ .reg .u64 t; cvta.to.shared.u64 t, %1; cvt.u32.u64 %0, t; }"
        : "=r"(a) : "l"(p));
    return a;
}

__device__ __forceinline__ void ldm4(uint32_t* a, uint32_t addr) {
    asm volatile("ldmatrix.sync.aligned.m8n8.x4.shared.b16 {%0,%1,%2,%3}, [%4];"
                 : "=r"(a[0]), "=r"(a[1]), "=r"(a[2]), "=r"(a[3]) : "r"(addr));
}

__device__ __forceinline__ void mma16816(float* c, const uint32_t* a,
                                         uint32_t b0, uint32_t b1) {
    asm volatile(
        "mma.sync.aligned.m16n8k16.row.col.f32.f16.f16.f32 "
        "{%0,%1,%2,%3}, {%4,%5,%6,%7}, {%8,%9}, {%0,%1,%2,%3};"
        : "+f"(c[0]), "+f"(c[1]), "+f"(c[2]), "+f"(c[3])
        : "r"(a[0]), "r"(a[1]), "r"(a[2]), "r"(a[3]), "r"(b0), "r"(b1));
}

// ---------------- prep: weights + x->fp16 + edge count + w2fc ----------------
__global__ void prep_kernel(const float* __restrict__ Wa, const float* __restrict__ Wb,
                            const float* __restrict__ Wc, const float* __restrict__ Wd,
                            const float* __restrict__ We, const float* __restrict__ Wf,
                            __half* __restrict__ hi, __half* __restrict__ lo,
                            const float* __restrict__ x, __half* __restrict__ xh, int N,
                            const int* __restrict__ ei, int* __restrict__ cnt, int E,
                            const float* __restrict__ fcw, const float* __restrict__ b2f,
                            float* __restrict__ w2fc) {
    int t = blockIdx.x * blockDim.x + threadIdx.x;
    if (t < 6 * 16384) {
        int m = t >> 14;
        int i = t & 16383;
        int n = i >> 7, k = i & 127;
        const float* W = (m == 0) ? Wa : (m == 1) ? Wb : (m == 2) ? Wc
                       : (m == 3) ? Wd : (m == 4) ? We : Wf;
        float v = W[k * 128 + n];
        __half h = __float2half_rn(v);
        hi[t] = h;
        lo[t] = __float2half_rn(v - __half2float(h));
    } else if (t < 6 * 16384 + 128) {
        int k = t - 6 * 16384;
        float s = 0.f;
        #pragma unroll 4
        for (int c = 0; c < 128; c++) s = fmaf(Wf[k * 128 + c], fcw[c], s);
        w2fc[k] = s;
    } else if (t == 6 * 16384 + 128) {
        float s = 0.f;
        for (int c = 0; c < 128; c++) s = fmaf(b2f[c], fcw[c], s);
        w2fc[128] = s;
    }
    // x -> fp16 (8 elements per thread)
    if (t < N * 16) {
        const float4* x4 = (const float4*)x;
        float4 a = x4[t * 2];
        float4 b = x4[t * 2 + 1];
        uint4 o;
        *(__half2*)&o.x = __floats2half2_rn(a.x, a.y);
        *(__half2*)&o.y = __floats2half2_rn(a.z, a.w);
        *(__half2*)&o.z = __floats2half2_rn(b.x, b.y);
        *(__half2*)&o.w = __floats2half2_rn(b.z, b.w);
        ((uint4*)xh)[t] = o;
    }
    if (t < E) atomicAdd(&cnt[ei[E + t]], 1);
}

// ---------------- CSR build ----------------
__global__ __launch_bounds__(1024) void scan_kernel(int* __restrict__ cursor,
                                                    int* __restrict__ rowptr, int N) {
    __shared__ int warpsums[32];
    __shared__ int s_carry;
    int tid = threadIdx.x, lane = tid & 31, wid = tid >> 5;
    if (tid == 0) s_carry = 0;
    __syncthreads();
    for (int base = 0; base < N; base += 1024) {
        int i = base + tid;
        int v = (i < N) ? cursor[i] : 0;
        int x = v;
        #pragma unroll
        for (int d = 1; d < 32; d <<= 1) {
            int y = __shfl_up_sync(0xffffffffu, x, d);
            if (lane >= d) x += y;
        }
        if (lane == 31) warpsums[wid] = x;
        __syncthreads();
        if (wid == 0) {
            int w = warpsums[lane];
            #pragma unroll
            for (int d = 1; d < 32; d <<= 1) {
                int y = __shfl_up_sync(0xffffffffu, w, d);
                if (lane >= d) w += y;
            }
            warpsums[lane] = w;
        }
        __syncthreads();
        int excl = x - v + ((wid > 0) ? warpsums[wid - 1] : 0) + s_carry;
        if (i < N) { rowptr[i] = excl; cursor[i] = excl; }
        __syncthreads();
        if (tid == 0) s_carry += warpsums[31];
        __syncthreads();
    }
    if (threadIdx.x == 0) rowptr[N] = s_carry;
}

__global__ void fill_kernel(const int* __restrict__ ei, int* __restrict__ cursor,
                            int* __restrict__ csrc, int E) {
    int t = blockIdx.x * blockDim.x + threadIdx.x;
    if (t < E) {
        int d = ei[E + t];
        int p = atomicAdd(&cursor[d], 1);
        csrc[p] = ei[t] << 5;   // pre-scale: row offset in uint2 units
    }
}

// final output + restore invariants (cursor/gsum/gcnt = 0)
__global__ void final_kernel(float* __restrict__ gsum, float* __restrict__ gcnt,
                             const float* __restrict__ fcb,
                             float* __restrict__ out, int G,
                             int* __restrict__ cursor, int N) {
    int i = blockIdx.x * blockDim.x + threadIdx.x;
    if (i < G) {
        out[i] = gsum[i] / fmaxf(gcnt[i], 1.0f) + fcb[0];
        gsum[i] = 0.f;
        gcnt[i] = 0.f;
    }
    if (i < N) cursor[i] = 0;
}

// ---------------- fused aggregate + MLP (persistent, 1024 thr) ----------------
#define SM_B1H 0
#define SM_B1L 34816
#define SM_B2H 69632
#define SM_B2L 104448
#define SM_A   139264   // single fp16 A plane (also T after epilogue1)
#define SM_SB1 174080
#define SM_SB2 174592
#define SM_SFW 175104
#define SM_SROW 175616
#define SM_TOTAL 176128

// 2-product fp16 GEMM: acc += A*Bh + A*Bl  (per-warp 16x32 tile)
__device__ __forceinline__ void gemm_tile(
    const __half* sA, const __half* sBh, const __half* sBl,
    float acc[4][4], int wr, int wc, int lane) {
    int arow = wr * 16 + (lane & 15);
    int acol = (lane >> 4) * 8;
    int bn = wc * 32 + ((lane >> 4) << 3) + (lane & 7);
    int bk = ((lane >> 3) & 1) << 3;
    const __half* a_base  = sA  + arow * LDT + acol;
    const __half* bh_base = sBh + bn * LDT + bk;
    const __half* bl_base = sBl + bn * LDT + bk;
    #pragma unroll
    for (int k0 = 0; k0 < 8; k0++) {
        uint32_t a[4];
        ldm4(a, smem_u32(a_base + k0 * 16));
        #pragma unroll
        for (int p = 0; p < 2; p++) {
            int nfp = p * 2;
            uint32_t bh[4], bl[4];
            ldm4(bh, smem_u32(bh_base + nfp * 8 * LDT + k0 * 16));
            ldm4(bl, smem_u32(bl_base + nfp * 8 * LDT + k0 * 16));
            mma16816(acc[nfp],     a, bh[0], bh[1]);
            mma16816(acc[nfp + 1], a, bh[2], bh[3]);
            mma16816(acc[nfp],     a, bl[0], bl[1]);
            mma16816(acc[nfp + 1], a, bl[2], bl[3]);
        }
    }
}

// accumulate 4 neighbor rows (fp16; csrc holds pre-scaled row offsets)
#define GATHER4H(v, J)                                                    \
    do {                                                                  \
        int o0 = __ldg(&csrc[(J)]);                                       \
        int o1 = __ldg(&csrc[(J) + 1]);                                   \
        int o2 = __ldg(&csrc[(J) + 2]);                                   \
        int o3 = __ldg(&csrc[(J) + 3]);                                   \
        uint2 w0 = Xh[o0 + lane];                                         \
        uint2 w1 = Xh[o1 + lane];                                         \
        uint2 w2 = Xh[o2 + lane];                                         \
        uint2 w3 = Xh[o3 + lane];                                         \
        float2 f;                                                         \
        f = __half22float2(*(__half2*)&w0.x); v.x += f.x; v.y += f.y;     \
        f = __half22float2(*(__half2*)&w0.y); v.z += f.x; v.w += f.y;     \
        f = __half22float2(*(__half2*)&w1.x); v.x += f.x; v.y += f.y;     \
        f = __half22float2(*(__half2*)&w1.y); v.z += f.x; v.w += f.y;     \
        f = __half22float2(*(__half2*)&w2.x); v.x += f.x; v.y += f.y;     \
        f = __half22float2(*(__half2*)&w2.y); v.z += f.x; v.w += f.y;     \
        f = __half22float2(*(__half2*)&w3.x); v.x += f.x; v.y += f.y;     \
        f = __half22float2(*(__half2*)&w3.y); v.z += f.x; v.w += f.y;     \
    } while (0)

__global__ __launch_bounds__(1024, 1) void mlp_kernel(
    const __half* __restrict__ X,
    const int* __restrict__ rowptr, const int* __restrict__ csrc,
    __half* __restrict__ H,
    const __half* __restrict__ W1h, const __half* __restrict__ W1l,
    const __half* __restrict__ W2h, const __half* __restrict__ W2l,
    const float* __restrict__ b1, const float* __restrict__ b2,
    const float* __restrict__ epsp,
    int n, int ntiles, int relu_out, int pool,
    const int* __restrict__ batch, const float* __restrict__ w2fc,
    float* __restrict__ gsum, float* __restrict__ gcnt) {
    extern __shared__ char sm[];
    __half* sB1h = (__half*)(sm + SM_B1H);
    __half* sB1l = (__half*)(sm + SM_B1L);
    __half* sB2h = (__half*)(sm + SM_B2H);
    __half* sB2l = (__half*)(sm + SM_B2L);
    __half* sA   = (__half*)(sm + SM_A);
    float* sb1  = (float*)(sm + SM_SB1);
    float* sb2  = (float*)(sm + SM_SB2);
    float* sfw  = (float*)(sm + SM_SFW);   // w2fc for pool layer
    float* srow = (float*)(sm + SM_SROW);

    int tid = threadIdx.x;
    int lane = tid & 31;
    int wid = tid >> 5;           // 0..31
    int wr = wid & 7;             // row group (16 rows)
    int wc = wid >> 3;            // col group (32 cols)

    if (tid < 128) {
        sb1[tid] = b1[tid];
        sb2[tid] = b2[tid];
        sfw[tid] = w2fc[tid];
    }

    // load weight planes once (persistent); pool layer skips B2
    {
        const uint4* p1h = (const uint4*)W1h;
        const uint4* p1l = (const uint4*)W1l;
        const uint4* p2h = (const uint4*)W2h;
        const uint4* p2l = (const uint4*)W2l;
        for (int i = tid; i < 2048; i += 1024) {
            int r = i >> 4, c = (i & 15) * 8;
            int d = r * LDT + c;
            *(uint4*)&sB1h[d] = p1h[i];
            *(uint4*)&sB1l[d] = p1l[i];
            if (!pool) {
                *(uint4*)&sB2h[d] = p2h[i];
                *(uint4*)&sB2l[d] = p2l[i];
            }
        }
    }

    float s = 1.0f + __ldg(epsp);
    float bconst = __ldg(&w2fc[128]);
    const uint2* Xh = (const uint2*)X;

    for (int tile = blockIdx.x; tile < ntiles; tile += gridDim.x) {
        int row0 = tile * 128;
        if (tid < 128) srow[tid] = 0.f;

        // gather: A = (1+eps)*X[row] + sum_nbrs X[j]; 2 rows per warp iter
        for (int r2 = wid; r2 < 64; r2 += 32) {
            int rA = r2, rB = r2 + 64;
            int grA = row0 + rA, grB = row0 + rB;
            float4 va = make_float4(0.f, 0.f, 0.f, 0.f);
            float4 vb = make_float4(0.f, 0.f, 0.f, 0.f);
            int ja = 0, ea = 0, jb = 0, eb = 0;
            if (grA < n) {
                uint2 w = Xh[grA * 32 + lane];
                float2 f0 = __half22float2(*(__half2*)&w.x);
                float2 f1 = __half22float2(*(__half2*)&w.y);
                va.x = s * f0.x; va.y = s * f0.y;
                va.z = s * f1.x; va.w = s * f1.y;
                ja = __ldg(&rowptr[grA]); ea = __ldg(&rowptr[grA + 1]);
            }
            if (grB < n) {
                uint2 w = Xh[grB * 32 + lane];
                float2 f0 = __half22float2(*(__half2*)&w.x);
                float2 f1 = __half22float2(*(__half2*)&w.y);
                vb.x = s * f0.x; vb.y = s * f0.y;
                vb.z = s * f1.x; vb.w = s * f1.y;
                jb = __ldg(&rowptr[grB]); eb = __ldg(&rowptr[grB + 1]);
            }
            while (ja + 4 <= ea && jb + 4 <= eb) {
                GATHER4H(va, ja);
                GATHER4H(vb, jb);
                ja += 4; jb += 4;
            }
            for (; ja + 4 <= ea; ja += 4) GATHER4H(va, ja);
            for (; ja < ea; ja++) {
                int o0 = __ldg(&csrc[ja]);
                uint2 w = Xh[o0 + lane];
                float2 f0 = __half22float2(*(__half2*)&w.x);
                float2 f1 = __half22float2(*(__half2*)&w.y);
                va.x += f0.x; va.y += f0.y; va.z += f1.x; va.w += f1.y;
            }
            for (; jb + 4 <= eb; jb += 4) GATHER4H(vb, jb);
            for (; jb < eb; jb++) {
                int o0 = __ldg(&csrc[jb]);
                uint2 w = Xh[o0 + lane];
                float2 f0 = __half22float2(*(__half2*)&w.x);
                float2 f1 = __half22float2(*(__half2*)&w.y);
                vb.x += f0.x; vb.y += f0.y; vb.z += f1.x; vb.w += f1.y;
            }
            uint2 o;
            *(__half2*)&o.x = __floats2half2_rn(va.x, va.y);
            *(__half2*)&o.y = __floats2half2_rn(va.z, va.w);
            *(uint2*)&sA[rA * LDT + lane * 4] = o;
            *(__half2*)&o.x = __floats2half2_rn(vb.x, vb.y);
            *(__half2*)&o.y = __floats2half2_rn(vb.z, vb.w);
            *(uint2*)&sA[rB * LDT + lane * 4] = o;
        }
        __syncthreads();

        float acc[4][4];
        #pragma unroll
        for (int j = 0; j < 4; j++)
            #pragma unroll
            for (int q = 0; q < 4; q++) acc[j][q] = 0.f;

        // GEMM1
        gemm_tile(sA, sB1h, sB1l, acc, wr, wc, lane);

        if (pool) {
            // layer 2: h.fc = ReLU(acc+b1) @ w2fc (+ bconst per node)
            int r = wr * 16 + (lane >> 2);
            float d0 = 0.f, d1 = 0.f;
            #pragma unroll
            for (int nf = 0; nf < 4; nf++) {
                int c = wc * 32 + nf * 8 + (lane & 3) * 2;
                float* a = acc[nf];
                d0 = fmaf(fmaxf(a[0] + sb1[c], 0.f), sfw[c], d0);
                d0 = fmaf(fmaxf(a[1] + sb1[c + 1], 0.f), sfw[c + 1], d0);
                d1 = fmaf(fmaxf(a[2] + sb1[c], 0.f), sfw[c], d1);
                d1 = fmaf(fmaxf(a[3] + sb1[c + 1], 0.f), sfw[c + 1], d1);
            }
            atomicAdd(&srow[r], d0);
            atomicAdd(&srow[r + 8], d1);
            __syncthreads();
            if (tid < 128) {
                int gr = row0 + tid;
                if (gr < n) {
                    int g = batch[gr];
                    atomicAdd(&gsum[g], srow[tid] + bconst);
                    atomicAdd(&gcnt[g], 1.0f);
                }
            }
            __syncthreads();
            continue;
        }

        __syncthreads();  // all reads of sA done before overwrite

        // epilogue1: T = ReLU(acc + b1) -> fp16 into sA
        {
            int r = wr * 16 + (lane >> 2);
            #pragma unroll
            for (int nf = 0; nf < 4; nf++) {
                int c = wc * 32 + nf * 8 + (lane & 3) * 2;
                float* a = acc[nf];
                float v0 = fmaxf(a[0] + sb1[c], 0.f);
                float v1 = fmaxf(a[1] + sb1[c + 1], 0.f);
                float v2 = fmaxf(a[2] + sb1[c], 0.f);
                float v3 = fmaxf(a[3] + sb1[c + 1], 0.f);
                *(__half2*)&sA[r * LDT + c] = __floats2half2_rn(v0, v1);
                *(__half2*)&sA[(r + 8) * LDT + c] = __floats2half2_rn(v2, v3);
            }
        }
        __syncthreads();

        #pragma unroll
        for (int j = 0; j < 4; j++)
            #pragma unroll
            for (int q = 0; q < 4; q++) acc[j][q] = 0.f;

        // GEMM2
        gemm_tile(sA, sB2h, sB2l, acc, wr, wc, lane);

        // epilogue2: out = acc + b2 (+ReLU) -> H (fp16)
        {
            int r = wr * 16 + (lane >> 2);
            int gr0 = row0 + r, gr1 = gr0 + 8;
            #pragma unroll
            for (int nf = 0; nf < 4; nf++) {
                int c = wc * 32 + nf * 8 + (lane & 3) * 2;
                float* a = acc[nf];
                float v0 = a[0] + sb2[c], v1 = a[1] + sb2[c + 1];
                float v2 = a[2] + sb2[c], v3 = a[3] + sb2[c + 1];
                if (relu_out) {
                    v0 = fmaxf(v0, 0.f); v1 = fmaxf(v1, 0.f);
                    v2 = fmaxf(v2, 0.f); v3 = fmaxf(v3, 0.f);
                }
                if (gr0 < n)
                    *(__half2*)&H[(size_t)gr0 * 128 + c] = __floats2half2_rn(v0, v1);
                if (gr1 < n)
                    *(__half2*)&H[(size_t)gr1 * 128 + c] = __floats2half2_rn(v2, v3);
            }
        }
        __syncthreads();  // protect sA before next tile's gather
    }
}

// ---------------- host launcher ----------------
extern "C" void kernel_launch(void* const* d_in, const int* in_sizes, int n_in,
                              void* d_out, int out_size) {
    const float* x     = (const float*)d_in[0];
    const int*   ei    = (const int*)d_in[1];
    const int*   batch = (const int*)d_in[2];
    const float* W1s[3] = {(const float*)d_in[3],  (const float*)d_in[8],  (const float*)d_in[13]};
    const float* b1s[3] = {(const float*)d_in[4],  (const float*)d_in[9],  (const float*)d_in[14]};
    const float* W2s[3] = {(const float*)d_in[5],  (const float*)d_in[10], (const float*)d_in[15]};
    const float* b2s[3] = {(const float*)d_in[6],  (const float*)d_in[11], (const float*)d_in[16]};
    const float* epss[3]= {(const float*)d_in[7],  (const float*)d_in[12], (const float*)d_in[17]};
    const float* fcw   = (const float*)d_in[18];
    const float* fcb   = (const float*)d_in[19];

    int N = in_sizes[2];
    int E = in_sizes[1] / 2;
    int G = out_size;

    float *gsum, *gcnt, *w2fc;
    __half *xh, *bufA, *bufB, *wthi, *wtlo;
    int *rowptr, *cursor, *csrc;
    cudaGetSymbolAddress((void**)&xh,   g_xh);
    cudaGetSymbolAddress((void**)&bufA, g_bufA);
    cudaGetSymbolAddress((void**)&bufB, g_bufB);
    cudaGetSymbolAddress((void**)&gsum, g_gsum);
    cudaGetSymbolAddress((void**)&gcnt, g_gcnt);
    cudaGetSymbolAddress((void**)&rowptr, g_rowptr);
    cudaGetSymbolAddress((void**)&cursor, g_cursor);
    cudaGetSymbolAddress((void**)&csrc, g_csrc);
    cudaGetSymbolAddress((void**)&w2fc, g_w2fc);
    cudaGetSymbolAddress((void**)&wthi, g_wthi);
    cudaGetSymbolAddress((void**)&wtlo, g_wtlo);

    cudaFuncSetAttribute(mlp_kernel, cudaFuncAttributeMaxDynamicSharedMemorySize, SM_TOTAL);

    int prep_threads = E;
    if (N * 16 > prep_threads) prep_threads = N * 16;
    if (6 * 16384 + 129 > prep_threads) prep_threads = 6 * 16384 + 129;
    // 1: weight transform + x->fp16 + edge count + w2fc (cursor==0 at entry)
    prep_kernel<<<(prep_threads + 255) / 256, 256>>>(
        W1s[0], W2s[0], W1s[1], W2s[1], W1s[2], W2s[2],
        wthi, wtlo, x, xh, N, ei, cursor, E, fcw, b2s[2], w2fc);
    // 2-3: CSR scan + fill (pre-scaled offsets)
    scan_kernel<<<1, 1024>>>(cursor, rowptr, N);
    fill_kernel<<<(E + 255) / 256, 256>>>(ei, cursor, csrc, E);

    // 4-6: ping-pong layers (fp16 everywhere); layer2 pools (no GEMM2)
    const __half* ins[3]  = {xh, bufA, bufB};
    __half*       outs[3] = {bufA, bufB, bufA /* unused (pool) */};
    int ntiles = (N + 127) / 128;
    for (int l = 0; l < 3; l++) {
        mlp_kernel<<<148, 1024, SM_TOTAL>>>(
            ins[l], rowptr, csrc, outs[l],
            wthi + (2 * l) * 16384, wtlo + (2 * l) * 16384,
            wthi + (2 * l + 1) * 16384, wtlo + (2 * l + 1) * 16384,
            b1s[l], b2s[l], epss[l],
            N, ntiles, (l < 2) ? 1 : 0, (l == 2) ? 1 : 0,
            batch, w2fc, gsum, gcnt);
    }
    // 7: output + restore invariants
    final_kernel<<<(N + 255) / 256, 256>>>(gsum, gcnt, fcb, (float*)d_out, G, cursor, N);
}

// round 14
// speedup vs baseline: 3.6575x; 1.0965x over previous
#include <cuda_runtime.h>
#include <cuda_fp16.h>
#include <cstdint>

// ---------------------------------------------------------------------------
// GINRegressor on GB300: CSR gather (fp16) fused into single-product fp16
// tensor MLP: D = A * fp16(W). Empirically calibrated: fp16 quantization of
// one operand moves final rel_err by ~1e-5 (R12 evidence), threshold 1e-3.
// 1024 thr/CTA persistent; ping-pong fp16 buffers; pre-scaled CSR offsets;
// layer2 GEMM2 folded to GEMV (w2fc = W2_2 @ fc_w).
// Launch order: prep(1), scan(2), fill(3), mlp0(4), mlp1(5), mlp2(6), final(7).
// Invariant: cursor/gsum/gcnt zero at entry (final_kernel restores).
// ---------------------------------------------------------------------------

#define NMAX 50000
#define EMAX 800000
#define GMAX 500
#define LDT 136  // padded smem tile stride (fp16 elems) -> conflict-free

__device__ __half g_xh[NMAX * 128];       // fp16 copy of input x
__device__ __half g_bufA[NMAX * 128];
__device__ __half g_bufB[NMAX * 128];
__device__ float g_gsum[GMAX];
__device__ float g_gcnt[GMAX];
__device__ int   g_rowptr[NMAX + 1];
__device__ int   g_cursor[NMAX];          // zero at entry (invariant)
__device__ int   g_csrc[EMAX];            // pre-scaled: src*32 (uint2 rows)
__device__ float g_w2fc[129];             // [0..127]=W2_2@fc, [128]=b2_2.fc
__device__ __align__(16) __half g_wth[6 * 16384];  // W^T fp16 planes

// ---------------- helpers ----------------
__device__ __forceinline__ uint32_t smem_u32(const void* p) {
    uint32_t a;
    asm("{ .reg .u64 t; cvta.to.shared.u64 t, %1; cvt.u32.u64 %0, t; }"
        : "=r"(a) : "l"(p));
    return a;
}

__device__ __forceinline__ void ldm4(uint32_t* a, uint32_t addr) {
    asm volatile("ldmatrix.sync.aligned.m8n8.x4.shared.b16 {%0,%1,%2,%3}, [%4];"
                 : "=r"(a[0]), "=r"(a[1]), "=r"(a[2]), "=r"(a[3]) : "r"(addr));
}

__device__ __forceinline__ void mma16816(float* c, const uint32_t* a,
                                         uint32_t b0, uint32_t b1) {
    asm volatile(
        "mma.sync.aligned.m16n8k16.row.col.f32.f16.f16.f32 "
        "{%0,%1,%2,%3}, {%4,%5,%6,%7}, {%8,%9}, {%0,%1,%2,%3};"
        : "+f"(c[0]), "+f"(c[1]), "+f"(c[2]), "+f"(c[3])
        : "r"(a[0]), "r"(a[1]), "r"(a[2]), "r"(a[3]), "r"(b0), "r"(b1));
}

// ---------------- prep: weights + x->fp16 + edge count + w2fc ----------------
__global__ void prep_kernel(const float* __restrict__ Wa, const float* __restrict__ Wb,
                            const float* __restrict__ Wc, const float* __restrict__ Wd,
                            const float* __restrict__ We, const float* __restrict__ Wf,
                            __half* __restrict__ wt,
                            const float* __restrict__ x, __half* __restrict__ xh, int N,
                            const int* __restrict__ ei, int* __restrict__ cnt, int E,
                            const float* __restrict__ fcw, const float* __restrict__ b2f,
                            float* __restrict__ w2fc) {
    int t = blockIdx.x * blockDim.x + threadIdx.x;
    if (t < 6 * 16384) {
        int m = t >> 14;
        int i = t & 16383;
        int n = i >> 7, k = i & 127;
        const float* W = (m == 0) ? Wa : (m == 1) ? Wb : (m == 2) ? Wc
                       : (m == 3) ? Wd : (m == 4) ? We : Wf;
        wt[t] = __float2half_rn(W[k * 128 + n]);
    } else if (t < 6 * 16384 + 128) {
        int k = t - 6 * 16384;
        float s = 0.f;
        #pragma unroll 4
        for (int c = 0; c < 128; c++) s = fmaf(Wf[k * 128 + c], fcw[c], s);
        w2fc[k] = s;
    } else if (t == 6 * 16384 + 128) {
        float s = 0.f;
        for (int c = 0; c < 128; c++) s = fmaf(b2f[c], fcw[c], s);
        w2fc[128] = s;
    }
    // x -> fp16 (8 elements per thread)
    if (t < N * 16) {
        const float4* x4 = (const float4*)x;
        float4 a = x4[t * 2];
        float4 b = x4[t * 2 + 1];
        uint4 o;
        *(__half2*)&o.x = __floats2half2_rn(a.x, a.y);
        *(__half2*)&o.y = __floats2half2_rn(a.z, a.w);
        *(__half2*)&o.z = __floats2half2_rn(b.x, b.y);
        *(__half2*)&o.w = __floats2half2_rn(b.z, b.w);
        ((uint4*)xh)[t] = o;
    }
    if (t < E) atomicAdd(&cnt[ei[E + t]], 1);
}

// ---------------- CSR build ----------------
__global__ __launch_bounds__(1024) void scan_kernel(int* __restrict__ cursor,
                                                    int* __restrict__ rowptr, int N) {
    __shared__ int warpsums[32];
    __shared__ int s_carry;
    int tid = threadIdx.x, lane = tid & 31, wid = tid >> 5;
    if (tid == 0) s_carry = 0;
    __syncthreads();
    for (int base = 0; base < N; base += 1024) {
        int i = base + tid;
        int v = (i < N) ? cursor[i] : 0;
        int x = v;
        #pragma unroll
        for (int d = 1; d < 32; d <<= 1) {
            int y = __shfl_up_sync(0xffffffffu, x, d);
            if (lane >= d) x += y;
        }
        if (lane == 31) warpsums[wid] = x;
        __syncthreads();
        if (wid == 0) {
            int w = warpsums[lane];
            #pragma unroll
            for (int d = 1; d < 32; d <<= 1) {
                int y = __shfl_up_sync(0xffffffffu, w, d);
                if (lane >= d) w += y;
            }
            warpsums[lane] = w;
        }
        __syncthreads();
        int excl = x - v + ((wid > 0) ? warpsums[wid - 1] : 0) + s_carry;
        if (i < N) { rowptr[i] = excl; cursor[i] = excl; }
        __syncthreads();
        if (tid == 0) s_carry += warpsums[31];
        __syncthreads();
    }
    if (threadIdx.x == 0) rowptr[N] = s_carry;
}

__global__ void fill_kernel(const int* __restrict__ ei, int* __restrict__ cursor,
                            int* __restrict__ csrc, int E) {
    int t = blockIdx.x * blockDim.x + threadIdx.x;
    if (t < E) {
        int d = ei[E + t];
        int p = atomicAdd(&cursor[d], 1);
        csrc[p] = ei[t] << 5;   // pre-scale: row offset in uint2 units
    }
}

// final output + restore invariants (cursor/gsum/gcnt = 0)
__global__ void final_kernel(float* __restrict__ gsum, float* __restrict__ gcnt,
                             const float* __restrict__ fcb,
                             float* __restrict__ out, int G,
                             int* __restrict__ cursor, int N) {
    int i = blockIdx.x * blockDim.x + threadIdx.x;
    if (i < G) {
        out[i] = gsum[i] / fmaxf(gcnt[i], 1.0f) + fcb[0];
        gsum[i] = 0.f;
        gcnt[i] = 0.f;
    }
    if (i < N) cursor[i] = 0;
}

// ---------------- fused aggregate + MLP (persistent, 1024 thr) ----------------
#define SM_B1  0        // 34816
#define SM_B2  34816
#define SM_A   69632    // single fp16 A plane (also T after epilogue1)
#define SM_SB1 104448
#define SM_SB2 104960
#define SM_SFW 105472
#define SM_SROW 105984
#define SM_TOTAL 106496

// single-product fp16 GEMM: acc += A*B  (per-warp 16x32 tile)
__device__ __forceinline__ void gemm_tile(
    const __half* sA, const __half* sB,
    float acc[4][4], int wr, int wc, int lane) {
    int arow = wr * 16 + (lane & 15);
    int acol = (lane >> 4) * 8;
    int bn = wc * 32 + ((lane >> 4) << 3) + (lane & 7);
    int bk = ((lane >> 3) & 1) << 3;
    const __half* a_base = sA + arow * LDT + acol;
    const __half* b_base = sB + bn * LDT + bk;
    #pragma unroll
    for (int k0 = 0; k0 < 8; k0++) {
        uint32_t a[4];
        ldm4(a, smem_u32(a_base + k0 * 16));
        #pragma unroll
        for (int p = 0; p < 2; p++) {
            int nfp = p * 2;
            uint32_t b[4];
            ldm4(b, smem_u32(b_base + nfp * 8 * LDT + k0 * 16));
            mma16816(acc[nfp],     a, b[0], b[1]);
            mma16816(acc[nfp + 1], a, b[2], b[3]);
        }
    }
}

// accumulate 4 neighbor rows (fp16; csrc holds pre-scaled row offsets)
#define GATHER4H(v, J)                                                    \
    do {                                                                  \
        int o0 = __ldg(&csrc[(J)]);                                       \
        int o1 = __ldg(&csrc[(J) + 1]);                                   \
        int o2 = __ldg(&csrc[(J) + 2]);                                   \
        int o3 = __ldg(&csrc[(J) + 3]);                                   \
        uint2 w0 = Xh[o0 + lane];                                         \
        uint2 w1 = Xh[o1 + lane];                                         \
        uint2 w2 = Xh[o2 + lane];                                         \
        uint2 w3 = Xh[o3 + lane];                                         \
        float2 f;                                                         \
        f = __half22float2(*(__half2*)&w0.x); v.x += f.x; v.y += f.y;     \
        f = __half22float2(*(__half2*)&w0.y); v.z += f.x; v.w += f.y;     \
        f = __half22float2(*(__half2*)&w1.x); v.x += f.x; v.y += f.y;     \
        f = __half22float2(*(__half2*)&w1.y); v.z += f.x; v.w += f.y;     \
        f = __half22float2(*(__half2*)&w2.x); v.x += f.x; v.y += f.y;     \
        f = __half22float2(*(__half2*)&w2.y); v.z += f.x; v.w += f.y;     \
        f = __half22float2(*(__half2*)&w3.x); v.x += f.x; v.y += f.y;     \
        f = __half22float2(*(__half2*)&w3.y); v.z += f.x; v.w += f.y;     \
    } while (0)

__global__ __launch_bounds__(1024, 1) void mlp_kernel(
    const __half* __restrict__ X,
    const int* __restrict__ rowptr, const int* __restrict__ csrc,
    __half* __restrict__ H,
    const __half* __restrict__ W1, const __half* __restrict__ W2,
    const float* __restrict__ b1, const float* __restrict__ b2,
    const float* __restrict__ epsp,
    int n, int ntiles, int relu_out, int pool,
    const int* __restrict__ batch, const float* __restrict__ w2fc,
    float* __restrict__ gsum, float* __restrict__ gcnt) {
    extern __shared__ char sm[];
    __half* sB1 = (__half*)(sm + SM_B1);
    __half* sB2 = (__half*)(sm + SM_B2);
    __half* sA  = (__half*)(sm + SM_A);
    float* sb1  = (float*)(sm + SM_SB1);
    float* sb2  = (float*)(sm + SM_SB2);
    float* sfw  = (float*)(sm + SM_SFW);   // w2fc for pool layer
    float* srow = (float*)(sm + SM_SROW);

    int tid = threadIdx.x;
    int lane = tid & 31;
    int wid = tid >> 5;           // 0..31
    int wr = wid & 7;             // row group (16 rows)
    int wc = wid >> 3;            // col group (32 cols)

    if (tid < 128) {
        sb1[tid] = b1[tid];
        sb2[tid] = b2[tid];
        sfw[tid] = w2fc[tid];
    }

    // load weight planes once (persistent); pool layer skips B2
    {
        const uint4* p1 = (const uint4*)W1;
        const uint4* p2 = (const uint4*)W2;
        for (int i = tid; i < 2048; i += 1024) {
            int r = i >> 4, c = (i & 15) * 8;
            int d = r * LDT + c;
            *(uint4*)&sB1[d] = p1[i];
            if (!pool) *(uint4*)&sB2[d] = p2[i];
        }
    }

    float s = 1.0f + __ldg(epsp);
    float bconst = __ldg(&w2fc[128]);
    const uint2* Xh = (const uint2*)X;

    for (int tile = blockIdx.x; tile < ntiles; tile += gridDim.x) {
        int row0 = tile * 128;
        if (tid < 128) srow[tid] = 0.f;

        // gather: A = (1+eps)*X[row] + sum_nbrs X[j]; 2 rows per warp iter
        for (int r2 = wid; r2 < 64; r2 += 32) {
            int rA = r2, rB = r2 + 64;
            int grA = row0 + rA, grB = row0 + rB;
            float4 va = make_float4(0.f, 0.f, 0.f, 0.f);
            float4 vb = make_float4(0.f, 0.f, 0.f, 0.f);
            int ja = 0, ea = 0, jb = 0, eb = 0;
            if (grA < n) {
                uint2 w = Xh[grA * 32 + lane];
                float2 f0 = __half22float2(*(__half2*)&w.x);
                float2 f1 = __half22float2(*(__half2*)&w.y);
                va.x = s * f0.x; va.y = s * f0.y;
                va.z = s * f1.x; va.w = s * f1.y;
                ja = __ldg(&rowptr[grA]); ea = __ldg(&rowptr[grA + 1]);
            }
            if (grB < n) {
                uint2 w = Xh[grB * 32 + lane];
                float2 f0 = __half22float2(*(__half2*)&w.x);
                float2 f1 = __half22float2(*(__half2*)&w.y);
                vb.x = s * f0.x; vb.y = s * f0.y;
                vb.z = s * f1.x; vb.w = s * f1.y;
                jb = __ldg(&rowptr[grB]); eb = __ldg(&rowptr[grB + 1]);
            }
            while (ja + 4 <= ea && jb + 4 <= eb) {
                GATHER4H(va, ja);
                GATHER4H(vb, jb);
                ja += 4; jb += 4;
            }
            for (; ja + 4 <= ea; ja += 4) GATHER4H(va, ja);
            for (; ja < ea; ja++) {
                int o0 = __ldg(&csrc[ja]);
                uint2 w = Xh[o0 + lane];
                float2 f0 = __half22float2(*(__half2*)&w.x);
                float2 f1 = __half22float2(*(__half2*)&w.y);
                va.x += f0.x; va.y += f0.y; va.z += f1.x; va.w += f1.y;
            }
            for (; jb + 4 <= eb; jb += 4) GATHER4H(vb, jb);
            for (; jb < eb; jb++) {
                int o0 = __ldg(&csrc[jb]);
                uint2 w = Xh[o0 + lane];
                float2 f0 = __half22float2(*(__half2*)&w.x);
                float2 f1 = __half22float2(*(__half2*)&w.y);
                vb.x += f0.x; vb.y += f0.y; vb.z += f1.x; vb.w += f1.y;
            }
            uint2 o;
            *(__half2*)&o.x = __floats2half2_rn(va.x, va.y);
            *(__half2*)&o.y = __floats2half2_rn(va.z, va.w);
            *(uint2*)&sA[rA * LDT + lane * 4] = o;
            *(__half2*)&o.x = __floats2half2_rn(vb.x, vb.y);
            *(__half2*)&o.y = __floats2half2_rn(vb.z, vb.w);
            *(uint2*)&sA[rB * LDT + lane * 4] = o;
        }
        __syncthreads();

        float acc[4][4];
        #pragma unroll
        for (int j = 0; j < 4; j++)
            #pragma unroll
            for (int q = 0; q < 4; q++) acc[j][q] = 0.f;

        // GEMM1
        gemm_tile(sA, sB1, acc, wr, wc, lane);

        if (pool) {
            // layer 2: h.fc = ReLU(acc+b1) @ w2fc (+ bconst per node)
            int r = wr * 16 + (lane >> 2);
            float d0 = 0.f, d1 = 0.f;
            #pragma unroll
            for (int nf = 0; nf < 4; nf++) {
                int c = wc * 32 + nf * 8 + (lane & 3) * 2;
                float* a = acc[nf];
                d0 = fmaf(fmaxf(a[0] + sb1[c], 0.f), sfw[c], d0);
                d0 = fmaf(fmaxf(a[1] + sb1[c + 1], 0.f), sfw[c + 1], d0);
                d1 = fmaf(fmaxf(a[2] + sb1[c], 0.f), sfw[c], d1);
                d1 = fmaf(fmaxf(a[3] + sb1[c + 1], 0.f), sfw[c + 1], d1);
            }
            atomicAdd(&srow[r], d0);
            atomicAdd(&srow[r + 8], d1);
            __syncthreads();
            if (tid < 128) {
                int gr = row0 + tid;
                if (gr < n) {
                    int g = batch[gr];
                    atomicAdd(&gsum[g], srow[tid] + bconst);
                    atomicAdd(&gcnt[g], 1.0f);
                }
            }
            __syncthreads();
            continue;
        }

        __syncthreads();  // all reads of sA done before overwrite

        // epilogue1: T = ReLU(acc + b1) -> fp16 into sA
        {
            int r = wr * 16 + (lane >> 2);
            #pragma unroll
            for (int nf = 0; nf < 4; nf++) {
                int c = wc * 32 + nf * 8 + (lane & 3) * 2;
                float* a = acc[nf];
                float v0 = fmaxf(a[0] + sb1[c], 0.f);
                float v1 = fmaxf(a[1] + sb1[c + 1], 0.f);
                float v2 = fmaxf(a[2] + sb1[c], 0.f);
                float v3 = fmaxf(a[3] + sb1[c + 1], 0.f);
                *(__half2*)&sA[r * LDT + c] = __floats2half2_rn(v0, v1);
                *(__half2*)&sA[(r + 8) * LDT + c] = __floats2half2_rn(v2, v3);
            }
        }
        __syncthreads();

        #pragma unroll
        for (int j = 0; j < 4; j++)
            #pragma unroll
            for (int q = 0; q < 4; q++) acc[j][q] = 0.f;

        // GEMM2
        gemm_tile(sA, sB2, acc, wr, wc, lane);

        // epilogue2: out = acc + b2 (+ReLU) -> H (fp16)
        {
            int r = wr * 16 + (lane >> 2);
            int gr0 = row0 + r, gr1 = gr0 + 8;
            #pragma unroll
            for (int nf = 0; nf < 4; nf++) {
                int c = wc * 32 + nf * 8 + (lane & 3) * 2;
                float* a = acc[nf];
                float v0 = a[0] + sb2[c], v1 = a[1] + sb2[c + 1];
                float v2 = a[2] + sb2[c], v3 = a[3] + sb2[c + 1];
                if (relu_out) {
                    v0 = fmaxf(v0, 0.f); v1 = fmaxf(v1, 0.f);
                    v2 = fmaxf(v2, 0.f); v3 = fmaxf(v3, 0.f);
                }
                if (gr0 < n)
                    *(__half2*)&H[(size_t)gr0 * 128 + c] = __floats2half2_rn(v0, v1);
                if (gr1 < n)
                    *(__half2*)&H[(size_t)gr1 * 128 + c] = __floats2half2_rn(v2, v3);
            }
        }
        __syncthreads();  // protect sA before next tile's gather
    }
}

// ---------------- host launcher ----------------
extern "C" void kernel_launch(void* const* d_in, const int* in_sizes, int n_in,
                              void* d_out, int out_size) {
    const float* x     = (const float*)d_in[0];
    const int*   ei    = (const int*)d_in[1];
    const int*   batch = (const int*)d_in[2];
    const float* W1s[3] = {(const float*)d_in[3],  (const float*)d_in[8],  (const float*)d_in[13]};
    const float* b1s[3] = {(const float*)d_in[4],  (const float*)d_in[9],  (const float*)d_in[14]};
    const float* W2s[3] = {(const float*)d_in[5],  (const float*)d_in[10], (const float*)d_in[15]};
    const float* b2s[3] = {(const float*)d_in[6],  (const float*)d_in[11], (const float*)d_in[16]};
    const float* epss[3]= {(const float*)d_in[7],  (const float*)d_in[12], (const float*)d_in[17]};
    const float* fcw   = (const float*)d_in[18];
    const float* fcb   = (const float*)d_in[19];

    int N = in_sizes[2];
    int E = in_sizes[1] / 2;
    int G = out_size;

    float *gsum, *gcnt, *w2fc;
    __half *xh, *bufA, *bufB, *wth;
    int *rowptr, *cursor, *csrc;
    cudaGetSymbolAddress((void**)&xh,   g_xh);
    cudaGetSymbolAddress((void**)&bufA, g_bufA);
    cudaGetSymbolAddress((void**)&bufB, g_bufB);
    cudaGetSymbolAddress((void**)&gsum, g_gsum);
    cudaGetSymbolAddress((void**)&gcnt, g_gcnt);
    cudaGetSymbolAddress((void**)&rowptr, g_rowptr);
    cudaGetSymbolAddress((void**)&cursor, g_cursor);
    cudaGetSymbolAddress((void**)&csrc, g_csrc);
    cudaGetSymbolAddress((void**)&w2fc, g_w2fc);
    cudaGetSymbolAddress((void**)&wth,  g_wth);

    cudaFuncSetAttribute(mlp_kernel, cudaFuncAttributeMaxDynamicSharedMemorySize, SM_TOTAL);

    int prep_threads = E;
    if (N * 16 > prep_threads) prep_threads = N * 16;
    if (6 * 16384 + 129 > prep_threads) prep_threads = 6 * 16384 + 129;
    // 1: weight transform + x->fp16 + edge count + w2fc (cursor==0 at entry)
    prep_kernel<<<(prep_threads + 255) / 256, 256>>>(
        W1s[0], W2s[0], W1s[1], W2s[1], W1s[2], W2s[2],
        wth, x, xh, N, ei, cursor, E, fcw, b2s[2], w2fc);
    // 2-3: CSR scan + fill (pre-scaled offsets)
    scan_kernel<<<1, 1024>>>(cursor, rowptr, N);
    fill_kernel<<<(E + 255) / 256, 256>>>(ei, cursor, csrc, E);

    // 4-6: ping-pong layers (fp16 everywhere); layer2 pools (no GEMM2)
    const __half* ins[3]  = {xh, bufA, bufB};
    __half*       outs[3] = {bufA, bufB, bufA /* unused (pool) */};
    int ntiles = (N + 127) / 128;
    for (int l = 0; l < 3; l++) {
        mlp_kernel<<<148, 1024, SM_TOTAL>>>(
            ins[l], rowptr, csrc, outs[l],
            wth + (2 * l) * 16384, wth + (2 * l + 1) * 16384,
            b1s[l], b2s[l], epss[l],
            N, ntiles, (l < 2) ? 1 : 0, (l == 2) ? 1 : 0,
            batch, w2fc, gsum, gcnt);
    }
    // 7: output + restore invariants
    final_kernel<<<(N + 255) / 256, 256>>>(gsum, gcnt, fcb, (float*)d_out, G, cursor, N);
}